// round 7
// baseline (speedup 1.0000x reference)
#include <cuda_runtime.h>
#include <cuda_bf16.h>
#include <cstdint>
#include <math.h>

#define N_NODES 25000
#define N_EDGES 100000
#define H 64
#define N_LAYERS 3
#define MTILE 64
#define NTILES 392               // 392*64 = 25088 >= 25000
#define CAPE 448                 // per-tile edge cache capacity (mean 256, sd ~16)
#define NPLANES 66

// ---------------- scratch (static device globals) ---------------------------
__device__ float g_h[N_NODES * H];
__device__ float g_hidden[N_NODES * H];
__device__ float g_ew2[N_EDGES * H];
__device__ float g_m[N_NODES * H];
__device__ float g_hgT[(size_t)H * N_EDGES];                 // [plane][edge-slot]
__device__ __align__(16) __nv_bfloat16 gBW_hi[64 * 4096];    // frag-packed We3 planes
__device__ __align__(16) __nv_bfloat16 gBW_lo[64 * 4096];
__device__ __align__(16) __nv_bfloat16 gBr_hi[4096], gBr_lo[4096];  // roots[l] plane
__device__ __align__(16) __nv_bfloat16 gBb_hi[4096], gBb_lo[4096];  // be3 plane
__device__ int   g_deg[N_NODES];
__device__ int   g_off[N_NODES + 1];
__device__ int   g_cur[N_NODES];
__device__ int   g_csr[N_EDGES];

// ---------------- helpers ------------------------------------------------
__device__ __forceinline__ uint32_t smem_u32(const void* p) {
    uint32_t a;
    asm("{ .reg .u64 t; cvta.to.shared.u64 t, %1; cvt.u32.u64 %0, t; }" : "=r"(a) : "l"(p));
    return a;
}
__device__ __forceinline__ void mma16816(float* c, const uint32_t* a, uint32_t b0, uint32_t b1) {
    asm volatile("mma.sync.aligned.m16n8k16.row.col.f32.bf16.bf16.f32 "
        "{%0,%1,%2,%3}, {%4,%5,%6,%7}, {%8,%9}, {%0,%1,%2,%3};"
        : "+f"(c[0]), "+f"(c[1]), "+f"(c[2]), "+f"(c[3])
        : "r"(a[0]), "r"(a[1]), "r"(a[2]), "r"(a[3]), "r"(b0), "r"(b1));
}
__device__ __forceinline__ void split_bf(float v, __nv_bfloat16& hi, __nv_bfloat16& lo) {
    hi = __float2bfloat16(v);
    lo = __float2bfloat16(v - __bfloat162float(hi));
}
__device__ __forceinline__ uint32_t pack_bf2(__nv_bfloat16 a, __nv_bfloat16 b) {
    uint16_t ua = *(uint16_t*)&a, ub = *(uint16_t*)&b;
    return (uint32_t)ua | ((uint32_t)ub << 16);
}
__device__ __forceinline__ void cpa16(uint32_t dst, const void* src) {
    asm volatile("cp.async.cg.shared.global [%0], [%1], 16;" :: "r"(dst), "l"(src));
}

// ---------------- zero init --------------------------------------------------
__global__ void k_zero_misc() {
    int i = blockIdx.x * blockDim.x + threadIdx.x;
    int st = gridDim.x * blockDim.x;
    for (int idx = i; idx < N_NODES; idx += st) g_deg[idx] = 0;
    for (int idx = i; idx < N_NODES * H; idx += st) g_hidden[idx] = 0.f;
}

// ---------------- node MLP ---------------------------------------------------
__global__ void k_node_mlp(const float* __restrict__ x,
                           const float* __restrict__ W1, const float* __restrict__ b1,
                           const float* __restrict__ W2, const float* __restrict__ b2,
                           const float* __restrict__ W3, const float* __restrict__ b3) {
    __shared__ float W1T[32 * 64], W2T[64 * 64], W3T[64 * 64];
    __shared__ float b1s[64], b2s[64], b3s[64];
    __shared__ float xs[4][32], h1[4][64], h2[4][64];
    int tid = threadIdx.x;
    for (int idx = tid; idx < 32 * 64; idx += 256) { int o = idx / 32, j = idx % 32; W1T[j * 64 + o] = W1[idx]; }
    for (int idx = tid; idx < 64 * 64; idx += 256) { int o = idx / 64, j = idx % 64; W2T[j * 64 + o] = W2[idx]; W3T[j * 64 + o] = W3[idx]; }
    if (tid < 64) { b1s[tid] = b1[tid]; b2s[tid] = b2[tid]; b3s[tid] = b3[tid]; }
    __syncthreads();
    int nl = tid >> 6, o = tid & 63;
    for (int base = blockIdx.x * 4; base < N_NODES; base += gridDim.x * 4) {
        int node = base + nl;
        if (o < 32 && node < N_NODES) xs[nl][o] = x[node * 32 + o];
        __syncthreads();
        if (node < N_NODES) {
            float a = b1s[o];
            #pragma unroll
            for (int j = 0; j < 32; j++) a += xs[nl][j] * W1T[j * 64 + o];
            h1[nl][o] = fmaxf(a, 0.f);
        }
        __syncthreads();
        if (node < N_NODES) {
            float a = b2s[o];
            #pragma unroll
            for (int j = 0; j < 64; j++) a += h1[nl][j] * W2T[j * 64 + o];
            h2[nl][o] = fmaxf(a, 0.f);
        }
        __syncthreads();
        if (node < N_NODES) {
            float a = b3s[o];
            #pragma unroll
            for (int j = 0; j < 64; j++) a += h2[nl][j] * W3T[j * 64 + o];
            g_h[node * 64 + o] = a;
        }
        __syncthreads();
    }
}

// ---------------- edge MLP (layers 1,2) --------------------------------------
__global__ void k_edge_mlp(const float* __restrict__ ea,
                           const float* __restrict__ W1, const float* __restrict__ b1,
                           const float* __restrict__ W2, const float* __restrict__ b2) {
    __shared__ float W1T[16 * 64], W2T[64 * 64];
    __shared__ float b1s[64], b2s[64];
    __shared__ float es[4][16], h1[4][64];
    int tid = threadIdx.x;
    for (int idx = tid; idx < 16 * 64; idx += 256) { int o = idx >> 4, j = idx & 15; W1T[j * 64 + o] = W1[idx]; }
    for (int idx = tid; idx < 64 * 64; idx += 256) { int o = idx >> 6, j = idx & 63; W2T[j * 64 + o] = W2[idx]; }
    if (tid < 64) { b1s[tid] = b1[tid]; b2s[tid] = b2[tid]; }
    __syncthreads();
    int nl = tid >> 6, o = tid & 63;
    for (int base = blockIdx.x * 4; base < N_EDGES; base += gridDim.x * 4) {
        int e = base + nl;
        if (o < 16 && e < N_EDGES) es[nl][o] = ea[e * 16 + o];
        __syncthreads();
        if (e < N_EDGES) {
            float a = b1s[o];
            #pragma unroll
            for (int j = 0; j < 16; j++) a += es[nl][j] * W1T[j * 64 + o];
            h1[nl][o] = fmaxf(a, 0.f);
        }
        __syncthreads();
        if (e < N_EDGES) {
            float a = b2s[o];
            #pragma unroll
            for (int j = 0; j < 64; j++) a += h1[nl][j] * W2T[j * 64 + o];
            g_ew2[e * 64 + o] = fmaxf(a, 0.f);
        }
        __syncthreads();
    }
}

// ---------------- CSR build --------------------------------------------------
__global__ void k_hist(const int* __restrict__ ei) {
    int i = blockIdx.x * blockDim.x + threadIdx.x, st = gridDim.x * blockDim.x;
    for (int e = i; e < N_EDGES; e += st) atomicAdd(&g_deg[ei[N_EDGES + e]], 1);
}
__global__ void k_scan() {
    __shared__ int part[1024];
    int t = threadIdx.x;
    const int CH = (N_NODES + 1023) / 1024;
    int b0 = t * CH, b1 = min(b0 + CH, N_NODES);
    int s = 0;
    for (int i = b0; i < b1; i++) s += g_deg[i];
    part[t] = s;
    __syncthreads();
    for (int d = 1; d < 1024; d <<= 1) {
        int v = (t >= d) ? part[t - d] : 0;
        __syncthreads();
        part[t] += v;
        __syncthreads();
    }
    int run = (t == 0) ? 0 : part[t - 1];
    for (int i = b0; i < b1; i++) { g_off[i] = run; g_cur[i] = run; run += g_deg[i]; }
    if (t == 1023) g_off[N_NODES] = part[1023];
}
__global__ void k_fill(const int* __restrict__ ei) {
    int i = blockIdx.x * blockDim.x + threadIdx.x, st = gridDim.x * blockDim.x;
    for (int e = i; e < N_EDGES; e += st) {
        int d = ei[N_EDGES + e];
        int p = atomicAdd(&g_cur[d], 1);
        g_csr[p] = e;
    }
}
__global__ void k_sort() {
    int d = blockIdx.x * blockDim.x + threadIdx.x;
    if (d >= N_NODES) return;
    int a = g_off[d], b = g_off[d + 1];
    for (int i = a + 1; i < b; i++) {
        int v = g_csr[i];
        int j = i - 1;
        while (j >= a && g_csr[j] > v) { g_csr[j + 1] = g_csr[j]; j--; }
        g_csr[j + 1] = v;
    }
}

// -------- frag-packed B planes: idx = ((s*64+n)*4+lr)*4 + c,
// value = B[n][k], k = s*16 + (c<2 ? 2*lr+c : 8+2*lr+(c-2)) --------------------
__global__ void k_buildBW(const float* __restrict__ We3) {       // once
    int idx = blockIdx.x * blockDim.x + threadIdx.x;
    if (idx >= 64 * 4096) return;
    int c = idx & 3, lr = (idx >> 2) & 3, n = (idx >> 4) & 63, s = (idx >> 10) & 3, i = idx >> 12;
    int k = s * 16 + ((c < 2) ? (2 * lr + c) : (8 + 2 * lr + (c - 2)));
    float v = We3[(i * 64 + n) * 64 + k];
    __nv_bfloat16 hi, lo; split_bf(v, hi, lo);
    gBW_hi[idx] = hi; gBW_lo[idx] = lo;
}
__global__ void k_buildB2(const float* __restrict__ roots, const float* __restrict__ be3, int l) {
    int idx = blockIdx.x * blockDim.x + threadIdx.x;
    if (idx >= 4096) return;
    int c = idx & 3, lr = (idx >> 2) & 3, n = (idx >> 4) & 63, s = (idx >> 10) & 3;
    int k = s * 16 + ((c < 2) ? (2 * lr + c) : (8 + 2 * lr + (c - 2)));
    __nv_bfloat16 hi, lo;
    split_bf(roots[(l * 64 + k) * 64 + n], hi, lo);
    gBr_hi[idx] = hi; gBr_lo[idx] = lo;
    split_bf(be3[k * 64 + n], hi, lo);
    gBb_hi[idx] = hi; gBb_lo[idx] = lo;
}

// -------- per-layer gather+transpose: hgT[p][j] = h[src(csr[j])][p] -----------
__global__ void k_hgT(const int* __restrict__ ei) {
    int j = blockIdx.x * blockDim.x + threadIdx.x;
    if (j >= N_EDGES) return;
    int s = ei[g_csr[j]];
    const float4* hr = (const float4*)(g_h + s * 64);
    #pragma unroll
    for (int q = 0; q < 16; q++) {
        float4 v = hr[q];
        g_hgT[(size_t)(q * 4 + 0) * N_EDGES + j] = v.x;
        g_hgT[(size_t)(q * 4 + 1) * N_EDGES + j] = v.y;
        g_hgT[(size_t)(q * 4 + 2) * N_EDGES + j] = v.z;
        g_hgT[(size_t)(q * 4 + 3) * N_EDGES + j] = v.w;
    }
}

// ---------------- fused build+GEMM ---------------------------------------------
// smem (bytes): A 4x9216 | B 3x16384 | hs 2xCAPE*4 | ssrc CAPE*4 | seid CAPE*4 | noff 65*4
#define A_OFF   0
#define A_PLANE (64 * 72 * 2)
#define B_OFF   (A_OFF + 4 * A_PLANE)            // 36864
#define B_SLOT  16384
#define HS_OFF  (B_OFF + 3 * B_SLOT)             // 86016
#define SS_OFF  (HS_OFF + 2 * CAPE * 4)          // 89600
#define SE_OFF  (SS_OFF + CAPE * 4)              // 91392
#define NO_OFF  (SE_OFF + CAPE * 4)              // 93184
#define FUSED_SMEM (NO_OFF + 80 * 4)

__global__ void __launch_bounds__(256, 2) k_fused(const int* __restrict__ ei,
                                                  const float* __restrict__ cbias, int l) {
    extern __shared__ __align__(16) char smb[];
    __nv_bfloat16* Abuf = (__nv_bfloat16*)(smb + A_OFF);
    __nv_bfloat16* Bbuf = (__nv_bfloat16*)(smb + B_OFF);
    float* hsb  = (float*)(smb + HS_OFF);
    int*   ssrc = (int*)(smb + SS_OFF);
    int*   seid = (int*)(smb + SE_OFF);
    int*   noff = (int*)(smb + NO_OFF);

    const int tid = threadIdx.x, w = tid >> 5, lane = tid & 31;
    const int lq = lane >> 2, lr = lane & 3;
    const int wm = w >> 1, wn = w & 1;
    const int m0 = blockIdx.x * MTILE;

    if (tid < 65) {
        int d = m0 + tid;
        noff[tid] = g_off[d > N_NODES ? N_NODES : d];
    }

    // prefetch B planes 0,1
    auto copyB = [&](int slot, int plane) {
        const __nv_bfloat16 *sh, *sl;
        if (plane < 64)       { sh = gBW_hi + plane * 4096; sl = gBW_lo + plane * 4096; }
        else if (plane == 64) { sh = gBr_hi; sl = gBr_lo; }
        else                  { sh = gBb_hi; sl = gBb_lo; }
        uint32_t dst = smem_u32(Bbuf + slot * (B_SLOT / 2));
        #pragma unroll
        for (int q = 0; q < 2; q++) {
            int c = q * 256 + tid;
            cpa16(dst + c * 16, sh + c * 8);
            cpa16(dst + 8192 + c * 16, sl + c * 8);
        }
        asm volatile("cp.async.commit_group;" ::: "memory");
    };
    copyB(0, 0);
    copyB(1, 1);
    __syncthreads();

    const int j0 = noff[0];
    const int cnt = noff[64] - j0;
    const int ccnt = cnt < CAPE ? cnt : CAPE;

    for (int jj = tid; jj < ccnt; jj += 256) {
        int e = g_csr[j0 + jj];
        seid[jj] = e;
        ssrc[jj] = ei[e];
        hsb[jj] = g_hgT[(size_t)0 * N_EDGES + j0 + jj];
        hsb[CAPE + jj] = g_hgT[(size_t)1 * N_EDGES + j0 + jj];
    }
    __syncthreads();

    float acc[4][4];
    #pragma unroll
    for (int na = 0; na < 4; na++)
        #pragma unroll
        for (int v = 0; v < 4; v++) acc[na][v] = 0.f;

    auto build_plane = [&](int p, int buf) {
        __nv_bfloat16* Ah = Abuf + (buf * 2 + 0) * (A_PLANE / 2);
        __nv_bfloat16* Al = Abuf + (buf * 2 + 1) * (A_PLANE / 2);
        const float* hs_s = hsb + (p & 1) * CAPE;
        #pragma unroll 1
        for (int r = 0; r < 8; r++) {
            int node = w * 8 + r;
            int js = noff[node] - j0;
            int dg = noff[node + 1] - noff[node];
            float a0 = 0.f, a1 = 0.f;
            if (p < 64) {
                for (int q = 0; q < dg; q++) {
                    int jj = js + q;
                    float hs; int e;
                    if (jj < CAPE) { hs = hs_s[jj]; e = seid[jj]; }
                    else { hs = g_hgT[(size_t)p * N_EDGES + j0 + jj]; e = g_csr[j0 + jj]; }
                    float2 ew = *(const float2*)&g_ew2[e * 64 + lane * 2];
                    a0 += hs * ew.x;
                    a1 += hs * ew.y;
                }
            } else if (p == 64) {
                int d = m0 + node;
                if (d < N_NODES) {
                    float2 hv = *(const float2*)&g_h[d * 64 + lane * 2];
                    a0 = hv.x; a1 = hv.y;
                }
            } else {
                for (int q = 0; q < dg; q++) {
                    int jj = js + q;
                    int src = (jj < CAPE) ? ssrc[jj] : ei[g_csr[j0 + jj]];
                    float2 hv = *(const float2*)&g_h[src * 64 + lane * 2];
                    a0 += hv.x; a1 += hv.y;
                }
            }
            __nv_bfloat16 h0, l0, h1, l1;
            split_bf(a0, h0, l0); split_bf(a1, h1, l1);
            *(uint32_t*)&Ah[node * 72 + lane * 2] = pack_bf2(h0, h1);
            *(uint32_t*)&Al[node * 72 + lane * 2] = pack_bf2(l0, l1);
        }
    };

    build_plane(0, 0);

    for (int i = 0; i < NPLANES; i++) {
        __syncthreads();                                  // A(i) built, hs(i+1) loaded
        if (i < NPLANES - 2) asm volatile("cp.async.wait_group 1;" ::: "memory");
        else                 asm volatile("cp.async.wait_group 0;" ::: "memory");
        __syncthreads();

        {   // mma on A buffer i&1 vs B slot i%3
            const __nv_bfloat16* Ah = Abuf + ((i & 1) * 2 + 0) * (A_PLANE / 2);
            const __nv_bfloat16* Al = Abuf + ((i & 1) * 2 + 1) * (A_PLANE / 2);
            const __nv_bfloat16* Bh = Bbuf + (i % 3) * (B_SLOT / 2);
            const __nv_bfloat16* Bl = Bh + 4096;
            int arow = (wm * 16 + lq) * 72 + lr * 2;
            #pragma unroll
            for (int s = 0; s < 4; s++) {
                int k0 = s * 16;
                uint32_t ahi[4], alo[4];
                ahi[0] = *(const uint32_t*)&Ah[arow + k0];
                ahi[1] = *(const uint32_t*)&Ah[arow + 576 + k0];
                ahi[2] = *(const uint32_t*)&Ah[arow + k0 + 8];
                ahi[3] = *(const uint32_t*)&Ah[arow + 576 + k0 + 8];
                alo[0] = *(const uint32_t*)&Al[arow + k0];
                alo[1] = *(const uint32_t*)&Al[arow + 576 + k0];
                alo[2] = *(const uint32_t*)&Al[arow + k0 + 8];
                alo[3] = *(const uint32_t*)&Al[arow + 576 + k0 + 8];
                #pragma unroll
                for (int na = 0; na < 4; na++) {
                    int n = wn * 32 + na * 8 + lq;
                    int fi = ((s * 64 + n) * 4 + lr) * 4;
                    uint2 bh = *(const uint2*)&Bh[fi];
                    uint2 bl = *(const uint2*)&Bl[fi];
                    mma16816(acc[na], ahi, bh.x, bh.y);
                    mma16816(acc[na], ahi, bl.x, bl.y);
                    mma16816(acc[na], alo, bh.x, bh.y);
                }
            }
        }
        if (i + 2 < NPLANES) copyB((i + 2) % 3, i + 2);
        if (i + 2 < 64) {                                  // prefetch hs plane i+2
            float* hd = hsb + (i & 1) * CAPE;
            for (int jj = tid; jj < ccnt; jj += 256)
                hd[jj] = g_hgT[(size_t)(i + 2) * N_EDGES + j0 + jj];
        }
        if (i + 1 < NPLANES) build_plane(i + 1, (i + 1) & 1);
    }

    // epilogue
    int r0 = m0 + wm * 16 + lq;
    #pragma unroll
    for (int na = 0; na < 4; na++) {
        int c0 = wn * 32 + na * 8 + lr * 2;
        float bx = cbias[l * 64 + c0], by = cbias[l * 64 + c0 + 1];
        if (r0 < N_NODES) {
            g_m[r0 * 64 + c0]     = acc[na][0] + bx;
            g_m[r0 * 64 + c0 + 1] = acc[na][1] + by;
        }
        if (r0 + 8 < N_NODES) {
            g_m[(r0 + 8) * 64 + c0]     = acc[na][2] + bx;
            g_m[(r0 + 8) * 64 + c0 + 1] = acc[na][3] + by;
        }
    }
}

// ---------------- GRU step ---------------------------------------------------
#define GRU_SMEM ((24576 + 192 * 2 + 64 * 2 + 192 * 2) * 4)
__global__ void k_gru(const float* __restrict__ Wih, const float* __restrict__ Whh,
                      const float* __restrict__ bih, const float* __restrict__ bhh,
                      float* __restrict__ dout, int last) {
    extern __shared__ float smf[];
    float* WihT = smf;
    float* WhhT = smf + 12288;
    float* bihs = smf + 24576;
    float* bhhs = bihs + 192;
    float* ms   = bhhs + 192;
    float* hs   = ms + 64;
    float* gi   = hs + 64;
    float* gh   = gi + 192;
    int t = threadIdx.x;
    for (int idx = t; idx < 192 * 64; idx += 192) {
        int j = idx / 64, i = idx % 64;
        WihT[i * 192 + j] = Wih[idx];
        WhhT[i * 192 + j] = Whh[idx];
    }
    bihs[t] = bih[t]; bhhs[t] = bhh[t];
    __syncthreads();
    for (int node = blockIdx.x; node < N_NODES; node += gridDim.x) {
        if (t < 64) { ms[t] = g_m[node * 64 + t]; hs[t] = g_hidden[node * 64 + t]; }
        __syncthreads();
        float a = bihs[t], b = bhhs[t];
        #pragma unroll 8
        for (int i = 0; i < 64; i++) {
            a += ms[i] * WihT[i * 192 + t];
            b += hs[i] * WhhT[i * 192 + t];
        }
        gi[t] = a; gh[t] = b;
        __syncthreads();
        if (t < 64) {
            float r = 1.f / (1.f + expf(-(gi[t] + gh[t])));
            float z = 1.f / (1.f + expf(-(gi[64 + t] + gh[64 + t])));
            float n = tanhf(gi[128 + t] + r * gh[128 + t]);
            float nh = (1.f - z) * n + z * hs[t];
            g_hidden[node * 64 + t] = nh;
            g_h[node * 64 + t] = nh;
            if (last) dout[node * 64 + t] = nh;
        }
        __syncthreads();
    }
}

// ---------------- launcher ----------------------------------------------------
extern "C" void kernel_launch(void* const* d_in, const int* in_sizes, int n_in,
                              void* d_out, int out_size) {
    const float* x     = (const float*)d_in[0];
    const float* ea    = (const float*)d_in[1];
    const float* Wn1   = (const float*)d_in[2];
    const float* bn1   = (const float*)d_in[3];
    const float* Wn2   = (const float*)d_in[4];
    const float* bn2   = (const float*)d_in[5];
    const float* Wn3   = (const float*)d_in[6];
    const float* bn3   = (const float*)d_in[7];
    const float* We1   = (const float*)d_in[8];
    const float* be1   = (const float*)d_in[9];
    const float* We2   = (const float*)d_in[10];
    const float* be2   = (const float*)d_in[11];
    const float* We3   = (const float*)d_in[12];
    const float* be3   = (const float*)d_in[13];
    const float* roots = (const float*)d_in[14];
    const float* cbias = (const float*)d_in[15];
    const float* gWih  = (const float*)d_in[16];
    const float* gWhh  = (const float*)d_in[17];
    const float* gbih  = (const float*)d_in[18];
    const float* gbhh  = (const float*)d_in[19];
    const int*   ei    = (const int*)d_in[20];
    float* dout = (float*)d_out;

    cudaFuncSetAttribute(k_gru, cudaFuncAttributeMaxDynamicSharedMemorySize, GRU_SMEM);
    cudaFuncSetAttribute(k_fused, cudaFuncAttributeMaxDynamicSharedMemorySize, FUSED_SMEM);

    k_zero_misc<<<128, 256>>>();
    k_node_mlp<<<296, 256>>>(x, Wn1, bn1, Wn2, bn2, Wn3, bn3);
    k_edge_mlp<<<296, 256>>>(ea, We1, be1, We2, be2);
    k_hist<<<200, 256>>>(ei);
    k_scan<<<1, 1024>>>();
    k_fill<<<200, 256>>>(ei);
    k_sort<<<(N_NODES + 255) / 256, 256>>>();
    k_buildBW<<<1024, 256>>>(We3);

    for (int l = 0; l < N_LAYERS; l++) {
        k_buildB2<<<16, 256>>>(roots, be3, l);
        k_hgT<<<(N_EDGES + 255) / 256, 256>>>(ei);
        k_fused<<<NTILES, 256, FUSED_SMEM>>>(ei, cbias, l);
        k_gru<<<296, 192, GRU_SMEM>>>(gWih, gWhh, gbih, gbhh, dout, l == N_LAYERS - 1);
    }
}

// round 8
// speedup vs baseline: 1.7006x; 1.7006x over previous
#include <cuda_runtime.h>
#include <cuda_bf16.h>
#include <cstdint>
#include <math.h>

#define N_NODES 25000
#define M_PAD   25088            // 196 * 128
#define N_EDGES 100000
#define H 64
#define K2 4224                  // 4096 (P edge part) + 64 (h for roots) + 64 (Q for be3)
#define N_LAYERS 3

// ---------------- scratch (static device globals) ---------------------------
__device__ float g_h[N_NODES * H];
__device__ float g_hidden[N_NODES * H];
__device__ float g_ew2[N_EDGES * H];
__device__ __align__(128) __nv_bfloat16 g_Phi[(size_t)M_PAD * K2];   // ~212 MB
__device__ __align__(128) __nv_bfloat16 g_Plo[(size_t)M_PAD * K2];   // ~212 MB
__device__ __align__(128) __nv_bfloat16 g_Bhi[H * K2];               // Bt[n][k]
__device__ __align__(128) __nv_bfloat16 g_Blo[H * K2];
__device__ float g_m[N_NODES * H];
__device__ int   g_deg[N_NODES];
__device__ int   g_off[N_NODES + 1];
__device__ int   g_cur[N_NODES];
__device__ int   g_csr[N_EDGES];

// ---------------- helpers ------------------------------------------------
__device__ __forceinline__ uint32_t smem_u32(const void* p) {
    uint32_t a;
    asm("{ .reg .u64 t; cvta.to.shared.u64 t, %1; cvt.u32.u64 %0, t; }" : "=r"(a) : "l"(p));
    return a;
}

__device__ __forceinline__ void mma16816(float* c, const uint32_t* a, uint32_t b0, uint32_t b1) {
    asm volatile("mma.sync.aligned.m16n8k16.row.col.f32.bf16.bf16.f32 "
        "{%0,%1,%2,%3}, {%4,%5,%6,%7}, {%8,%9}, {%0,%1,%2,%3};"
        : "+f"(c[0]), "+f"(c[1]), "+f"(c[2]), "+f"(c[3])
        : "r"(a[0]), "r"(a[1]), "r"(a[2]), "r"(a[3]), "r"(b0), "r"(b1));
}

__device__ __forceinline__ void ldsm_x4(uint32_t* r, uint32_t addr) {
    asm volatile("ldmatrix.sync.aligned.m8n8.x4.shared.b16 {%0,%1,%2,%3}, [%4];"
        : "=r"(r[0]), "=r"(r[1]), "=r"(r[2]), "=r"(r[3]) : "r"(addr));
}

__device__ __forceinline__ void split_bf(float v, __nv_bfloat16& hi, __nv_bfloat16& lo) {
    hi = __float2bfloat16(v);
    lo = __float2bfloat16(v - __bfloat162float(hi));
}
__device__ __forceinline__ uint32_t pack_bf2(__nv_bfloat16 a, __nv_bfloat16 b) {
    uint16_t ua = *(uint16_t*)&a, ub = *(uint16_t*)&b;
    return (uint32_t)ua | ((uint32_t)ub << 16);
}

// ---------------- zero init --------------------------------------------------
__global__ void k_zero_misc() {
    int i = blockIdx.x * blockDim.x + threadIdx.x;
    int st = gridDim.x * blockDim.x;
    for (int idx = i; idx < N_NODES; idx += st) g_deg[idx] = 0;
    for (int idx = i; idx < N_NODES * H; idx += st) g_hidden[idx] = 0.f;
    const size_t padN = (size_t)(M_PAD - N_NODES) * K2;
    __nv_bfloat16 z = __float2bfloat16(0.f);
    for (size_t idx = i; idx < padN; idx += st) {
        g_Phi[(size_t)N_NODES * K2 + idx] = z;
        g_Plo[(size_t)N_NODES * K2 + idx] = z;
    }
}

// ---------------- node MLP ---------------------------------------------------
__global__ void k_node_mlp(const float* __restrict__ x,
                           const float* __restrict__ W1, const float* __restrict__ b1,
                           const float* __restrict__ W2, const float* __restrict__ b2,
                           const float* __restrict__ W3, const float* __restrict__ b3) {
    __shared__ float W1T[32 * 64], W2T[64 * 64], W3T[64 * 64];
    __shared__ float b1s[64], b2s[64], b3s[64];
    __shared__ float xs[4][32], h1[4][64], h2[4][64];
    int tid = threadIdx.x;
    for (int idx = tid; idx < 32 * 64; idx += 256) { int o = idx / 32, j = idx % 32; W1T[j * 64 + o] = W1[idx]; }
    for (int idx = tid; idx < 64 * 64; idx += 256) { int o = idx / 64, j = idx % 64; W2T[j * 64 + o] = W2[idx]; W3T[j * 64 + o] = W3[idx]; }
    if (tid < 64) { b1s[tid] = b1[tid]; b2s[tid] = b2[tid]; b3s[tid] = b3[tid]; }
    __syncthreads();
    int nl = tid >> 6, o = tid & 63;
    for (int base = blockIdx.x * 4; base < N_NODES; base += gridDim.x * 4) {
        int node = base + nl;
        if (o < 32 && node < N_NODES) xs[nl][o] = x[node * 32 + o];
        __syncthreads();
        if (node < N_NODES) {
            float a = b1s[o];
            #pragma unroll
            for (int j = 0; j < 32; j++) a += xs[nl][j] * W1T[j * 64 + o];
            h1[nl][o] = fmaxf(a, 0.f);
        }
        __syncthreads();
        if (node < N_NODES) {
            float a = b2s[o];
            #pragma unroll
            for (int j = 0; j < 64; j++) a += h1[nl][j] * W2T[j * 64 + o];
            h2[nl][o] = fmaxf(a, 0.f);
        }
        __syncthreads();
        if (node < N_NODES) {
            float a = b3s[o];
            #pragma unroll
            for (int j = 0; j < 64; j++) a += h2[nl][j] * W3T[j * 64 + o];
            g_h[node * 64 + o] = a;
        }
        __syncthreads();
    }
}

// ---------------- edge MLP (layers 1,2) --------------------------------------
__global__ void k_edge_mlp(const float* __restrict__ ea,
                           const float* __restrict__ W1, const float* __restrict__ b1,
                           const float* __restrict__ W2, const float* __restrict__ b2) {
    __shared__ float W1T[16 * 64], W2T[64 * 64];
    __shared__ float b1s[64], b2s[64];
    __shared__ float es[4][16], h1[4][64];
    int tid = threadIdx.x;
    for (int idx = tid; idx < 16 * 64; idx += 256) { int o = idx >> 4, j = idx & 15; W1T[j * 64 + o] = W1[idx]; }
    for (int idx = tid; idx < 64 * 64; idx += 256) { int o = idx >> 6, j = idx & 63; W2T[j * 64 + o] = W2[idx]; }
    if (tid < 64) { b1s[tid] = b1[tid]; b2s[tid] = b2[tid]; }
    __syncthreads();
    int nl = tid >> 6, o = tid & 63;
    for (int base = blockIdx.x * 4; base < N_EDGES; base += gridDim.x * 4) {
        int e = base + nl;
        if (o < 16 && e < N_EDGES) es[nl][o] = ea[e * 16 + o];
        __syncthreads();
        if (e < N_EDGES) {
            float a = b1s[o];
            #pragma unroll
            for (int j = 0; j < 16; j++) a += es[nl][j] * W1T[j * 64 + o];
            h1[nl][o] = fmaxf(a, 0.f);
        }
        __syncthreads();
        if (e < N_EDGES) {
            float a = b2s[o];
            #pragma unroll
            for (int j = 0; j < 64; j++) a += h1[nl][j] * W2T[j * 64 + o];
            g_ew2[e * 64 + o] = fmaxf(a, 0.f);
        }
        __syncthreads();
    }
}

// ---------------- CSR build --------------------------------------------------
__global__ void k_hist(const int* __restrict__ ei) {
    int i = blockIdx.x * blockDim.x + threadIdx.x, st = gridDim.x * blockDim.x;
    for (int e = i; e < N_EDGES; e += st) atomicAdd(&g_deg[ei[N_EDGES + e]], 1);
}

__global__ void k_scan() {
    __shared__ int part[1024];
    int t = threadIdx.x;
    const int CH = (N_NODES + 1023) / 1024;
    int b0 = t * CH, b1 = min(b0 + CH, N_NODES);
    int s = 0;
    for (int i = b0; i < b1; i++) s += g_deg[i];
    part[t] = s;
    __syncthreads();
    for (int d = 1; d < 1024; d <<= 1) {
        int v = (t >= d) ? part[t - d] : 0;
        __syncthreads();
        part[t] += v;
        __syncthreads();
    }
    int run = (t == 0) ? 0 : part[t - 1];
    for (int i = b0; i < b1; i++) { g_off[i] = run; g_cur[i] = run; run += g_deg[i]; }
    if (t == 1023) g_off[N_NODES] = part[1023];
}

__global__ void k_fill(const int* __restrict__ ei) {
    int i = blockIdx.x * blockDim.x + threadIdx.x, st = gridDim.x * blockDim.x;
    for (int e = i; e < N_EDGES; e += st) {
        int d = ei[N_EDGES + e];
        int p = atomicAdd(&g_cur[d], 1);
        g_csr[p] = e;
    }
}

__global__ void k_sort() {
    int d = blockIdx.x * blockDim.x + threadIdx.x;
    if (d >= N_NODES) return;
    int a = g_off[d], b = g_off[d + 1];
    for (int i = a + 1; i < b; i++) {
        int v = g_csr[i];
        int j = i - 1;
        while (j >= a && g_csr[j] > v) { g_csr[j + 1] = g_csr[j]; j--; }
        g_csr[j + 1] = v;
    }
}

// ---------------- build Bt[n][k] (bf16 hi/lo) for layer l --------------------
__global__ void k_buildB(const float* __restrict__ We3, const float* __restrict__ be3,
                         const float* __restrict__ roots, int l) {
    int i0 = blockIdx.x * blockDim.x + threadIdx.x, st = gridDim.x * blockDim.x;
    for (int idx = i0; idx < H * K2; idx += st) {
        int n = idx / K2, kg = idx % K2;
        float v;
        if (kg < 4096)      { int i = kg >> 6, k = kg & 63; v = We3[((i << 6) + n) * 64 + k]; }
        else if (kg < 4160) { v = roots[(l * 64 + (kg - 4096)) * 64 + n]; }
        else                { v = be3[((kg - 4160) << 6) + n]; }
        __nv_bfloat16 hi, lo;
        split_bf(v, hi, lo);
        g_Bhi[idx] = hi;
        g_Blo[idx] = lo;
    }
}

// ---------------- build P rows (register accumulation) ------------------------
__global__ void __launch_bounds__(128) k_buildP(const int* __restrict__ ei) {
    __shared__ float stg[2][64][68];
    int tid = threadIdx.x, warp = tid >> 5, lane = tid & 31;
    int ns_w = warp >> 1, kh = warp & 1;
    int d = blockIdx.x * 2 + ns_w;
    int kcol = kh * 32 + lane;

    float acc[64];
    #pragma unroll
    for (int i = 0; i < 64; i++) acc[i] = 0.f;

    int off0 = g_off[d];
    int deg = g_off[d + 1] - off0;
    for (int j = 0; j < deg; j++) {
        int e = g_csr[off0 + j];
        int s = ei[e];
        float ew = g_ew2[e * 64 + kcol];
        const float4* hr = (const float4*)(g_h + s * 64);
        #pragma unroll
        for (int i4 = 0; i4 < 16; i4++) {
            float4 hv = hr[i4];
            acc[i4 * 4 + 0] += hv.x * ew;
            acc[i4 * 4 + 1] += hv.y * ew;
            acc[i4 * 4 + 2] += hv.z * ew;
            acc[i4 * 4 + 3] += hv.w * ew;
        }
    }
    #pragma unroll
    for (int i = 0; i < 64; i++) stg[ns_w][i][kcol] = acc[i];
    __syncthreads();

    #pragma unroll 1
    for (int ns = 0; ns < 2; ns++) {
        int dn = blockIdx.x * 2 + ns;
        size_t rb = (size_t)dn * K2;
        uint2* phi = (uint2*)(g_Phi + rb);
        uint2* plo = (uint2*)(g_Plo + rb);
        for (int t4 = tid; t4 < 1024; t4 += 128) {
            int i = t4 >> 4, c4 = t4 & 15;
            float4 v = *(const float4*)&stg[ns][i][c4 * 4];
            __nv_bfloat16 h0, l0, h1, l1, h2, l2, h3, l3;
            split_bf(v.x, h0, l0); split_bf(v.y, h1, l1);
            split_bf(v.z, h2, l2); split_bf(v.w, h3, l3);
            uint2 hv2, lv2;
            hv2.x = pack_bf2(h0, h1); hv2.y = pack_bf2(h2, h3);
            lv2.x = pack_bf2(l0, l1); lv2.y = pack_bf2(l2, l3);
            phi[t4] = hv2;
            plo[t4] = lv2;
        }
    }

    {
        int ns = tid >> 6, i = tid & 63;
        int dn = blockIdx.x * 2 + ns;
        size_t rb = (size_t)dn * K2;
        __nv_bfloat16 hi, lo;
        float hv = g_h[dn * 64 + i];
        split_bf(hv, hi, lo);
        g_Phi[rb + 4096 + i] = hi;
        g_Plo[rb + 4096 + i] = lo;
        int o0 = g_off[dn], dg = g_off[dn + 1] - o0;
        float q = 0.f;
        for (int j = 0; j < dg; j++) q += g_h[ei[g_csr[o0 + j]] * 64 + i];
        split_bf(q, hi, lo);
        g_Phi[rb + 4160 + i] = hi;
        g_Plo[rb + 4160 + i] = lo;
    }
}

// ---------------- mma.sync GEMM with ldmatrix: m = P @ Bt^T + cbias -----------
// 256 threads / 8 warps, M-tile 128 (16 rows/warp), N=64, K-blocks of 32,
// 3-stage cp.async pipeline. Padded rows of 40 bf16 (80B): ldmatrix row
// addresses land on a bank permutation -> conflict-free.
#define NKB2 132                 // K2 / 32
#define ST_AHI 0
#define ST_ALO 5120
#define ST_BHI 10240
#define ST_BLO 12800
#define ST_ELEMS 15360           // 30720 bytes
#define GEMM_SMEM (3 * ST_ELEMS * 2)

__device__ __forceinline__ void load_stage32(__nv_bfloat16* st, int m0, int kb, int tid) {
    #pragma unroll
    for (int q = 0; q < 6; q++) {
        int c = q * 256 + tid;                  // 1536 chunks of 16B
        const __nv_bfloat16* src;
        __nv_bfloat16* dst;
        if (c < 1024) {                          // A: 2 planes x 128 rows x 4 chunks
            int half = c >> 9, cc = c & 511;
            int row = cc >> 2, c4 = cc & 3;
            const __nv_bfloat16* g = half ? g_Plo : g_Phi;
            src = g + (size_t)(m0 + row) * K2 + kb * 32 + c4 * 8;
            dst = st + (half ? ST_ALO : ST_AHI) + row * 40 + c4 * 8;
        } else {                                 // B: 2 planes x 64 rows x 4 chunks
            int c2 = c - 1024;
            int half = c2 >> 8, cc = c2 & 255;
            int row = cc >> 2, c4 = cc & 3;
            const __nv_bfloat16* g = half ? g_Blo : g_Bhi;
            src = g + (size_t)row * K2 + kb * 32 + c4 * 8;
            dst = st + (half ? ST_BLO : ST_BHI) + row * 40 + c4 * 8;
        }
        asm volatile("cp.async.cg.shared.global [%0], [%1], 16;" :: "r"(smem_u32(dst)), "l"(src));
    }
    asm volatile("cp.async.commit_group;" ::: "memory");
}

__global__ void __launch_bounds__(256, 2) k_gemm_mma(const float* __restrict__ cbias, int l) {
    extern __shared__ __align__(16) __nv_bfloat16 sm[];
    const int tid = threadIdx.x, w = tid >> 5, lane = tid & 31;
    const int m0 = blockIdx.x * 128;
    const int lq = lane >> 2;          // 0..7
    const int lr = lane & 3;           // 0..3

    // ldmatrix lane-address components
    const int l7 = lane & 7;
    const int lbit = (lane >> 3) & 1;
    const int csel = (lane >> 4) ? 8 : 0;      // k+8 half for matrices 2,3
    const int arow = w * 16 + l7 + lbit * 8;
    const uint32_t aoff_hi = (uint32_t)(ST_AHI + arow * 40 + csel) * 2;
    const uint32_t aoff_lo = (uint32_t)(ST_ALO + arow * 40 + csel) * 2;
    uint32_t boff_hi[4], boff_lo[4];
    #pragma unroll
    for (int g = 0; g < 4; g++) {
        int brow = g * 16 + l7 + lbit * 8;
        boff_hi[g] = (uint32_t)(ST_BHI + brow * 40 + csel) * 2;
        boff_lo[g] = (uint32_t)(ST_BLO + brow * 40 + csel) * 2;
    }

    float acc[8][4];
    #pragma unroll
    for (int na = 0; na < 8; na++)
        #pragma unroll
        for (int v = 0; v < 4; v++) acc[na][v] = 0.f;

    load_stage32(sm + 0 * ST_ELEMS, m0, 0, tid);
    load_stage32(sm + 1 * ST_ELEMS, m0, 1, tid);
    load_stage32(sm + 2 * ST_ELEMS, m0, 2, tid);

    int slot = 0;
    for (int blk = 0; blk < NKB2; blk++) {
        int rem = NKB2 - 1 - blk;
        if (rem >= 2)      asm volatile("cp.async.wait_group 2;" ::: "memory");
        else if (rem == 1) asm volatile("cp.async.wait_group 1;" ::: "memory");
        else               asm volatile("cp.async.wait_group 0;" ::: "memory");
        __syncthreads();
        uint32_t sb = smem_u32(sm + slot * ST_ELEMS);

        #pragma unroll
        for (int s = 0; s < 2; s++) {
            uint32_t k0b = (uint32_t)(s * 16) * 2;
            uint32_t ahi[4], alo[4];
            ldsm_x4(ahi, sb + aoff_hi + k0b);
            ldsm_x4(alo, sb + aoff_lo + k0b);
            #pragma unroll
            for (int g = 0; g < 4; g++) {
                uint32_t bh[4], bl[4];
                ldsm_x4(bh, sb + boff_hi[g] + k0b);
                ldsm_x4(bl, sb + boff_lo[g] + k0b);
                mma16816(acc[2 * g],     ahi, bh[0], bh[2]);
                mma16816(acc[2 * g],     ahi, bl[0], bl[2]);
                mma16816(acc[2 * g],     alo, bh[0], bh[2]);
                mma16816(acc[2 * g + 1], ahi, bh[1], bh[3]);
                mma16816(acc[2 * g + 1], ahi, bl[1], bl[3]);
                mma16816(acc[2 * g + 1], alo, bh[1], bh[3]);
            }
        }
        __syncthreads();
        if (blk + 3 < NKB2) load_stage32(sm + slot * ST_ELEMS, m0, blk + 3, tid);
        slot = (slot == 2) ? 0 : slot + 1;
    }

    // epilogue: rows m0 + w*16 + lq (+8), cols na*8 + lr*2 (+1)
    int r0 = m0 + w * 16 + lq;
    #pragma unroll
    for (int na = 0; na < 8; na++) {
        int c0 = na * 8 + lr * 2;
        float bx = cbias[l * 64 + c0], by = cbias[l * 64 + c0 + 1];
        if (r0 < N_NODES) {
            g_m[r0 * 64 + c0]     = acc[na][0] + bx;
            g_m[r0 * 64 + c0 + 1] = acc[na][1] + by;
        }
        if (r0 + 8 < N_NODES) {
            g_m[(r0 + 8) * 64 + c0]     = acc[na][2] + bx;
            g_m[(r0 + 8) * 64 + c0 + 1] = acc[na][3] + by;
        }
    }
}

// ---------------- GRU step (2 nodes per iteration) ----------------------------
#define GRU_SMEM ((12288 * 2 + 192 * 2 + 64 * 4 + 192 * 4) * 4)
__global__ void k_gru(const float* __restrict__ Wih, const float* __restrict__ Whh,
                      const float* __restrict__ bih, const float* __restrict__ bhh,
                      float* __restrict__ dout, int last) {
    extern __shared__ float smf[];
    float* WihT = smf;                  // [i*192 + t]
    float* WhhT = smf + 12288;
    float* bihs = smf + 24576;
    float* bhhs = bihs + 192;
    float* ms   = bhhs + 192;           // 2 x 64
    float* hs   = ms + 128;             // 2 x 64
    float* gi   = hs + 128;             // 2 x 192
    float* gh   = gi + 384;             // 2 x 192
    int t = threadIdx.x;                // 192 threads
    for (int idx = t; idx < 192 * 64; idx += 192) {
        int j = idx / 64, i = idx % 64;
        WihT[i * 192 + j] = Wih[idx];
        WhhT[i * 192 + j] = Whh[idx];
    }
    bihs[t] = bih[t]; bhhs[t] = bhh[t];
    __syncthreads();
    for (int pair = blockIdx.x; pair < N_NODES / 2; pair += gridDim.x) {
        int n0 = pair * 2;
        if (t < 64) {
            ms[t]       = g_m[n0 * 64 + t];
            ms[64 + t]  = g_m[(n0 + 1) * 64 + t];
            hs[t]       = g_hidden[n0 * 64 + t];
            hs[64 + t]  = g_hidden[(n0 + 1) * 64 + t];
        }
        __syncthreads();
        float a0 = bihs[t], a1 = bihs[t], b0 = bhhs[t], b1 = bhhs[t];
        #pragma unroll 8
        for (int i = 0; i < 64; i++) {
            float w1 = WihT[i * 192 + t];
            float w2 = WhhT[i * 192 + t];
            a0 += ms[i] * w1;
            a1 += ms[64 + i] * w1;
            b0 += hs[i] * w2;
            b1 += hs[64 + i] * w2;
        }
        gi[t] = a0; gi[192 + t] = a1;
        gh[t] = b0; gh[192 + t] = b1;
        __syncthreads();
        if (t < 128) {
            int ns = t >> 6, tt = t & 63;
            int node = n0 + ns;
            const float* gin = gi + ns * 192;
            const float* ghn = gh + ns * 192;
            float r = 1.f / (1.f + expf(-(gin[tt] + ghn[tt])));
            float z = 1.f / (1.f + expf(-(gin[64 + tt] + ghn[64 + tt])));
            float n = tanhf(gin[128 + tt] + r * ghn[128 + tt]);
            float nh = (1.f - z) * n + z * hs[ns * 64 + tt];
            g_hidden[node * 64 + tt] = nh;
            g_h[node * 64 + tt] = nh;
            if (last) dout[node * 64 + tt] = nh;
        }
        __syncthreads();
    }
}

// ---------------- launcher ----------------------------------------------------
extern "C" void kernel_launch(void* const* d_in, const int* in_sizes, int n_in,
                              void* d_out, int out_size) {
    const float* x     = (const float*)d_in[0];
    const float* ea    = (const float*)d_in[1];
    const float* Wn1   = (const float*)d_in[2];
    const float* bn1   = (const float*)d_in[3];
    const float* Wn2   = (const float*)d_in[4];
    const float* bn2   = (const float*)d_in[5];
    const float* Wn3   = (const float*)d_in[6];
    const float* bn3   = (const float*)d_in[7];
    const float* We1   = (const float*)d_in[8];
    const float* be1   = (const float*)d_in[9];
    const float* We2   = (const float*)d_in[10];
    const float* be2   = (const float*)d_in[11];
    const float* We3   = (const float*)d_in[12];
    const float* be3   = (const float*)d_in[13];
    const float* roots = (const float*)d_in[14];
    const float* cbias = (const float*)d_in[15];
    const float* gWih  = (const float*)d_in[16];
    const float* gWhh  = (const float*)d_in[17];
    const float* gbih  = (const float*)d_in[18];
    const float* gbhh  = (const float*)d_in[19];
    const int*   ei    = (const int*)d_in[20];
    float* dout = (float*)d_out;

    cudaFuncSetAttribute(k_gru, cudaFuncAttributeMaxDynamicSharedMemorySize, GRU_SMEM);
    cudaFuncSetAttribute(k_gemm_mma, cudaFuncAttributeMaxDynamicSharedMemorySize, GEMM_SMEM);

    k_zero_misc<<<400, 256>>>();
    k_node_mlp<<<296, 256>>>(x, Wn1, bn1, Wn2, bn2, Wn3, bn3);
    k_edge_mlp<<<296, 256>>>(ea, We1, be1, We2, be2);
    k_hist<<<200, 256>>>(ei);
    k_scan<<<1, 1024>>>();
    k_fill<<<200, 256>>>(ei);
    k_sort<<<(N_NODES + 255) / 256, 256>>>();

    for (int l = 0; l < N_LAYERS; l++) {
        k_buildB<<<264, 256>>>(We3, be3, roots, l);
        k_buildP<<<N_NODES / 2, 128>>>(ei);
        k_gemm_mma<<<M_PAD / 128, 256, GEMM_SMEM>>>(cbias, l);
        k_gru<<<296, 192, GRU_SMEM>>>(gWih, gWhh, gbih, gbhh, dout, l == N_LAYERS - 1);
    }
}

// round 9
// speedup vs baseline: 1.7240x; 1.0137x over previous
#include <cuda_runtime.h>
#include <cuda_bf16.h>
#include <cstdint>
#include <math.h>

#define N_NODES 25000
#define M_PAD   25088            // 196 * 128
#define N_EDGES 100000
#define H 64
#define K2 4224                  // 4096 (P edge part) + 64 (h for roots) + 64 (Q for be3)
#define N_LAYERS 3

// ---------------- scratch (static device globals) ---------------------------
__device__ float g_h[N_NODES * H];
__device__ float g_hidden[N_NODES * H];
__device__ float g_ew2[N_EDGES * H];
__device__ __align__(128) float g_P[(size_t)M_PAD * K2];             // ~424 MB fp32
__device__ __align__(128) __nv_bfloat16 g_Bhi[H * K2];               // Bt[n][k]
__device__ __align__(128) __nv_bfloat16 g_Blo[H * K2];
__device__ float g_m[N_NODES * H];
__device__ int   g_deg[N_NODES];
__device__ int   g_off[N_NODES + 1];
__device__ int   g_cur[N_NODES];
__device__ int   g_csr[N_EDGES];

// ---------------- helpers ------------------------------------------------
__device__ __forceinline__ uint32_t smem_u32(const void* p) {
    uint32_t a;
    asm("{ .reg .u64 t; cvta.to.shared.u64 t, %1; cvt.u32.u64 %0, t; }" : "=r"(a) : "l"(p));
    return a;
}

__device__ __forceinline__ void mma16816(float* c, const uint32_t* a, uint32_t b0, uint32_t b1) {
    asm volatile("mma.sync.aligned.m16n8k16.row.col.f32.bf16.bf16.f32 "
        "{%0,%1,%2,%3}, {%4,%5,%6,%7}, {%8,%9}, {%0,%1,%2,%3};"
        : "+f"(c[0]), "+f"(c[1]), "+f"(c[2]), "+f"(c[3])
        : "r"(a[0]), "r"(a[1]), "r"(a[2]), "r"(a[3]), "r"(b0), "r"(b1));
}

__device__ __forceinline__ void ldsm_x4(uint32_t* r, uint32_t addr) {
    asm volatile("ldmatrix.sync.aligned.m8n8.x4.shared.b16 {%0,%1,%2,%3}, [%4];"
        : "=r"(r[0]), "=r"(r[1]), "=r"(r[2]), "=r"(r[3]) : "r"(addr));
}

__device__ __forceinline__ void split_bf(float v, __nv_bfloat16& hi, __nv_bfloat16& lo) {
    hi = __float2bfloat16(v);
    lo = __float2bfloat16(v - __bfloat162float(hi));
}

// ---------------- zero init --------------------------------------------------
__global__ void k_zero_misc() {
    int i = blockIdx.x * blockDim.x + threadIdx.x;
    int st = gridDim.x * blockDim.x;
    for (int idx = i; idx < N_NODES; idx += st) g_deg[idx] = 0;
    for (int idx = i; idx < N_NODES * H; idx += st) g_hidden[idx] = 0.f;
    const size_t padN = (size_t)(M_PAD - N_NODES) * K2;
    for (size_t idx = i; idx < padN; idx += st)
        g_P[(size_t)N_NODES * K2 + idx] = 0.f;
}

// ---------------- node MLP ---------------------------------------------------
__global__ void k_node_mlp(const float* __restrict__ x,
                           const float* __restrict__ W1, const float* __restrict__ b1,
                           const float* __restrict__ W2, const float* __restrict__ b2,
                           const float* __restrict__ W3, const float* __restrict__ b3) {
    __shared__ float W1T[32 * 64], W2T[64 * 64], W3T[64 * 64];
    __shared__ float b1s[64], b2s[64], b3s[64];
    __shared__ float xs[4][32], h1[4][64], h2[4][64];
    int tid = threadIdx.x;
    for (int idx = tid; idx < 32 * 64; idx += 256) { int o = idx / 32, j = idx % 32; W1T[j * 64 + o] = W1[idx]; }
    for (int idx = tid; idx < 64 * 64; idx += 256) { int o = idx / 64, j = idx % 64; W2T[j * 64 + o] = W2[idx]; W3T[j * 64 + o] = W3[idx]; }
    if (tid < 64) { b1s[tid] = b1[tid]; b2s[tid] = b2[tid]; b3s[tid] = b3[tid]; }
    __syncthreads();
    int nl = tid >> 6, o = tid & 63;
    for (int base = blockIdx.x * 4; base < N_NODES; base += gridDim.x * 4) {
        int node = base + nl;
        if (o < 32 && node < N_NODES) xs[nl][o] = x[node * 32 + o];
        __syncthreads();
        if (node < N_NODES) {
            float a = b1s[o];
            #pragma unroll
            for (int j = 0; j < 32; j++) a += xs[nl][j] * W1T[j * 64 + o];
            h1[nl][o] = fmaxf(a, 0.f);
        }
        __syncthreads();
        if (node < N_NODES) {
            float a = b2s[o];
            #pragma unroll
            for (int j = 0; j < 64; j++) a += h1[nl][j] * W2T[j * 64 + o];
            h2[nl][o] = fmaxf(a, 0.f);
        }
        __syncthreads();
        if (node < N_NODES) {
            float a = b3s[o];
            #pragma unroll
            for (int j = 0; j < 64; j++) a += h2[nl][j] * W3T[j * 64 + o];
            g_h[node * 64 + o] = a;
        }
        __syncthreads();
    }
}

// ---------------- edge MLP (layers 1,2) --------------------------------------
__global__ void k_edge_mlp(const float* __restrict__ ea,
                           const float* __restrict__ W1, const float* __restrict__ b1,
                           const float* __restrict__ W2, const float* __restrict__ b2) {
    __shared__ float W1T[16 * 64], W2T[64 * 64];
    __shared__ float b1s[64], b2s[64];
    __shared__ float es[4][16], h1[4][64];
    int tid = threadIdx.x;
    for (int idx = tid; idx < 16 * 64; idx += 256) { int o = idx >> 4, j = idx & 15; W1T[j * 64 + o] = W1[idx]; }
    for (int idx = tid; idx < 64 * 64; idx += 256) { int o = idx >> 6, j = idx & 63; W2T[j * 64 + o] = W2[idx]; }
    if (tid < 64) { b1s[tid] = b1[tid]; b2s[tid] = b2[tid]; }
    __syncthreads();
    int nl = tid >> 6, o = tid & 63;
    for (int base = blockIdx.x * 4; base < N_EDGES; base += gridDim.x * 4) {
        int e = base + nl;
        if (o < 16 && e < N_EDGES) es[nl][o] = ea[e * 16 + o];
        __syncthreads();
        if (e < N_EDGES) {
            float a = b1s[o];
            #pragma unroll
            for (int j = 0; j < 16; j++) a += es[nl][j] * W1T[j * 64 + o];
            h1[nl][o] = fmaxf(a, 0.f);
        }
        __syncthreads();
        if (e < N_EDGES) {
            float a = b2s[o];
            #pragma unroll
            for (int j = 0; j < 64; j++) a += h1[nl][j] * W2T[j * 64 + o];
            g_ew2[e * 64 + o] = fmaxf(a, 0.f);
        }
        __syncthreads();
    }
}

// ---------------- CSR build --------------------------------------------------
__global__ void k_hist(const int* __restrict__ ei) {
    int i = blockIdx.x * blockDim.x + threadIdx.x, st = gridDim.x * blockDim.x;
    for (int e = i; e < N_EDGES; e += st) atomicAdd(&g_deg[ei[N_EDGES + e]], 1);
}

__global__ void k_scan() {
    __shared__ int part[1024];
    int t = threadIdx.x;
    const int CH = (N_NODES + 1023) / 1024;
    int b0 = t * CH, b1 = min(b0 + CH, N_NODES);
    int s = 0;
    for (int i = b0; i < b1; i++) s += g_deg[i];
    part[t] = s;
    __syncthreads();
    for (int d = 1; d < 1024; d <<= 1) {
        int v = (t >= d) ? part[t - d] : 0;
        __syncthreads();
        part[t] += v;
        __syncthreads();
    }
    int run = (t == 0) ? 0 : part[t - 1];
    for (int i = b0; i < b1; i++) { g_off[i] = run; g_cur[i] = run; run += g_deg[i]; }
    if (t == 1023) g_off[N_NODES] = part[1023];
}

__global__ void k_fill(const int* __restrict__ ei) {
    int i = blockIdx.x * blockDim.x + threadIdx.x, st = gridDim.x * blockDim.x;
    for (int e = i; e < N_EDGES; e += st) {
        int d = ei[N_EDGES + e];
        int p = atomicAdd(&g_cur[d], 1);
        g_csr[p] = e;
    }
}

__global__ void k_sort() {
    int d = blockIdx.x * blockDim.x + threadIdx.x;
    if (d >= N_NODES) return;
    int a = g_off[d], b = g_off[d + 1];
    for (int i = a + 1; i < b; i++) {
        int v = g_csr[i];
        int j = i - 1;
        while (j >= a && g_csr[j] > v) { g_csr[j + 1] = g_csr[j]; j--; }
        g_csr[j + 1] = v;
    }
}

// ---------------- build Bt[n][k] (bf16 hi/lo) for layer l --------------------
__global__ void k_buildB(const float* __restrict__ We3, const float* __restrict__ be3,
                         const float* __restrict__ roots, int l) {
    int i0 = blockIdx.x * blockDim.x + threadIdx.x, st = gridDim.x * blockDim.x;
    for (int idx = i0; idx < H * K2; idx += st) {
        int n = idx / K2, kg = idx % K2;
        float v;
        if (kg < 4096)      { int i = kg >> 6, k = kg & 63; v = We3[((i << 6) + n) * 64 + k]; }
        else if (kg < 4160) { v = roots[(l * 64 + (kg - 4096)) * 64 + n]; }
        else                { v = be3[((kg - 4160) << 6) + n]; }
        __nv_bfloat16 hi, lo;
        split_bf(v, hi, lo);
        g_Bhi[idx] = hi;
        g_Blo[idx] = lo;
    }
}

// ---------------- build P rows (fp32, register accumulation, direct stores) ---
__global__ void __launch_bounds__(128) k_buildP(const int* __restrict__ ei) {
    int tid = threadIdx.x, warp = tid >> 5, lane = tid & 31;
    int ns_w = warp >> 1, kh = warp & 1;
    int d = blockIdx.x * 2 + ns_w;
    int kcol = kh * 32 + lane;

    float acc[64];
    #pragma unroll
    for (int i = 0; i < 64; i++) acc[i] = 0.f;

    int off0 = g_off[d];
    int deg = g_off[d + 1] - off0;
    for (int j = 0; j < deg; j++) {
        int e = g_csr[off0 + j];               // sorted -> deterministic order
        int s = ei[e];
        float ew = g_ew2[e * 64 + kcol];
        const float4* hr = (const float4*)(g_h + s * 64);
        #pragma unroll
        for (int i4 = 0; i4 < 16; i4++) {
            float4 hv = hr[i4];
            acc[i4 * 4 + 0] += hv.x * ew;
            acc[i4 * 4 + 1] += hv.y * ew;
            acc[i4 * 4 + 2] += hv.z * ew;
            acc[i4 * 4 + 3] += hv.w * ew;
        }
    }
    // direct coalesced writeout: lane -> column kcol, rows i
    size_t rb = (size_t)d * K2;
    #pragma unroll
    for (int i = 0; i < 64; i++)
        g_P[rb + i * 64 + kcol] = acc[i];

    // tail rows: h (4096..4159) and Q (4160..4223) for both nodes of the block
    {
        int ns = tid >> 6, i = tid & 63;
        int dn = blockIdx.x * 2 + ns;
        size_t rb2 = (size_t)dn * K2;
        g_P[rb2 + 4096 + i] = g_h[dn * 64 + i];
        int o0 = g_off[dn], dg = g_off[dn + 1] - o0;
        float q = 0.f;
        for (int j = 0; j < dg; j++) q += g_h[ei[g_csr[o0 + j]] * 64 + i];
        g_P[rb2 + 4160 + i] = q;
    }
}

// ---------------- GEMM: fp32 A staged, in-kernel bf16 hi/lo split, ldmatrix ---
// smem bytes:
//   AF (fp32 A stages, 3x): stage s at s*20480; row stride 160B (40 floats)
//   B  (bf16 hi/lo stages, 3x): 61440 + s*10240; hi at +0 (64x40x2B), lo at +5120
//   ABUF (bf16 convert output): hi at 92160, lo at 102400; row stride 80B (40 bf16)
#define NKB2 132                 // K2 / 32
#define AF_OFF   0
#define AF_STAGE 20480
#define B_OFF    61440
#define B_STAGE  10240
#define ABUF_HI  92160
#define ABUF_LO  102400
#define GEMM_SMEM 112640

__device__ __forceinline__ void load_stageF(char* smb, int slot, int m0, int kb, int tid) {
    // A fp32: 128 rows x 8 chunks(16B) = 1024
    char* afs = smb + AF_OFF + slot * AF_STAGE;
    #pragma unroll
    for (int q = 0; q < 4; q++) {
        int c = q * 256 + tid;
        int row = c >> 3, c8 = c & 7;
        const float* src = g_P + (size_t)(m0 + row) * K2 + kb * 32 + c8 * 4;
        uint32_t dst = smem_u32(afs + row * 160 + c8 * 16);
        asm volatile("cp.async.cg.shared.global [%0], [%1], 16;" :: "r"(dst), "l"(src));
    }
    // B bf16: 2 planes x 64 rows x 4 chunks(16B) = 512
    char* bst = smb + B_OFF + slot * B_STAGE;
    #pragma unroll
    for (int q = 0; q < 2; q++) {
        int c = q * 256 + tid;
        int half = c >> 8, cc = c & 255;
        int row = cc >> 2, c4 = cc & 3;
        const __nv_bfloat16* src = (half ? g_Blo : g_Bhi) + (size_t)row * K2 + kb * 32 + c4 * 8;
        uint32_t dst = smem_u32(bst + half * 5120 + row * 80 + c4 * 16);
        asm volatile("cp.async.cg.shared.global [%0], [%1], 16;" :: "r"(dst), "l"(src));
    }
    asm volatile("cp.async.commit_group;" ::: "memory");
}

__global__ void __launch_bounds__(256, 2) k_gemm_mma(const float* __restrict__ cbias, int l) {
    extern __shared__ __align__(16) char smb[];
    const int tid = threadIdx.x, w = tid >> 5, lane = tid & 31;
    const int m0 = blockIdx.x * 128;
    const int lq = lane >> 2;          // 0..7
    const int lr = lane & 3;           // 0..3

    // ldmatrix lane-address components (rows of 40 bf16 = 80B)
    const int l7 = lane & 7;
    const int lbit = (lane >> 3) & 1;
    const int csel = (lane >> 4) ? 16 : 0;      // byte offset for k+8 half
    const int arow = w * 16 + l7 + lbit * 8;
    const uint32_t aoff_hi = (uint32_t)(ABUF_HI + arow * 80 + csel);
    const uint32_t aoff_lo = (uint32_t)(ABUF_LO + arow * 80 + csel);
    uint32_t brow_off[4];
    #pragma unroll
    for (int g = 0; g < 4; g++)
        brow_off[g] = (uint32_t)((g * 16 + l7 + lbit * 8) * 80 + csel);

    // convert-phase mapping: thread -> row r, 16 cols starting c0
    const int cr = tid >> 1;
    const int cc0 = (tid & 1) * 16;
    const float* cvt_src_base = (const float*)(smb + AF_OFF + cr * 160) + cc0;
    char* abuf_hi_dst = smb + ABUF_HI + cr * 80 + cc0 * 2;
    char* abuf_lo_dst = smb + ABUF_LO + cr * 80 + cc0 * 2;

    float acc[8][4];
    #pragma unroll
    for (int na = 0; na < 8; na++)
        #pragma unroll
        for (int v = 0; v < 4; v++) acc[na][v] = 0.f;

    load_stageF(smb, 0, m0, 0, tid);
    load_stageF(smb, 1, m0, 1, tid);
    load_stageF(smb, 2, m0, 2, tid);

    uint32_t sb = smem_u32(smb);
    int slot = 0;
    for (int blk = 0; blk < NKB2; blk++) {
        int rem = NKB2 - 1 - blk;
        if (rem >= 2)      asm volatile("cp.async.wait_group 2;" ::: "memory");
        else if (rem == 1) asm volatile("cp.async.wait_group 1;" ::: "memory");
        else               asm volatile("cp.async.wait_group 0;" ::: "memory");
        __syncthreads();

        // convert fp32 stage -> bf16 hi/lo ABUF (truncation split)
        {
            const float* s4 = cvt_src_base + slot * (AF_STAGE / 4);
            #pragma unroll
            for (int g = 0; g < 2; g++) {
                float4 a = *(const float4*)(s4 + g * 8);
                float4 b = *(const float4*)(s4 + g * 8 + 4);
                uint32_t hp0 = __byte_perm(__float_as_uint(a.x), __float_as_uint(a.y), 0x7632);
                uint32_t hp1 = __byte_perm(__float_as_uint(a.z), __float_as_uint(a.w), 0x7632);
                uint32_t hp2 = __byte_perm(__float_as_uint(b.x), __float_as_uint(b.y), 0x7632);
                uint32_t hp3 = __byte_perm(__float_as_uint(b.z), __float_as_uint(b.w), 0x7632);
                float l0 = a.x - __uint_as_float(__float_as_uint(a.x) & 0xffff0000u);
                float l1 = a.y - __uint_as_float(__float_as_uint(a.y) & 0xffff0000u);
                float l2 = a.z - __uint_as_float(__float_as_uint(a.z) & 0xffff0000u);
                float l3 = a.w - __uint_as_float(__float_as_uint(a.w) & 0xffff0000u);
                float l4 = b.x - __uint_as_float(__float_as_uint(b.x) & 0xffff0000u);
                float l5 = b.y - __uint_as_float(__float_as_uint(b.y) & 0xffff0000u);
                float l6 = b.z - __uint_as_float(__float_as_uint(b.z) & 0xffff0000u);
                float l7f = b.w - __uint_as_float(__float_as_uint(b.w) & 0xffff0000u);
                __nv_bfloat162 lp0 = __float22bfloat162_rn(make_float2(l0, l1));
                __nv_bfloat162 lp1 = __float22bfloat162_rn(make_float2(l2, l3));
                __nv_bfloat162 lp2 = __float22bfloat162_rn(make_float2(l4, l5));
                __nv_bfloat162 lp3 = __float22bfloat162_rn(make_float2(l6, l7f));
                uint4 hv; hv.x = hp0; hv.y = hp1; hv.z = hp2; hv.w = hp3;
                *(uint4*)(abuf_hi_dst + g * 16) = hv;
                uint4 lv;
                lv.x = *(uint32_t*)&lp0; lv.y = *(uint32_t*)&lp1;
                lv.z = *(uint32_t*)&lp2; lv.w = *(uint32_t*)&lp3;
                *(uint4*)(abuf_lo_dst + g * 16) = lv;
            }
        }
        __syncthreads();

        // mma from ABUF + B stage slot
        {
            uint32_t bbase = sb + B_OFF + slot * B_STAGE;
            #pragma unroll
            for (int s = 0; s < 2; s++) {
                uint32_t k0b = (uint32_t)(s * 32);
                uint32_t ahi[4], alo[4];
                ldsm_x4(ahi, sb + aoff_hi + k0b);
                ldsm_x4(alo, sb + aoff_lo + k0b);
                #pragma unroll
                for (int g = 0; g < 4; g++) {
                    uint32_t bh[4], bl[4];
                    ldsm_x4(bh, bbase + brow_off[g] + k0b);
                    ldsm_x4(bl, bbase + 5120 + brow_off[g] + k0b);
                    mma16816(acc[2 * g],     ahi, bh[0], bh[2]);
                    mma16816(acc[2 * g],     ahi, bl[0], bl[2]);
                    mma16816(acc[2 * g],     alo, bh[0], bh[2]);
                    mma16816(acc[2 * g + 1], ahi, bh[1], bh[3]);
                    mma16816(acc[2 * g + 1], ahi, bl[1], bl[3]);
                    mma16816(acc[2 * g + 1], alo, bh[1], bh[3]);
                }
            }
        }
        __syncthreads();
        if (blk + 3 < NKB2) load_stageF(smb, slot, m0, blk + 3, tid);
        slot = (slot == 2) ? 0 : slot + 1;
    }

    // epilogue: rows m0 + w*16 + lq (+8), cols na*8 + lr*2 (+1)
    int r0 = m0 + w * 16 + lq;
    #pragma unroll
    for (int na = 0; na < 8; na++) {
        int c0 = na * 8 + lr * 2;
        float bx = cbias[l * 64 + c0], by = cbias[l * 64 + c0 + 1];
        if (r0 < N_NODES) {
            g_m[r0 * 64 + c0]     = acc[na][0] + bx;
            g_m[r0 * 64 + c0 + 1] = acc[na][1] + by;
        }
        if (r0 + 8 < N_NODES) {
            g_m[(r0 + 8) * 64 + c0]     = acc[na][2] + bx;
            g_m[(r0 + 8) * 64 + c0 + 1] = acc[na][3] + by;
        }
    }
}

// ---------------- GRU step (2 nodes per iteration) ----------------------------
#define GRU_SMEM ((12288 * 2 + 192 * 2 + 64 * 4 + 192 * 4) * 4)
__global__ void k_gru(const float* __restrict__ Wih, const float* __restrict__ Whh,
                      const float* __restrict__ bih, const float* __restrict__ bhh,
                      float* __restrict__ dout, int last) {
    extern __shared__ float smf[];
    float* WihT = smf;                  // [i*192 + t]
    float* WhhT = smf + 12288;
    float* bihs = smf + 24576;
    float* bhhs = bihs + 192;
    float* ms   = bhhs + 192;           // 2 x 64
    float* hs   = ms + 128;             // 2 x 64
    float* gi   = hs + 128;             // 2 x 192
    float* gh   = gi + 384;             // 2 x 192
    int t = threadIdx.x;                // 192 threads
    for (int idx = t; idx < 192 * 64; idx += 192) {
        int j = idx / 64, i = idx % 64;
        WihT[i * 192 + j] = Wih[idx];
        WhhT[i * 192 + j] = Whh[idx];
    }
    bihs[t] = bih[t]; bhhs[t] = bhh[t];
    __syncthreads();
    for (int pair = blockIdx.x; pair < N_NODES / 2; pair += gridDim.x) {
        int n0 = pair * 2;
        if (t < 64) {
            ms[t]       = g_m[n0 * 64 + t];
            ms[64 + t]  = g_m[(n0 + 1) * 64 + t];
            hs[t]       = g_hidden[n0 * 64 + t];
            hs[64 + t]  = g_hidden[(n0 + 1) * 64 + t];
        }
        __syncthreads();
        float a0 = bihs[t], a1 = bihs[t], b0 = bhhs[t], b1 = bhhs[t];
        #pragma unroll 8
        for (int i = 0; i < 64; i++) {
            float w1 = WihT[i * 192 + t];
            float w2 = WhhT[i * 192 + t];
            a0 += ms[i] * w1;
            a1 += ms[64 + i] * w1;
            b0 += hs[i] * w2;
            b1 += hs[64 + i] * w2;
        }
        gi[t] = a0; gi[192 + t] = a1;
        gh[t] = b0; gh[192 + t] = b1;
        __syncthreads();
        if (t < 128) {
            int ns = t >> 6, tt = t & 63;
            int node = n0 + ns;
            const float* gin = gi + ns * 192;
            const float* ghn = gh + ns * 192;
            float r = 1.f / (1.f + expf(-(gin[tt] + ghn[tt])));
            float z = 1.f / (1.f + expf(-(gin[64 + tt] + ghn[64 + tt])));
            float n = tanhf(gin[128 + tt] + r * ghn[128 + tt]);
            float nh = (1.f - z) * n + z * hs[ns * 64 + tt];
            g_hidden[node * 64 + tt] = nh;
            g_h[node * 64 + tt] = nh;
            if (last) dout[node * 64 + tt] = nh;
        }
        __syncthreads();
    }
}

// ---------------- launcher ----------------------------------------------------
extern "C" void kernel_launch(void* const* d_in, const int* in_sizes, int n_in,
                              void* d_out, int out_size) {
    const float* x     = (const float*)d_in[0];
    const float* ea    = (const float*)d_in[1];
    const float* Wn1   = (const float*)d_in[2];
    const float* bn1   = (const float*)d_in[3];
    const float* Wn2   = (const float*)d_in[4];
    const float* bn2   = (const float*)d_in[5];
    const float* Wn3   = (const float*)d_in[6];
    const float* bn3   = (const float*)d_in[7];
    const float* We1   = (const float*)d_in[8];
    const float* be1   = (const float*)d_in[9];
    const float* We2   = (const float*)d_in[10];
    const float* be2   = (const float*)d_in[11];
    const float* We3   = (const float*)d_in[12];
    const float* be3   = (const float*)d_in[13];
    const float* roots = (const float*)d_in[14];
    const float* cbias = (const float*)d_in[15];
    const float* gWih  = (const float*)d_in[16];
    const float* gWhh  = (const float*)d_in[17];
    const float* gbih  = (const float*)d_in[18];
    const float* gbhh  = (const float*)d_in[19];
    const int*   ei    = (const int*)d_in[20];
    float* dout = (float*)d_out;

    cudaFuncSetAttribute(k_gru, cudaFuncAttributeMaxDynamicSharedMemorySize, GRU_SMEM);
    cudaFuncSetAttribute(k_gemm_mma, cudaFuncAttributeMaxDynamicSharedMemorySize, GEMM_SMEM);

    k_zero_misc<<<400, 256>>>();
    k_node_mlp<<<296, 256>>>(x, Wn1, bn1, Wn2, bn2, Wn3, bn3);
    k_edge_mlp<<<296, 256>>>(ea, We1, be1, We2, be2);
    k_hist<<<200, 256>>>(ei);
    k_scan<<<1, 1024>>>();
    k_fill<<<200, 256>>>(ei);
    k_sort<<<(N_NODES + 255) / 256, 256>>>();

    for (int l = 0; l < N_LAYERS; l++) {
        k_buildB<<<264, 256>>>(We3, be3, roots, l);
        k_buildP<<<N_NODES / 2, 128>>>(ei);
        k_gemm_mma<<<M_PAD / 128, 256, GEMM_SMEM>>>(cbias, l);
        k_gru<<<296, 192, GRU_SMEM>>>(gWih, gWhh, gbih, gbhh, dout, l == N_LAYERS - 1);
    }
}

// round 11
// speedup vs baseline: 1.8611x; 1.0795x over previous
#include <cuda_runtime.h>
#include <cuda_bf16.h>
#include <cstdint>
#include <math.h>

#define N_NODES 25000
#define M_PAD   25088            // 196 * 128
#define N_EDGES 100000
#define H 64
#define K2 4224                  // 4096 (P edge part) + 64 (h for roots) + 64 (Q for be3)
#define N_LAYERS 3

// ---------------- scratch (static device globals) ---------------------------
__device__ float g_h[N_NODES * H];
__device__ float g_hidden[N_NODES * H];
__device__ float g_ew2[N_EDGES * H];
__device__ __align__(128) float g_P[(size_t)M_PAD * K2];             // ~424 MB fp32
__device__ __align__(128) __nv_bfloat16 g_Bhi[H * K2];               // Bt[n][k]
__device__ __align__(128) __nv_bfloat16 g_Blo[H * K2];
__device__ float g_m[N_NODES * H];
__device__ int   g_deg[N_NODES];
__device__ int   g_off[N_NODES + 1];
__device__ int   g_cur[N_NODES];
__device__ int   g_csr[N_EDGES];

// ---------------- helpers ------------------------------------------------
__device__ __forceinline__ uint32_t smem_u32(const void* p) {
    uint32_t a;
    asm("{ .reg .u64 t; cvta.to.shared.u64 t, %1; cvt.u32.u64 %0, t; }" : "=r"(a) : "l"(p));
    return a;
}

__device__ __forceinline__ void mma16816(float* c, const uint32_t* a, uint32_t b0, uint32_t b1) {
    asm volatile("mma.sync.aligned.m16n8k16.row.col.f32.bf16.bf16.f32 "
        "{%0,%1,%2,%3}, {%4,%5,%6,%7}, {%8,%9}, {%0,%1,%2,%3};"
        : "+f"(c[0]), "+f"(c[1]), "+f"(c[2]), "+f"(c[3])
        : "r"(a[0]), "r"(a[1]), "r"(a[2]), "r"(a[3]), "r"(b0), "r"(b1));
}

__device__ __forceinline__ void ldsm_x4(uint32_t* r, uint32_t addr) {
    asm volatile("ldmatrix.sync.aligned.m8n8.x4.shared.b16 {%0,%1,%2,%3}, [%4];"
        : "=r"(r[0]), "=r"(r[1]), "=r"(r[2]), "=r"(r[3]) : "r"(addr));
}

__device__ __forceinline__ void split_bf(float v, __nv_bfloat16& hi, __nv_bfloat16& lo) {
    hi = __float2bfloat16(v);
    lo = __float2bfloat16(v - __bfloat162float(hi));
}

// ---------------- zero init --------------------------------------------------
__global__ void k_zero_misc() {
    int i = blockIdx.x * blockDim.x + threadIdx.x;
    int st = gridDim.x * blockDim.x;
    for (int idx = i; idx < N_NODES; idx += st) g_deg[idx] = 0;
    for (int idx = i; idx < N_NODES * H; idx += st) g_hidden[idx] = 0.f;
    const size_t padN = (size_t)(M_PAD - N_NODES) * K2;
    for (size_t idx = i; idx < padN; idx += st)
        g_P[(size_t)N_NODES * K2 + idx] = 0.f;
}

// ---------------- node MLP ---------------------------------------------------
__global__ void k_node_mlp(const float* __restrict__ x,
                           const float* __restrict__ W1, const float* __restrict__ b1,
                           const float* __restrict__ W2, const float* __restrict__ b2,
                           const float* __restrict__ W3, const float* __restrict__ b3) {
    __shared__ float W1T[32 * 64], W2T[64 * 64], W3T[64 * 64];
    __shared__ float b1s[64], b2s[64], b3s[64];
    __shared__ float xs[4][32], h1[4][64], h2[4][64];
    int tid = threadIdx.x;
    for (int idx = tid; idx < 32 * 64; idx += 256) { int o = idx / 32, j = idx % 32; W1T[j * 64 + o] = W1[idx]; }
    for (int idx = tid; idx < 64 * 64; idx += 256) { int o = idx / 64, j = idx % 64; W2T[j * 64 + o] = W2[idx]; W3T[j * 64 + o] = W3[idx]; }
    if (tid < 64) { b1s[tid] = b1[tid]; b2s[tid] = b2[tid]; b3s[tid] = b3[tid]; }
    __syncthreads();
    int nl = tid >> 6, o = tid & 63;
    for (int base = blockIdx.x * 4; base < N_NODES; base += gridDim.x * 4) {
        int node = base + nl;
        if (o < 32 && node < N_NODES) xs[nl][o] = x[node * 32 + o];
        __syncthreads();
        if (node < N_NODES) {
            float a = b1s[o];
            #pragma unroll
            for (int j = 0; j < 32; j++) a += xs[nl][j] * W1T[j * 64 + o];
            h1[nl][o] = fmaxf(a, 0.f);
        }
        __syncthreads();
        if (node < N_NODES) {
            float a = b2s[o];
            #pragma unroll
            for (int j = 0; j < 64; j++) a += h1[nl][j] * W2T[j * 64 + o];
            h2[nl][o] = fmaxf(a, 0.f);
        }
        __syncthreads();
        if (node < N_NODES) {
            float a = b3s[o];
            #pragma unroll
            for (int j = 0; j < 64; j++) a += h2[nl][j] * W3T[j * 64 + o];
            g_h[node * 64 + o] = a;
        }
        __syncthreads();
    }
}

// ---------------- edge MLP (layers 1,2) --------------------------------------
__global__ void k_edge_mlp(const float* __restrict__ ea,
                           const float* __restrict__ W1, const float* __restrict__ b1,
                           const float* __restrict__ W2, const float* __restrict__ b2) {
    __shared__ float W1T[16 * 64], W2T[64 * 64];
    __shared__ float b1s[64], b2s[64];
    __shared__ float es[4][16], h1[4][64];
    int tid = threadIdx.x;
    for (int idx = tid; idx < 16 * 64; idx += 256) { int o = idx >> 4, j = idx & 15; W1T[j * 64 + o] = W1[idx]; }
    for (int idx = tid; idx < 64 * 64; idx += 256) { int o = idx >> 6, j = idx & 63; W2T[j * 64 + o] = W2[idx]; }
    if (tid < 64) { b1s[tid] = b1[tid]; b2s[tid] = b2[tid]; }
    __syncthreads();
    int nl = tid >> 6, o = tid & 63;
    for (int base = blockIdx.x * 4; base < N_EDGES; base += gridDim.x * 4) {
        int e = base + nl;
        if (o < 16 && e < N_EDGES) es[nl][o] = ea[e * 16 + o];
        __syncthreads();
        if (e < N_EDGES) {
            float a = b1s[o];
            #pragma unroll
            for (int j = 0; j < 16; j++) a += es[nl][j] * W1T[j * 64 + o];
            h1[nl][o] = fmaxf(a, 0.f);
        }
        __syncthreads();
        if (e < N_EDGES) {
            float a = b2s[o];
            #pragma unroll
            for (int j = 0; j < 64; j++) a += h1[nl][j] * W2T[j * 64 + o];
            g_ew2[e * 64 + o] = fmaxf(a, 0.f);
        }
        __syncthreads();
    }
}

// ---------------- CSR build --------------------------------------------------
__global__ void k_hist(const int* __restrict__ ei) {
    int i = blockIdx.x * blockDim.x + threadIdx.x, st = gridDim.x * blockDim.x;
    for (int e = i; e < N_EDGES; e += st) atomicAdd(&g_deg[ei[N_EDGES + e]], 1);
}

__global__ void k_scan() {
    __shared__ int part[1024];
    int t = threadIdx.x;
    const int CH = (N_NODES + 1023) / 1024;
    int b0 = t * CH, b1 = min(b0 + CH, N_NODES);
    int s = 0;
    for (int i = b0; i < b1; i++) s += g_deg[i];
    part[t] = s;
    __syncthreads();
    for (int d = 1; d < 1024; d <<= 1) {
        int v = (t >= d) ? part[t - d] : 0;
        __syncthreads();
        part[t] += v;
        __syncthreads();
    }
    int run = (t == 0) ? 0 : part[t - 1];
    for (int i = b0; i < b1; i++) { g_off[i] = run; g_cur[i] = run; run += g_deg[i]; }
    if (t == 1023) g_off[N_NODES] = part[1023];
}

__global__ void k_fill(const int* __restrict__ ei) {
    int i = blockIdx.x * blockDim.x + threadIdx.x, st = gridDim.x * blockDim.x;
    for (int e = i; e < N_EDGES; e += st) {
        int d = ei[N_EDGES + e];
        int p = atomicAdd(&g_cur[d], 1);
        g_csr[p] = e;
    }
}

__global__ void k_sort() {
    int d = blockIdx.x * blockDim.x + threadIdx.x;
    if (d >= N_NODES) return;
    int a = g_off[d], b = g_off[d + 1];
    for (int i = a + 1; i < b; i++) {
        int v = g_csr[i];
        int j = i - 1;
        while (j >= a && g_csr[j] > v) { g_csr[j + 1] = g_csr[j]; j--; }
        g_csr[j + 1] = v;
    }
}

// ---------------- build Bt[n][k]: layer-invariant part (once) -----------------
__global__ void k_buildB_static(const float* __restrict__ We3, const float* __restrict__ be3) {
    int i0 = blockIdx.x * blockDim.x + threadIdx.x, st = gridDim.x * blockDim.x;
    for (int idx = i0; idx < H * K2; idx += st) {
        int n = idx / K2, kg = idx % K2;
        if (kg >= 4096 && kg < 4160) continue;         // roots rows: per layer
        float v;
        if (kg < 4096) { int i = kg >> 6, k = kg & 63; v = We3[((i << 6) + n) * 64 + k]; }
        else           { v = be3[((kg - 4160) << 6) + n]; }
        __nv_bfloat16 hi, lo;
        split_bf(v, hi, lo);
        g_Bhi[idx] = hi;
        g_Blo[idx] = lo;
    }
}

// per-layer: only the 64 roots rows (kg in [4096,4160))
__global__ void k_buildB_roots(const float* __restrict__ roots, int l) {
    int idx = blockIdx.x * blockDim.x + threadIdx.x;     // 64*64
    if (idx >= 64 * 64) return;
    int n = idx >> 6, r = idx & 63;
    float v = roots[(l * 64 + r) * 64 + n];
    __nv_bfloat16 hi, lo;
    split_bf(v, hi, lo);
    g_Bhi[n * K2 + 4096 + r] = hi;
    g_Blo[n * K2 + 4096 + r] = lo;
}

// ---------------- build P rows (fp32, register accumulation, direct stores) ---
__global__ void __launch_bounds__(128) k_buildP(const int* __restrict__ ei) {
    int tid = threadIdx.x, warp = tid >> 5, lane = tid & 31;
    int ns_w = warp >> 1, kh = warp & 1;
    int d = blockIdx.x * 2 + ns_w;
    int kcol = kh * 32 + lane;

    float acc[64];
    #pragma unroll
    for (int i = 0; i < 64; i++) acc[i] = 0.f;

    int off0 = g_off[d];
    int deg = g_off[d + 1] - off0;
    for (int j = 0; j < deg; j++) {
        int e = g_csr[off0 + j];               // sorted -> deterministic order
        int s = ei[e];
        float ew = g_ew2[e * 64 + kcol];
        const float4* hr = (const float4*)(g_h + s * 64);
        #pragma unroll
        for (int i4 = 0; i4 < 16; i4++) {
            float4 hv = hr[i4];
            acc[i4 * 4 + 0] += hv.x * ew;
            acc[i4 * 4 + 1] += hv.y * ew;
            acc[i4 * 4 + 2] += hv.z * ew;
            acc[i4 * 4 + 3] += hv.w * ew;
        }
    }
    size_t rb = (size_t)d * K2;
    #pragma unroll
    for (int i = 0; i < 64; i++)
        g_P[rb + i * 64 + kcol] = acc[i];

    {
        int ns = tid >> 6, i = tid & 63;
        int dn = blockIdx.x * 2 + ns;
        size_t rb2 = (size_t)dn * K2;
        g_P[rb2 + 4096 + i] = g_h[dn * 64 + i];
        int o0 = g_off[dn], dg = g_off[dn + 1] - o0;
        float q = 0.f;
        for (int j = 0; j < dg; j++) q += g_h[ei[g_csr[o0 + j]] * 64 + i];
        g_P[rb2 + 4160 + i] = q;
    }
}

// ---------------- GEMM: direct-LDG A, pipelined convert<->mma, ldmatrix -------
// smem: ABUF x2 (hi 128x40x2B=10240 + lo 10240 each) at 0 / 20480;
//       B stages x4 (hi 5120 + lo 5120) at 40960 + s*10240.
// 4 B slots: refill targets (blk+3)%4 whose last reader was iteration blk-1
// (completed before this iteration's barrier) -> no race with one sync/iter.
#define NKB2 132                 // K2 / 32
#define ABUF_SZ  20480
#define B_OFF    40960
#define B_STAGE  10240
#define GEMM_SMEM 81920

__device__ __forceinline__ void copyB_stage(char* smb, int slot, int kb, int tid) {
    char* bst = smb + B_OFF + slot * B_STAGE;
    #pragma unroll
    for (int q = 0; q < 2; q++) {
        int c = q * 256 + tid;                  // 512 chunks of 16B
        int half = c >> 8, cc = c & 255;
        int row = cc >> 2, c4 = cc & 3;
        const __nv_bfloat16* src = (half ? g_Blo : g_Bhi) + (size_t)row * K2 + kb * 32 + c4 * 8;
        uint32_t dst = smem_u32(bst + half * 5120 + row * 80 + c4 * 16);
        asm volatile("cp.async.cg.shared.global [%0], [%1], 16;" :: "r"(dst), "l"(src));
    }
    asm volatile("cp.async.commit_group;" ::: "memory");
}

__global__ void __launch_bounds__(256, 2) k_gemm_mma(const float* __restrict__ cbias, int l) {
    extern __shared__ __align__(16) char smb[];
    const int tid = threadIdx.x, w = tid >> 5, lane = tid & 31;
    const int m0 = blockIdx.x * 128;
    const int lq = lane >> 2;          // 0..7
    const int lr = lane & 3;           // 0..3

    // ldmatrix lane-address components (rows of 40 bf16 = 80B)
    const int l7 = lane & 7;
    const int lbit = (lane >> 3) & 1;
    const int csel = (lane >> 4) ? 16 : 0;
    const uint32_t aoff = (uint32_t)((w * 16 + l7 + lbit * 8) * 80 + csel);
    uint32_t brow_off[4];
    #pragma unroll
    for (int g = 0; g < 4; g++)
        brow_off[g] = (uint32_t)((g * 16 + l7 + lbit * 8) * 80 + csel);

    // convert mapping: thread -> row cr, 16 cols starting cc0
    const int cr = tid >> 1;
    const int cc0 = (tid & 1) * 16;
    const float* asrc = g_P + (size_t)(m0 + cr) * K2 + cc0;   // + kb*32 per block
    char* ah_base = smb + cr * 80 + cc0 * 2;                  // + (b)*ABUF_SZ
    char* al_base = ah_base + 10240;

    float4 pf[4];

    auto cvt_store = [&](int b) {
        char* hd = ah_base + b * ABUF_SZ;
        char* ld = al_base + b * ABUF_SZ;
        #pragma unroll
        for (int g = 0; g < 2; g++) {
            float4 a = pf[g * 2];
            float4 bb = pf[g * 2 + 1];
            uint32_t hp0 = __byte_perm(__float_as_uint(a.x), __float_as_uint(a.y), 0x7632);
            uint32_t hp1 = __byte_perm(__float_as_uint(a.z), __float_as_uint(a.w), 0x7632);
            uint32_t hp2 = __byte_perm(__float_as_uint(bb.x), __float_as_uint(bb.y), 0x7632);
            uint32_t hp3 = __byte_perm(__float_as_uint(bb.z), __float_as_uint(bb.w), 0x7632);
            float l0 = a.x - __uint_as_float(__float_as_uint(a.x) & 0xffff0000u);
            float l1 = a.y - __uint_as_float(__float_as_uint(a.y) & 0xffff0000u);
            float l2 = a.z - __uint_as_float(__float_as_uint(a.z) & 0xffff0000u);
            float l3 = a.w - __uint_as_float(__float_as_uint(a.w) & 0xffff0000u);
            float l4 = bb.x - __uint_as_float(__float_as_uint(bb.x) & 0xffff0000u);
            float l5 = bb.y - __uint_as_float(__float_as_uint(bb.y) & 0xffff0000u);
            float l6 = bb.z - __uint_as_float(__float_as_uint(bb.z) & 0xffff0000u);
            float l7f = bb.w - __uint_as_float(__float_as_uint(bb.w) & 0xffff0000u);
            __nv_bfloat162 lp0 = __float22bfloat162_rn(make_float2(l0, l1));
            __nv_bfloat162 lp1 = __float22bfloat162_rn(make_float2(l2, l3));
            __nv_bfloat162 lp2 = __float22bfloat162_rn(make_float2(l4, l5));
            __nv_bfloat162 lp3 = __float22bfloat162_rn(make_float2(l6, l7f));
            uint4 hv; hv.x = hp0; hv.y = hp1; hv.z = hp2; hv.w = hp3;
            *(uint4*)(hd + g * 16) = hv;
            uint4 lv;
            lv.x = *(uint32_t*)&lp0; lv.y = *(uint32_t*)&lp1;
            lv.z = *(uint32_t*)&lp2; lv.w = *(uint32_t*)&lp3;
            *(uint4*)(ld + g * 16) = lv;
        }
    };
    auto lda = [&](int kb) {
        const float4* s4 = (const float4*)(asrc + kb * 32);
        pf[0] = s4[0]; pf[1] = s4[1]; pf[2] = s4[2]; pf[3] = s4[3];
    };

    float acc[8][4];
    #pragma unroll
    for (int na = 0; na < 8; na++)
        #pragma unroll
        for (int v = 0; v < 4; v++) acc[na][v] = 0.f;

    // prologue
    copyB_stage(smb, 0, 0, tid);
    copyB_stage(smb, 1, 1, tid);
    copyB_stage(smb, 2, 2, tid);
    lda(0);
    cvt_store(0);
    lda(1);

    uint32_t sb = smem_u32(smb);
    for (int blk = 0; blk < NKB2; blk++) {
        int rem = NKB2 - 1 - blk;
        if (rem >= 2)      asm volatile("cp.async.wait_group 2;" ::: "memory");
        else if (rem == 1) asm volatile("cp.async.wait_group 1;" ::: "memory");
        else               asm volatile("cp.async.wait_group 0;" ::: "memory");
        __syncthreads();

        // mma on ABUF[blk&1] + B slot blk%4; convert pf(blk+1) overlapped
        uint32_t ab = sb + (blk & 1) * ABUF_SZ;
        uint32_t bbase = sb + B_OFF + (blk & 3) * B_STAGE;
        #pragma unroll
        for (int s = 0; s < 2; s++) {
            uint32_t k0b = (uint32_t)(s * 32);
            uint32_t ahi[4], alo[4];
            ldsm_x4(ahi, ab + aoff + k0b);
            ldsm_x4(alo, ab + 10240 + aoff + k0b);
            #pragma unroll
            for (int g = 0; g < 4; g++) {
                uint32_t bh[4], bl[4];
                ldsm_x4(bh, bbase + brow_off[g] + k0b);
                ldsm_x4(bl, bbase + 5120 + brow_off[g] + k0b);
                mma16816(acc[2 * g],     ahi, bh[0], bh[2]);
                mma16816(acc[2 * g],     ahi, bl[0], bl[2]);
                mma16816(acc[2 * g],     alo, bh[0], bh[2]);
                mma16816(acc[2 * g + 1], ahi, bh[1], bh[3]);
                mma16816(acc[2 * g + 1], ahi, bl[1], bl[3]);
                mma16816(acc[2 * g + 1], alo, bh[1], bh[3]);
            }
        }
        if (blk + 1 < NKB2) cvt_store((blk + 1) & 1);
        if (blk + 2 < NKB2) lda(blk + 2);
        if (blk + 3 < NKB2) copyB_stage(smb, (blk + 3) & 3, blk + 3, tid);
    }

    // epilogue: rows m0 + w*16 + lq (+8), cols na*8 + lr*2 (+1)
    int r0 = m0 + w * 16 + lq;
    #pragma unroll
    for (int na = 0; na < 8; na++) {
        int c0 = na * 8 + lr * 2;
        float bx = cbias[l * 64 + c0], by = cbias[l * 64 + c0 + 1];
        if (r0 < N_NODES) {
            g_m[r0 * 64 + c0]     = acc[na][0] + bx;
            g_m[r0 * 64 + c0 + 1] = acc[na][1] + by;
        }
        if (r0 + 8 < N_NODES) {
            g_m[(r0 + 8) * 64 + c0]     = acc[na][2] + bx;
            g_m[(r0 + 8) * 64 + c0 + 1] = acc[na][3] + by;
        }
    }
}

// ---------------- GRU step (2 nodes per iteration) ----------------------------
#define GRU_SMEM ((12288 * 2 + 192 * 2 + 64 * 4 + 192 * 4) * 4)
__global__ void k_gru(const float* __restrict__ Wih, const float* __restrict__ Whh,
                      const float* __restrict__ bih, const float* __restrict__ bhh,
                      float* __restrict__ dout, int last) {
    extern __shared__ float smf[];
    float* WihT = smf;                  // [i*192 + t]
    float* WhhT = smf + 12288;
    float* bihs = smf + 24576;
    float* bhhs = bihs + 192;
    float* ms   = bhhs + 192;           // 2 x 64
    float* hs   = ms + 128;             // 2 x 64
    float* gi   = hs + 128;             // 2 x 192
    float* gh   = gi + 384;             // 2 x 192
    int t = threadIdx.x;                // 192 threads
    for (int idx = t; idx < 192 * 64; idx += 192) {
        int j = idx / 64, i = idx % 64;
        WihT[i * 192 + j] = Wih[idx];
        WhhT[i * 192 + j] = Whh[idx];
    }
    bihs[t] = bih[t]; bhhs[t] = bhh[t];
    __syncthreads();
    for (int pair = blockIdx.x; pair < N_NODES / 2; pair += gridDim.x) {
        int n0 = pair * 2;
        if (t < 64) {
            ms[t]       = g_m[n0 * 64 + t];
            ms[64 + t]  = g_m[(n0 + 1) * 64 + t];
            hs[t]       = g_hidden[n0 * 64 + t];
            hs[64 + t]  = g_hidden[(n0 + 1) * 64 + t];
        }
        __syncthreads();
        float a0 = bihs[t], a1 = bihs[t], b0 = bhhs[t], b1 = bhhs[t];
        #pragma unroll 8
        for (int i = 0; i < 64; i++) {
            float w1 = WihT[i * 192 + t];
            float w2 = WhhT[i * 192 + t];
            a0 += ms[i] * w1;
            a1 += ms[64 + i] * w1;
            b0 += hs[i] * w2;
            b1 += hs[64 + i] * w2;
        }
        gi[t] = a0; gi[192 + t] = a1;
        gh[t] = b0; gh[192 + t] = b1;
        __syncthreads();
        if (t < 128) {
            int ns = t >> 6, tt = t & 63;
            int node = n0 + ns;
            const float* gin = gi + ns * 192;
            const float* ghn = gh + ns * 192;
            float r = 1.f / (1.f + expf(-(gin[tt] + ghn[tt])));
            float z = 1.f / (1.f + expf(-(gin[64 + tt] + ghn[64 + tt])));
            float n = tanhf(gin[128 + tt] + r * ghn[128 + tt]);
            float nh = (1.f - z) * n + z * hs[ns * 64 + tt];
            g_hidden[node * 64 + tt] = nh;
            g_h[node * 64 + tt] = nh;
            if (last) dout[node * 64 + tt] = nh;
        }
        __syncthreads();
    }
}

// ---------------- launcher ----------------------------------------------------
extern "C" void kernel_launch(void* const* d_in, const int* in_sizes, int n_in,
                              void* d_out, int out_size) {
    const float* x     = (const float*)d_in[0];
    const float* ea    = (const float*)d_in[1];
    const float* Wn1   = (const float*)d_in[2];
    const float* bn1   = (const float*)d_in[3];
    const float* Wn2   = (const float*)d_in[4];
    const float* bn2   = (const float*)d_in[5];
    const float* Wn3   = (const float*)d_in[6];
    const float* bn3   = (const float*)d_in[7];
    const float* We1   = (const float*)d_in[8];
    const float* be1   = (const float*)d_in[9];
    const float* We2   = (const float*)d_in[10];
    const float* be2   = (const float*)d_in[11];
    const float* We3   = (const float*)d_in[12];
    const float* be3   = (const float*)d_in[13];
    const float* roots = (const float*)d_in[14];
    const float* cbias = (const float*)d_in[15];
    const float* gWih  = (const float*)d_in[16];
    const float* gWhh  = (const float*)d_in[17];
    const float* gbih  = (const float*)d_in[18];
    const float* gbhh  = (const float*)d_in[19];
    const int*   ei    = (const int*)d_in[20];
    float* dout = (float*)d_out;

    cudaFuncSetAttribute(k_gru, cudaFuncAttributeMaxDynamicSharedMemorySize, GRU_SMEM);
    cudaFuncSetAttribute(k_gemm_mma, cudaFuncAttributeMaxDynamicSharedMemorySize, GEMM_SMEM);

    k_zero_misc<<<400, 256>>>();
    k_node_mlp<<<296, 256>>>(x, Wn1, bn1, Wn2, bn2, Wn3, bn3);
    k_edge_mlp<<<296, 256>>>(ea, We1, be1, We2, be2);
    k_hist<<<200, 256>>>(ei);
    k_scan<<<1, 1024>>>();
    k_fill<<<200, 256>>>(ei);
    k_sort<<<(N_NODES + 255) / 256, 256>>>();
    k_buildB_static<<<264, 256>>>(We3, be3);

    for (int l = 0; l < N_LAYERS; l++) {
        k_buildB_roots<<<16, 256>>>(roots, l);
        k_buildP<<<N_NODES / 2, 128>>>(ei);
        k_gemm_mma<<<M_PAD / 128, 256, GEMM_SMEM>>>(cbias, l);
        k_gru<<<296, 192, GRU_SMEM>>>(gWih, gWhh, gbih, gbhh, dout, l == N_LAYERS - 1);
    }
}

// round 12
// speedup vs baseline: 2.0195x; 1.0851x over previous
#include <cuda_runtime.h>
#include <cuda_bf16.h>
#include <cstdint>
#include <math.h>

#define N_NODES 25000
#define M_PAD   25088            // 392 * 64
#define N_EDGES 100000
#define H 64
#define K2 4224                  // 4096 (P edge part) + 64 (h for roots) + 64 (Q for be3)
#define N_LAYERS 3

// ---------------- scratch (static device globals) ---------------------------
__device__ float g_h[N_NODES * H];
__device__ float g_hidden[N_NODES * H];
__device__ float g_ew2[N_EDGES * H];
__device__ __align__(128) float g_P[(size_t)M_PAD * K2];             // ~424 MB fp32
__device__ __align__(128) __nv_bfloat16 g_Bhi[H * K2];               // Bt[n][k]
__device__ __align__(128) __nv_bfloat16 g_Blo[H * K2];
__device__ float g_m[N_NODES * H];
__device__ int   g_deg[N_NODES];
__device__ int   g_off[N_NODES + 1];
__device__ int   g_cur[N_NODES];
__device__ int   g_csr[N_EDGES];

// ---------------- helpers ------------------------------------------------
__device__ __forceinline__ uint32_t smem_u32(const void* p) {
    uint32_t a;
    asm("{ .reg .u64 t; cvta.to.shared.u64 t, %1; cvt.u32.u64 %0, t; }" : "=r"(a) : "l"(p));
    return a;
}

__device__ __forceinline__ void mma16816(float* c, const uint32_t* a, uint32_t b0, uint32_t b1) {
    asm volatile("mma.sync.aligned.m16n8k16.row.col.f32.bf16.bf16.f32 "
        "{%0,%1,%2,%3}, {%4,%5,%6,%7}, {%8,%9}, {%0,%1,%2,%3};"
        : "+f"(c[0]), "+f"(c[1]), "+f"(c[2]), "+f"(c[3])
        : "r"(a[0]), "r"(a[1]), "r"(a[2]), "r"(a[3]), "r"(b0), "r"(b1));
}

__device__ __forceinline__ void ldsm_x4(uint32_t* r, uint32_t addr) {
    asm volatile("ldmatrix.sync.aligned.m8n8.x4.shared.b16 {%0,%1,%2,%3}, [%4];"
        : "=r"(r[0]), "=r"(r[1]), "=r"(r[2]), "=r"(r[3]) : "r"(addr));
}

__device__ __forceinline__ void split_bf(float v, __nv_bfloat16& hi, __nv_bfloat16& lo) {
    hi = __float2bfloat16(v);
    lo = __float2bfloat16(v - __bfloat162float(hi));
}

// ---------------- zero init --------------------------------------------------
__global__ void k_zero_misc() {
    int i = blockIdx.x * blockDim.x + threadIdx.x;
    int st = gridDim.x * blockDim.x;
    for (int idx = i; idx < N_NODES; idx += st) g_deg[idx] = 0;
    for (int idx = i; idx < N_NODES * H; idx += st) g_hidden[idx] = 0.f;
    const size_t padN = (size_t)(M_PAD - N_NODES) * K2;
    for (size_t idx = i; idx < padN; idx += st)
        g_P[(size_t)N_NODES * K2 + idx] = 0.f;
}

// ---------------- node MLP ---------------------------------------------------
__global__ void k_node_mlp(const float* __restrict__ x,
                           const float* __restrict__ W1, const float* __restrict__ b1,
                           const float* __restrict__ W2, const float* __restrict__ b2,
                           const float* __restrict__ W3, const float* __restrict__ b3) {
    __shared__ float W1T[32 * 64], W2T[64 * 64], W3T[64 * 64];
    __shared__ float b1s[64], b2s[64], b3s[64];
    __shared__ float xs[4][32], h1[4][64], h2[4][64];
    int tid = threadIdx.x;
    for (int idx = tid; idx < 32 * 64; idx += 256) { int o = idx / 32, j = idx % 32; W1T[j * 64 + o] = W1[idx]; }
    for (int idx = tid; idx < 64 * 64; idx += 256) { int o = idx / 64, j = idx % 64; W2T[j * 64 + o] = W2[idx]; W3T[j * 64 + o] = W3[idx]; }
    if (tid < 64) { b1s[tid] = b1[tid]; b2s[tid] = b2[tid]; b3s[tid] = b3[tid]; }
    __syncthreads();
    int nl = tid >> 6, o = tid & 63;
    for (int base = blockIdx.x * 4; base < N_NODES; base += gridDim.x * 4) {
        int node = base + nl;
        if (o < 32 && node < N_NODES) xs[nl][o] = x[node * 32 + o];
        __syncthreads();
        if (node < N_NODES) {
            float a = b1s[o];
            #pragma unroll
            for (int j = 0; j < 32; j++) a += xs[nl][j] * W1T[j * 64 + o];
            h1[nl][o] = fmaxf(a, 0.f);
        }
        __syncthreads();
        if (node < N_NODES) {
            float a = b2s[o];
            #pragma unroll
            for (int j = 0; j < 64; j++) a += h1[nl][j] * W2T[j * 64 + o];
            h2[nl][o] = fmaxf(a, 0.f);
        }
        __syncthreads();
        if (node < N_NODES) {
            float a = b3s[o];
            #pragma unroll
            for (int j = 0; j < 64; j++) a += h2[nl][j] * W3T[j * 64 + o];
            g_h[node * 64 + o] = a;
        }
        __syncthreads();
    }
}

// ---------------- edge MLP (layers 1,2) --------------------------------------
__global__ void k_edge_mlp(const float* __restrict__ ea,
                           const float* __restrict__ W1, const float* __restrict__ b1,
                           const float* __restrict__ W2, const float* __restrict__ b2) {
    __shared__ float W1T[16 * 64], W2T[64 * 64];
    __shared__ float b1s[64], b2s[64];
    __shared__ float es[4][16], h1[4][64];
    int tid = threadIdx.x;
    for (int idx = tid; idx < 16 * 64; idx += 256) { int o = idx >> 4, j = idx & 15; W1T[j * 64 + o] = W1[idx]; }
    for (int idx = tid; idx < 64 * 64; idx += 256) { int o = idx >> 6, j = idx & 63; W2T[j * 64 + o] = W2[idx]; }
    if (tid < 64) { b1s[tid] = b1[tid]; b2s[tid] = b2[tid]; }
    __syncthreads();
    int nl = tid >> 6, o = tid & 63;
    for (int base = blockIdx.x * 4; base < N_EDGES; base += gridDim.x * 4) {
        int e = base + nl;
        if (o < 16 && e < N_EDGES) es[nl][o] = ea[e * 16 + o];
        __syncthreads();
        if (e < N_EDGES) {
            float a = b1s[o];
            #pragma unroll
            for (int j = 0; j < 16; j++) a += es[nl][j] * W1T[j * 64 + o];
            h1[nl][o] = fmaxf(a, 0.f);
        }
        __syncthreads();
        if (e < N_EDGES) {
            float a = b2s[o];
            #pragma unroll
            for (int j = 0; j < 64; j++) a += h1[nl][j] * W2T[j * 64 + o];
            g_ew2[e * 64 + o] = fmaxf(a, 0.f);
        }
        __syncthreads();
    }
}

// ---------------- CSR build --------------------------------------------------
__global__ void k_hist(const int* __restrict__ ei) {
    int i = blockIdx.x * blockDim.x + threadIdx.x, st = gridDim.x * blockDim.x;
    for (int e = i; e < N_EDGES; e += st) atomicAdd(&g_deg[ei[N_EDGES + e]], 1);
}

__global__ void k_scan() {
    __shared__ int part[1024];
    int t = threadIdx.x;
    const int CH = (N_NODES + 1023) / 1024;
    int b0 = t * CH, b1 = min(b0 + CH, N_NODES);
    int s = 0;
    for (int i = b0; i < b1; i++) s += g_deg[i];
    part[t] = s;
    __syncthreads();
    for (int d = 1; d < 1024; d <<= 1) {
        int v = (t >= d) ? part[t - d] : 0;
        __syncthreads();
        part[t] += v;
        __syncthreads();
    }
    int run = (t == 0) ? 0 : part[t - 1];
    for (int i = b0; i < b1; i++) { g_off[i] = run; g_cur[i] = run; run += g_deg[i]; }
    if (t == 1023) g_off[N_NODES] = part[1023];
}

__global__ void k_fill(const int* __restrict__ ei) {
    int i = blockIdx.x * blockDim.x + threadIdx.x, st = gridDim.x * blockDim.x;
    for (int e = i; e < N_EDGES; e += st) {
        int d = ei[N_EDGES + e];
        int p = atomicAdd(&g_cur[d], 1);
        g_csr[p] = e;
    }
}

__global__ void k_sort() {
    int d = blockIdx.x * blockDim.x + threadIdx.x;
    if (d >= N_NODES) return;
    int a = g_off[d], b = g_off[d + 1];
    for (int i = a + 1; i < b; i++) {
        int v = g_csr[i];
        int j = i - 1;
        while (j >= a && g_csr[j] > v) { g_csr[j + 1] = g_csr[j]; j--; }
        g_csr[j + 1] = v;
    }
}

// ---------------- build Bt[n][k]: layer-invariant part (once) -----------------
__global__ void k_buildB_static(const float* __restrict__ We3, const float* __restrict__ be3) {
    int i0 = blockIdx.x * blockDim.x + threadIdx.x, st = gridDim.x * blockDim.x;
    for (int idx = i0; idx < H * K2; idx += st) {
        int n = idx / K2, kg = idx % K2;
        if (kg >= 4096 && kg < 4160) continue;         // roots rows: per layer
        float v;
        if (kg < 4096) { int i = kg >> 6, k = kg & 63; v = We3[((i << 6) + n) * 64 + k]; }
        else           { v = be3[((kg - 4160) << 6) + n]; }
        __nv_bfloat16 hi, lo;
        split_bf(v, hi, lo);
        g_Bhi[idx] = hi;
        g_Blo[idx] = lo;
    }
}

// per-layer: only the 64 roots rows (kg in [4096,4160))
__global__ void k_buildB_roots(const float* __restrict__ roots, int l) {
    int idx = blockIdx.x * blockDim.x + threadIdx.x;     // 64*64
    if (idx >= 64 * 64) return;
    int n = idx >> 6, r = idx & 63;
    float v = roots[(l * 64 + r) * 64 + n];
    __nv_bfloat16 hi, lo;
    split_bf(v, hi, lo);
    g_Bhi[n * K2 + 4096 + r] = hi;
    g_Blo[n * K2 + 4096 + r] = lo;
}

// ---------------- build P rows (fp32, register accumulation, direct stores) ---
__global__ void __launch_bounds__(128) k_buildP(const int* __restrict__ ei) {
    int tid = threadIdx.x, warp = tid >> 5, lane = tid & 31;
    int ns_w = warp >> 1, kh = warp & 1;
    int d = blockIdx.x * 2 + ns_w;
    int kcol = kh * 32 + lane;

    float acc[64];
    #pragma unroll
    for (int i = 0; i < 64; i++) acc[i] = 0.f;

    int off0 = g_off[d];
    int deg = g_off[d + 1] - off0;
    for (int j = 0; j < deg; j++) {
        int e = g_csr[off0 + j];               // sorted -> deterministic order
        int s = ei[e];
        float ew = g_ew2[e * 64 + kcol];
        const float4* hr = (const float4*)(g_h + s * 64);
        #pragma unroll
        for (int i4 = 0; i4 < 16; i4++) {
            float4 hv = hr[i4];
            acc[i4 * 4 + 0] += hv.x * ew;
            acc[i4 * 4 + 1] += hv.y * ew;
            acc[i4 * 4 + 2] += hv.z * ew;
            acc[i4 * 4 + 3] += hv.w * ew;
        }
    }
    size_t rb = (size_t)d * K2;
    #pragma unroll
    for (int i = 0; i < 64; i++)
        g_P[rb + i * 64 + kcol] = acc[i];

    {
        int ns = tid >> 6, i = tid & 63;
        int dn = blockIdx.x * 2 + ns;
        size_t rb2 = (size_t)dn * K2;
        g_P[rb2 + 4096 + i] = g_h[dn * 64 + i];
        int o0 = g_off[dn], dg = g_off[dn + 1] - o0;
        float q = 0.f;
        for (int j = 0; j < dg; j++) q += g_h[ei[g_csr[o0 + j]] * 64 + i];
        g_P[rb2 + 4160 + i] = q;
    }
}

// ---------------- GEMM (M-tile 64): direct-LDG A, pipelined convert<->mma -----
// smem: ABUF x2 (hi 64x40x2B=5120 + lo 5120 each) at 0 / 10240;
//       B stages x4 (hi 5120 + lo 5120) at 20480 + s*10240.
// 4 B slots: refill targets (blk+3)%4 whose last reader was iteration blk-1.
#define NKB2 132                 // K2 / 32
#define ABUF_SZ  10240
#define B_OFF    20480
#define B_STAGE  10240
#define GEMM_SMEM 61440

__device__ __forceinline__ void copyB_stage(char* smb, int slot, int kb, int tid) {
    char* bst = smb + B_OFF + slot * B_STAGE;
    #pragma unroll
    for (int q = 0; q < 2; q++) {
        int c = q * 256 + tid;                  // 512 chunks of 16B
        int half = c >> 8, cc = c & 255;
        int row = cc >> 2, c4 = cc & 3;
        const __nv_bfloat16* src = (half ? g_Blo : g_Bhi) + (size_t)row * K2 + kb * 32 + c4 * 8;
        uint32_t dst = smem_u32(bst + half * 5120 + row * 80 + c4 * 16);
        asm volatile("cp.async.cg.shared.global [%0], [%1], 16;" :: "r"(dst), "l"(src));
    }
    asm volatile("cp.async.commit_group;" ::: "memory");
}

__global__ void __launch_bounds__(256, 3) k_gemm_mma(const float* __restrict__ cbias, int l) {
    extern __shared__ __align__(16) char smb[];
    const int tid = threadIdx.x, w = tid >> 5, lane = tid & 31;
    const int m0 = blockIdx.x * 64;
    const int lq = lane >> 2;          // 0..7
    const int lr = lane & 3;           // 0..3
    const int wm = w >> 1;             // 0..3 (m16 group)
    const int wn = w & 1;              // 0..1 (n32 half)

    // ldmatrix lane-address components (rows of 40 bf16 = 80B)
    const int l7 = lane & 7;
    const int lbit = (lane >> 3) & 1;
    const int csel = (lane >> 4) ? 16 : 0;
    const uint32_t aoff = (uint32_t)((wm * 16 + l7 + lbit * 8) * 80 + csel);
    uint32_t brow_off[2];
    #pragma unroll
    for (int g = 0; g < 2; g++)
        brow_off[g] = (uint32_t)((wn * 32 + g * 16 + l7 + lbit * 8) * 80 + csel);

    // convert mapping: thread -> row cr (0..63), 8 cols starting cc0
    const int cr = tid >> 2;
    const int cc0 = (tid & 3) * 8;
    const float* asrc = g_P + (size_t)(m0 + cr) * K2 + cc0;   // + kb*32 per block
    char* ah_base = smb + cr * 80 + cc0 * 2;                  // + (b)*ABUF_SZ
    char* al_base = ah_base + 5120;

    float4 pf[2];

    auto cvt_store = [&](int b) {
        char* hd = ah_base + b * ABUF_SZ;
        char* ld = al_base + b * ABUF_SZ;
        float4 a = pf[0];
        float4 bb = pf[1];
        uint32_t hp0 = __byte_perm(__float_as_uint(a.x), __float_as_uint(a.y), 0x7632);
        uint32_t hp1 = __byte_perm(__float_as_uint(a.z), __float_as_uint(a.w), 0x7632);
        uint32_t hp2 = __byte_perm(__float_as_uint(bb.x), __float_as_uint(bb.y), 0x7632);
        uint32_t hp3 = __byte_perm(__float_as_uint(bb.z), __float_as_uint(bb.w), 0x7632);
        float l0 = a.x - __uint_as_float(__float_as_uint(a.x) & 0xffff0000u);
        float l1 = a.y - __uint_as_float(__float_as_uint(a.y) & 0xffff0000u);
        float l2 = a.z - __uint_as_float(__float_as_uint(a.z) & 0xffff0000u);
        float l3 = a.w - __uint_as_float(__float_as_uint(a.w) & 0xffff0000u);
        float l4 = bb.x - __uint_as_float(__float_as_uint(bb.x) & 0xffff0000u);
        float l5 = bb.y - __uint_as_float(__float_as_uint(bb.y) & 0xffff0000u);
        float l6 = bb.z - __uint_as_float(__float_as_uint(bb.z) & 0xffff0000u);
        float l7f = bb.w - __uint_as_float(__float_as_uint(bb.w) & 0xffff0000u);
        __nv_bfloat162 lp0 = __float22bfloat162_rn(make_float2(l0, l1));
        __nv_bfloat162 lp1 = __float22bfloat162_rn(make_float2(l2, l3));
        __nv_bfloat162 lp2 = __float22bfloat162_rn(make_float2(l4, l5));
        __nv_bfloat162 lp3 = __float22bfloat162_rn(make_float2(l6, l7f));
        uint4 hv; hv.x = hp0; hv.y = hp1; hv.z = hp2; hv.w = hp3;
        *(uint4*)hd = hv;
        uint4 lv;
        lv.x = *(uint32_t*)&lp0; lv.y = *(uint32_t*)&lp1;
        lv.z = *(uint32_t*)&lp2; lv.w = *(uint32_t*)&lp3;
        *(uint4*)ld = lv;
    };
    auto lda = [&](int kb) {
        const float4* s4 = (const float4*)(asrc + kb * 32);
        pf[0] = s4[0]; pf[1] = s4[1];
    };

    float acc[4][4];
    #pragma unroll
    for (int na = 0; na < 4; na++)
        #pragma unroll
        for (int v = 0; v < 4; v++) acc[na][v] = 0.f;

    // prologue
    copyB_stage(smb, 0, 0, tid);
    copyB_stage(smb, 1, 1, tid);
    copyB_stage(smb, 2, 2, tid);
    lda(0);
    cvt_store(0);
    lda(1);

    uint32_t sb = smem_u32(smb);
    for (int blk = 0; blk < NKB2; blk++) {
        int rem = NKB2 - 1 - blk;
        if (rem >= 2)      asm volatile("cp.async.wait_group 2;" ::: "memory");
        else if (rem == 1) asm volatile("cp.async.wait_group 1;" ::: "memory");
        else               asm volatile("cp.async.wait_group 0;" ::: "memory");
        __syncthreads();

        // mma on ABUF[blk&1] + B slot blk%4; convert pf(blk+1) overlapped
        uint32_t ab = sb + (blk & 1) * ABUF_SZ;
        uint32_t bbase = sb + B_OFF + (blk & 3) * B_STAGE;
        #pragma unroll
        for (int s = 0; s < 2; s++) {
            uint32_t k0b = (uint32_t)(s * 32);
            uint32_t ahi[4], alo[4];
            ldsm_x4(ahi, ab + aoff + k0b);
            ldsm_x4(alo, ab + 5120 + aoff + k0b);
            #pragma unroll
            for (int g = 0; g < 2; g++) {
                uint32_t bh[4], bl[4];
                ldsm_x4(bh, bbase + brow_off[g] + k0b);
                ldsm_x4(bl, bbase + 5120 + brow_off[g] + k0b);
                mma16816(acc[2 * g],     ahi, bh[0], bh[2]);
                mma16816(acc[2 * g],     ahi, bl[0], bl[2]);
                mma16816(acc[2 * g],     alo, bh[0], bh[2]);
                mma16816(acc[2 * g + 1], ahi, bh[1], bh[3]);
                mma16816(acc[2 * g + 1], ahi, bl[1], bl[3]);
                mma16816(acc[2 * g + 1], alo, bh[1], bh[3]);
            }
        }
        if (blk + 1 < NKB2) cvt_store((blk + 1) & 1);
        if (blk + 2 < NKB2) lda(blk + 2);
        if (blk + 3 < NKB2) copyB_stage(smb, (blk + 3) & 3, blk + 3, tid);
    }

    // epilogue: rows m0 + wm*16 + lq (+8), cols wn*32 + na*8 + lr*2 (+1)
    int r0 = m0 + wm * 16 + lq;
    #pragma unroll
    for (int na = 0; na < 4; na++) {
        int c0 = wn * 32 + na * 8 + lr * 2;
        float bx = cbias[l * 64 + c0], by = cbias[l * 64 + c0 + 1];
        if (r0 < N_NODES) {
            g_m[r0 * 64 + c0]     = acc[na][0] + bx;
            g_m[r0 * 64 + c0 + 1] = acc[na][1] + by;
        }
        if (r0 + 8 < N_NODES) {
            g_m[(r0 + 8) * 64 + c0]     = acc[na][2] + bx;
            g_m[(r0 + 8) * 64 + c0 + 1] = acc[na][3] + by;
        }
    }
}

// ---------------- GRU step (2 nodes per iteration) ----------------------------
#define GRU_SMEM ((12288 * 2 + 192 * 2 + 64 * 4 + 192 * 4) * 4)
__global__ void k_gru(const float* __restrict__ Wih, const float* __restrict__ Whh,
                      const float* __restrict__ bih, const float* __restrict__ bhh,
                      float* __restrict__ dout, int last) {
    extern __shared__ float smf[];
    float* WihT = smf;                  // [i*192 + t]
    float* WhhT = smf + 12288;
    float* bihs = smf + 24576;
    float* bhhs = bihs + 192;
    float* ms   = bhhs + 192;           // 2 x 64
    float* hs   = ms + 128;             // 2 x 64
    float* gi   = hs + 128;             // 2 x 192
    float* gh   = gi + 384;             // 2 x 192
    int t = threadIdx.x;                // 192 threads
    for (int idx = t; idx < 192 * 64; idx += 192) {
        int j = idx / 64, i = idx % 64;
        WihT[i * 192 + j] = Wih[idx];
        WhhT[i * 192 + j] = Whh[idx];
    }
    bihs[t] = bih[t]; bhhs[t] = bhh[t];
    __syncthreads();
    for (int pair = blockIdx.x; pair < N_NODES / 2; pair += gridDim.x) {
        int n0 = pair * 2;
        if (t < 64) {
            ms[t]       = g_m[n0 * 64 + t];
            ms[64 + t]  = g_m[(n0 + 1) * 64 + t];
            hs[t]       = g_hidden[n0 * 64 + t];
            hs[64 + t]  = g_hidden[(n0 + 1) * 64 + t];
        }
        __syncthreads();
        float a0 = bihs[t], a1 = bihs[t], b0 = bhhs[t], b1 = bhhs[t];
        #pragma unroll 8
        for (int i = 0; i < 64; i++) {
            float w1 = WihT[i * 192 + t];
            float w2 = WhhT[i * 192 + t];
            a0 += ms[i] * w1;
            a1 += ms[64 + i] * w1;
            b0 += hs[i] * w2;
            b1 += hs[64 + i] * w2;
        }
        gi[t] = a0; gi[192 + t] = a1;
        gh[t] = b0; gh[192 + t] = b1;
        __syncthreads();
        if (t < 128) {
            int ns = t >> 6, tt = t & 63;
            int node = n0 + ns;
            const float* gin = gi + ns * 192;
            const float* ghn = gh + ns * 192;
            float r = 1.f / (1.f + expf(-(gin[tt] + ghn[tt])));
            float z = 1.f / (1.f + expf(-(gin[64 + tt] + ghn[64 + tt])));
            float n = tanhf(gin[128 + tt] + r * ghn[128 + tt]);
            float nh = (1.f - z) * n + z * hs[ns * 64 + tt];
            g_hidden[node * 64 + tt] = nh;
            g_h[node * 64 + tt] = nh;
            if (last) dout[node * 64 + tt] = nh;
        }
        __syncthreads();
    }
}

// ---------------- launcher ----------------------------------------------------
extern "C" void kernel_launch(void* const* d_in, const int* in_sizes, int n_in,
                              void* d_out, int out_size) {
    const float* x     = (const float*)d_in[0];
    const float* ea    = (const float*)d_in[1];
    const float* Wn1   = (const float*)d_in[2];
    const float* bn1   = (const float*)d_in[3];
    const float* Wn2   = (const float*)d_in[4];
    const float* bn2   = (const float*)d_in[5];
    const float* Wn3   = (const float*)d_in[6];
    const float* bn3   = (const float*)d_in[7];
    const float* We1   = (const float*)d_in[8];
    const float* be1   = (const float*)d_in[9];
    const float* We2   = (const float*)d_in[10];
    const float* be2   = (const float*)d_in[11];
    const float* We3   = (const float*)d_in[12];
    const float* be3   = (const float*)d_in[13];
    const float* roots = (const float*)d_in[14];
    const float* cbias = (const float*)d_in[15];
    const float* gWih  = (const float*)d_in[16];
    const float* gWhh  = (const float*)d_in[17];
    const float* gbih  = (const float*)d_in[18];
    const float* gbhh  = (const float*)d_in[19];
    const int*   ei    = (const int*)d_in[20];
    float* dout = (float*)d_out;

    cudaFuncSetAttribute(k_gru, cudaFuncAttributeMaxDynamicSharedMemorySize, GRU_SMEM);
    cudaFuncSetAttribute(k_gemm_mma, cudaFuncAttributeMaxDynamicSharedMemorySize, GEMM_SMEM);

    k_zero_misc<<<400, 256>>>();
    k_node_mlp<<<296, 256>>>(x, Wn1, bn1, Wn2, bn2, Wn3, bn3);
    k_edge_mlp<<<296, 256>>>(ea, We1, be1, We2, be2);
    k_hist<<<200, 256>>>(ei);
    k_scan<<<1, 1024>>>();
    k_fill<<<200, 256>>>(ei);
    k_sort<<<(N_NODES + 255) / 256, 256>>>();
    k_buildB_static<<<264, 256>>>(We3, be3);

    for (int l = 0; l < N_LAYERS; l++) {
        k_buildB_roots<<<16, 256>>>(roots, l);
        k_buildP<<<N_NODES / 2, 128>>>(ei);
        k_gemm_mma<<<M_PAD / 64, 256, GEMM_SMEM>>>(cbias, l);
        k_gru<<<296, 192, GRU_SMEM>>>(gWih, gWhh, gbih, gbhh, dout, l == N_LAYERS - 1);
    }
}

// round 13
// speedup vs baseline: 2.1701x; 1.0746x over previous
#include <cuda_runtime.h>
#include <cuda_bf16.h>
#include <cuda_fp16.h>
#include <cstdint>
#include <math.h>

#define N_NODES 25000
#define M_PAD   25088            // 392 * 64
#define N_EDGES 100000
#define H 64
#define K2 4224                  // 4096 (P edge part) + 64 (h for roots) + 64 (Q for be3)
#define N_LAYERS 3

// ---------------- scratch (static device globals) ---------------------------
__device__ float g_h[N_NODES * H];
__device__ float g_hidden[N_NODES * H];
__device__ float g_ew2[N_EDGES * H];
__device__ __align__(128) float g_P[(size_t)M_PAD * K2];             // ~424 MB fp32
__device__ __align__(128) __half g_B16[H * K2];                      // Bt[n][k] fp16
__device__ float g_m[N_NODES * H];
__device__ int   g_deg[N_NODES];
__device__ int   g_off[N_NODES + 1];
__device__ int   g_cur[N_NODES];
__device__ int   g_csr[N_EDGES];

// ---------------- helpers ------------------------------------------------
__device__ __forceinline__ uint32_t smem_u32(const void* p) {
    uint32_t a;
    asm("{ .reg .u64 t; cvta.to.shared.u64 t, %1; cvt.u32.u64 %0, t; }" : "=r"(a) : "l"(p));
    return a;
}

__device__ __forceinline__ void mma16816h(float* c, const uint32_t* a, uint32_t b0, uint32_t b1) {
    asm volatile("mma.sync.aligned.m16n8k16.row.col.f32.f16.f16.f32 "
        "{%0,%1,%2,%3}, {%4,%5,%6,%7}, {%8,%9}, {%0,%1,%2,%3};"
        : "+f"(c[0]), "+f"(c[1]), "+f"(c[2]), "+f"(c[3])
        : "r"(a[0]), "r"(a[1]), "r"(a[2]), "r"(a[3]), "r"(b0), "r"(b1));
}

__device__ __forceinline__ void ldsm_x4(uint32_t* r, uint32_t addr) {
    asm volatile("ldmatrix.sync.aligned.m8n8.x4.shared.b16 {%0,%1,%2,%3}, [%4];"
        : "=r"(r[0]), "=r"(r[1]), "=r"(r[2]), "=r"(r[3]) : "r"(addr));
}

// ---------------- zero init --------------------------------------------------
__global__ void k_zero_misc() {
    int i = blockIdx.x * blockDim.x + threadIdx.x;
    int st = gridDim.x * blockDim.x;
    for (int idx = i; idx < N_NODES; idx += st) g_deg[idx] = 0;
    for (int idx = i; idx < N_NODES * H; idx += st) g_hidden[idx] = 0.f;
    const size_t padN = (size_t)(M_PAD - N_NODES) * K2;
    for (size_t idx = i; idx < padN; idx += st)
        g_P[(size_t)N_NODES * K2 + idx] = 0.f;
}

// ---------------- node MLP ---------------------------------------------------
__global__ void k_node_mlp(const float* __restrict__ x,
                           const float* __restrict__ W1, const float* __restrict__ b1,
                           const float* __restrict__ W2, const float* __restrict__ b2,
                           const float* __restrict__ W3, const float* __restrict__ b3) {
    __shared__ float W1T[32 * 64], W2T[64 * 64], W3T[64 * 64];
    __shared__ float b1s[64], b2s[64], b3s[64];
    __shared__ float xs[4][32], h1[4][64], h2[4][64];
    int tid = threadIdx.x;
    for (int idx = tid; idx < 32 * 64; idx += 256) { int o = idx / 32, j = idx % 32; W1T[j * 64 + o] = W1[idx]; }
    for (int idx = tid; idx < 64 * 64; idx += 256) { int o = idx / 64, j = idx % 64; W2T[j * 64 + o] = W2[idx]; W3T[j * 64 + o] = W3[idx]; }
    if (tid < 64) { b1s[tid] = b1[tid]; b2s[tid] = b2[tid]; b3s[tid] = b3[tid]; }
    __syncthreads();
    int nl = tid >> 6, o = tid & 63;
    for (int base = blockIdx.x * 4; base < N_NODES; base += gridDim.x * 4) {
        int node = base + nl;
        if (o < 32 && node < N_NODES) xs[nl][o] = x[node * 32 + o];
        __syncthreads();
        if (node < N_NODES) {
            float a = b1s[o];
            #pragma unroll
            for (int j = 0; j < 32; j++) a += xs[nl][j] * W1T[j * 64 + o];
            h1[nl][o] = fmaxf(a, 0.f);
        }
        __syncthreads();
        if (node < N_NODES) {
            float a = b2s[o];
            #pragma unroll
            for (int j = 0; j < 64; j++) a += h1[nl][j] * W2T[j * 64 + o];
            h2[nl][o] = fmaxf(a, 0.f);
        }
        __syncthreads();
        if (node < N_NODES) {
            float a = b3s[o];
            #pragma unroll
            for (int j = 0; j < 64; j++) a += h2[nl][j] * W3T[j * 64 + o];
            g_h[node * 64 + o] = a;
        }
        __syncthreads();
    }
}

// ---------------- edge MLP (layers 1,2) --------------------------------------
__global__ void k_edge_mlp(const float* __restrict__ ea,
                           const float* __restrict__ W1, const float* __restrict__ b1,
                           const float* __restrict__ W2, const float* __restrict__ b2) {
    __shared__ float W1T[16 * 64], W2T[64 * 64];
    __shared__ float b1s[64], b2s[64];
    __shared__ float es[4][16], h1[4][64];
    int tid = threadIdx.x;
    for (int idx = tid; idx < 16 * 64; idx += 256) { int o = idx >> 4, j = idx & 15; W1T[j * 64 + o] = W1[idx]; }
    for (int idx = tid; idx < 64 * 64; idx += 256) { int o = idx >> 6, j = idx & 63; W2T[j * 64 + o] = W2[idx]; }
    if (tid < 64) { b1s[tid] = b1[tid]; b2s[tid] = b2[tid]; }
    __syncthreads();
    int nl = tid >> 6, o = tid & 63;
    for (int base = blockIdx.x * 4; base < N_EDGES; base += gridDim.x * 4) {
        int e = base + nl;
        if (o < 16 && e < N_EDGES) es[nl][o] = ea[e * 16 + o];
        __syncthreads();
        if (e < N_EDGES) {
            float a = b1s[o];
            #pragma unroll
            for (int j = 0; j < 16; j++) a += es[nl][j] * W1T[j * 64 + o];
            h1[nl][o] = fmaxf(a, 0.f);
        }
        __syncthreads();
        if (e < N_EDGES) {
            float a = b2s[o];
            #pragma unroll
            for (int j = 0; j < 64; j++) a += h1[nl][j] * W2T[j * 64 + o];
            g_ew2[e * 64 + o] = fmaxf(a, 0.f);
        }
        __syncthreads();
    }
}

// ---------------- CSR build --------------------------------------------------
__global__ void k_hist(const int* __restrict__ ei) {
    int i = blockIdx.x * blockDim.x + threadIdx.x, st = gridDim.x * blockDim.x;
    for (int e = i; e < N_EDGES; e += st) atomicAdd(&g_deg[ei[N_EDGES + e]], 1);
}

__global__ void k_scan() {
    __shared__ int part[1024];
    int t = threadIdx.x;
    const int CH = (N_NODES + 1023) / 1024;
    int b0 = t * CH, b1 = min(b0 + CH, N_NODES);
    int s = 0;
    for (int i = b0; i < b1; i++) s += g_deg[i];
    part[t] = s;
    __syncthreads();
    for (int d = 1; d < 1024; d <<= 1) {
        int v = (t >= d) ? part[t - d] : 0;
        __syncthreads();
        part[t] += v;
        __syncthreads();
    }
    int run = (t == 0) ? 0 : part[t - 1];
    for (int i = b0; i < b1; i++) { g_off[i] = run; g_cur[i] = run; run += g_deg[i]; }
    if (t == 1023) g_off[N_NODES] = part[1023];
}

__global__ void k_fill(const int* __restrict__ ei) {
    int i = blockIdx.x * blockDim.x + threadIdx.x, st = gridDim.x * blockDim.x;
    for (int e = i; e < N_EDGES; e += st) {
        int d = ei[N_EDGES + e];
        int p = atomicAdd(&g_cur[d], 1);
        g_csr[p] = e;
    }
}

__global__ void k_sort() {
    int d = blockIdx.x * blockDim.x + threadIdx.x;
    if (d >= N_NODES) return;
    int a = g_off[d], b = g_off[d + 1];
    for (int i = a + 1; i < b; i++) {
        int v = g_csr[i];
        int j = i - 1;
        while (j >= a && g_csr[j] > v) { g_csr[j + 1] = g_csr[j]; j--; }
        g_csr[j + 1] = v;
    }
}

// ---------------- build Bt[n][k] fp16: layer-invariant part (once) ------------
__global__ void k_buildB_static(const float* __restrict__ We3, const float* __restrict__ be3) {
    int i0 = blockIdx.x * blockDim.x + threadIdx.x, st = gridDim.x * blockDim.x;
    for (int idx = i0; idx < H * K2; idx += st) {
        int n = idx / K2, kg = idx % K2;
        if (kg >= 4096 && kg < 4160) continue;         // roots rows: per layer
        float v;
        if (kg < 4096) { int i = kg >> 6, k = kg & 63; v = We3[((i << 6) + n) * 64 + k]; }
        else           { v = be3[((kg - 4160) << 6) + n]; }
        g_B16[idx] = __float2half_rn(v);
    }
}

// per-layer: only the 64 roots rows (kg in [4096,4160))
__global__ void k_buildB_roots(const float* __restrict__ roots, int l) {
    int idx = blockIdx.x * blockDim.x + threadIdx.x;     // 64*64
    if (idx >= 64 * 64) return;
    int n = idx >> 6, r = idx & 63;
    g_B16[n * K2 + 4096 + r] = __float2half_rn(roots[(l * 64 + r) * 64 + n]);
}

// ---------------- build P rows (fp32, register accumulation, direct stores) ---
__global__ void __launch_bounds__(128) k_buildP(const int* __restrict__ ei) {
    int tid = threadIdx.x, warp = tid >> 5, lane = tid & 31;
    int ns_w = warp >> 1, kh = warp & 1;
    int d = blockIdx.x * 2 + ns_w;
    int kcol = kh * 32 + lane;

    float acc[64];
    #pragma unroll
    for (int i = 0; i < 64; i++) acc[i] = 0.f;

    int off0 = g_off[d];
    int deg = g_off[d + 1] - off0;
    for (int j = 0; j < deg; j++) {
        int e = g_csr[off0 + j];               // sorted -> deterministic order
        int s = ei[e];
        float ew = g_ew2[e * 64 + kcol];
        const float4* hr = (const float4*)(g_h + s * 64);
        #pragma unroll
        for (int i4 = 0; i4 < 16; i4++) {
            float4 hv = hr[i4];
            acc[i4 * 4 + 0] += hv.x * ew;
            acc[i4 * 4 + 1] += hv.y * ew;
            acc[i4 * 4 + 2] += hv.z * ew;
            acc[i4 * 4 + 3] += hv.w * ew;
        }
    }
    size_t rb = (size_t)d * K2;
    #pragma unroll
    for (int i = 0; i < 64; i++)
        g_P[rb + i * 64 + kcol] = acc[i];

    {
        int ns = tid >> 6, i = tid & 63;
        int dn = blockIdx.x * 2 + ns;
        size_t rb2 = (size_t)dn * K2;
        g_P[rb2 + 4096 + i] = g_h[dn * 64 + i];
        int o0 = g_off[dn], dg = g_off[dn + 1] - o0;
        float q = 0.f;
        for (int j = 0; j < dg; j++) q += g_h[ei[g_csr[o0 + j]] * 64 + i];
        g_P[rb2 + 4160 + i] = q;
    }
}

// ---------------- GEMM (M64, fp16 2-pass): direct-LDG A, convert<->mma --------
// smem: ABUF x2 (hi 64x40x2B=5120 + lo 5120 each) at 0 / 10240;
//       B stages x4 (single fp16 plane 5120) at 20480 + s*5120.
#define NKB2 132                 // K2 / 32
#define ABUF_SZ  10240
#define B_OFF    20480
#define B_STAGE  5120
#define GEMM_SMEM 40960

__device__ __forceinline__ void copyB_stage(char* smb, int slot, int kb, int tid) {
    char* bst = smb + B_OFF + slot * B_STAGE;
    int c = tid;                                // 256 chunks of 16B
    int row = c >> 2, c4 = c & 3;
    const __half* src = g_B16 + (size_t)row * K2 + kb * 32 + c4 * 8;
    uint32_t dst = smem_u32(bst + row * 80 + c4 * 16);
    asm volatile("cp.async.cg.shared.global [%0], [%1], 16;" :: "r"(dst), "l"(src));
    asm volatile("cp.async.commit_group;" ::: "memory");
}

__global__ void __launch_bounds__(256, 3) k_gemm_mma(const float* __restrict__ cbias, int l) {
    extern __shared__ __align__(16) char smb[];
    const int tid = threadIdx.x, w = tid >> 5, lane = tid & 31;
    const int m0 = blockIdx.x * 64;
    const int lq = lane >> 2;          // 0..7
    const int lr = lane & 3;           // 0..3
    const int wm = w >> 1;             // 0..3 (m16 group)
    const int wn = w & 1;              // 0..1 (n32 half)

    // ldmatrix lane-address components (rows of 40 fp16 = 80B)
    const int l7 = lane & 7;
    const int lbit = (lane >> 3) & 1;
    const int csel = (lane >> 4) ? 16 : 0;
    const uint32_t aoff = (uint32_t)((wm * 16 + l7 + lbit * 8) * 80 + csel);
    uint32_t brow_off[2];
    #pragma unroll
    for (int g = 0; g < 2; g++)
        brow_off[g] = (uint32_t)((wn * 32 + g * 16 + l7 + lbit * 8) * 80 + csel);

    // convert mapping: thread -> row cr (0..63), 8 cols starting cc0
    const int cr = tid >> 2;
    const int cc0 = (tid & 3) * 8;
    const float* asrc = g_P + (size_t)(m0 + cr) * K2 + cc0;   // + kb*32 per block
    char* ah_base = smb + cr * 80 + cc0 * 2;                  // + (b)*ABUF_SZ
    char* al_base = ah_base + 5120;

    float4 pf[2];

    auto cvt_store = [&](int b) {
        char* hd = ah_base + b * ABUF_SZ;
        char* ld = al_base + b * ABUF_SZ;
        float4 a = pf[0];
        float4 bb = pf[1];
        __half2 h0 = __float22half2_rn(make_float2(a.x, a.y));
        __half2 h1 = __float22half2_rn(make_float2(a.z, a.w));
        __half2 h2 = __float22half2_rn(make_float2(bb.x, bb.y));
        __half2 h3 = __float22half2_rn(make_float2(bb.z, bb.w));
        float2 f0 = __half22float2(h0);
        float2 f1 = __half22float2(h1);
        float2 f2 = __half22float2(h2);
        float2 f3 = __half22float2(h3);
        __half2 l0 = __float22half2_rn(make_float2(a.x - f0.x, a.y - f0.y));
        __half2 l1 = __float22half2_rn(make_float2(a.z - f1.x, a.w - f1.y));
        __half2 l2 = __float22half2_rn(make_float2(bb.x - f2.x, bb.y - f2.y));
        __half2 l3 = __float22half2_rn(make_float2(bb.z - f3.x, bb.w - f3.y));
        uint4 hv;
        hv.x = *(uint32_t*)&h0; hv.y = *(uint32_t*)&h1;
        hv.z = *(uint32_t*)&h2; hv.w = *(uint32_t*)&h3;
        *(uint4*)hd = hv;
        uint4 lv;
        lv.x = *(uint32_t*)&l0; lv.y = *(uint32_t*)&l1;
        lv.z = *(uint32_t*)&l2; lv.w = *(uint32_t*)&l3;
        *(uint4*)ld = lv;
    };
    auto lda = [&](int kb) {
        const float4* s4 = (const float4*)(asrc + kb * 32);
        pf[0] = s4[0]; pf[1] = s4[1];
    };

    float acc[4][4];
    #pragma unroll
    for (int na = 0; na < 4; na++)
        #pragma unroll
        for (int v = 0; v < 4; v++) acc[na][v] = 0.f;

    // prologue
    copyB_stage(smb, 0, 0, tid);
    copyB_stage(smb, 1, 1, tid);
    copyB_stage(smb, 2, 2, tid);
    lda(0);
    cvt_store(0);
    lda(1);

    uint32_t sb = smem_u32(smb);
    for (int blk = 0; blk < NKB2; blk++) {
        int rem = NKB2 - 1 - blk;
        if (rem >= 2)      asm volatile("cp.async.wait_group 2;" ::: "memory");
        else if (rem == 1) asm volatile("cp.async.wait_group 1;" ::: "memory");
        else               asm volatile("cp.async.wait_group 0;" ::: "memory");
        __syncthreads();

        // mma on ABUF[blk&1] + B slot blk%4; convert pf(blk+1) overlapped
        uint32_t ab = sb + (blk & 1) * ABUF_SZ;
        uint32_t bbase = sb + B_OFF + (blk & 3) * B_STAGE;
        #pragma unroll
        for (int s = 0; s < 2; s++) {
            uint32_t k0b = (uint32_t)(s * 32);
            uint32_t ahi[4], alo[4];
            ldsm_x4(ahi, ab + aoff + k0b);
            ldsm_x4(alo, ab + 5120 + aoff + k0b);
            #pragma unroll
            for (int g = 0; g < 2; g++) {
                uint32_t bh[4];
                ldsm_x4(bh, bbase + brow_off[g] + k0b);
                mma16816h(acc[2 * g],     ahi, bh[0], bh[2]);
                mma16816h(acc[2 * g],     alo, bh[0], bh[2]);
                mma16816h(acc[2 * g + 1], ahi, bh[1], bh[3]);
                mma16816h(acc[2 * g + 1], alo, bh[1], bh[3]);
            }
        }
        if (blk + 1 < NKB2) cvt_store((blk + 1) & 1);
        if (blk + 2 < NKB2) lda(blk + 2);
        if (blk + 3 < NKB2) copyB_stage(smb, (blk + 3) & 3, blk + 3, tid);
    }

    // epilogue: rows m0 + wm*16 + lq (+8), cols wn*32 + na*8 + lr*2 (+1)
    int r0 = m0 + wm * 16 + lq;
    #pragma unroll
    for (int na = 0; na < 4; na++) {
        int c0 = wn * 32 + na * 8 + lr * 2;
        float bx = cbias[l * 64 + c0], by = cbias[l * 64 + c0 + 1];
        if (r0 < N_NODES) {
            g_m[r0 * 64 + c0]     = acc[na][0] + bx;
            g_m[r0 * 64 + c0 + 1] = acc[na][1] + by;
        }
        if (r0 + 8 < N_NODES) {
            g_m[(r0 + 8) * 64 + c0]     = acc[na][2] + bx;
            g_m[(r0 + 8) * 64 + c0 + 1] = acc[na][3] + by;
        }
    }
}

// ---------------- GRU step (2 nodes per iteration) ----------------------------
#define GRU_SMEM ((12288 * 2 + 192 * 2 + 64 * 4 + 192 * 4) * 4)
__global__ void k_gru(const float* __restrict__ Wih, const float* __restrict__ Whh,
                      const float* __restrict__ bih, const float* __restrict__ bhh,
                      float* __restrict__ dout, int last) {
    extern __shared__ float smf[];
    float* WihT = smf;                  // [i*192 + t]
    float* WhhT = smf + 12288;
    float* bihs = smf + 24576;
    float* bhhs = bihs + 192;
    float* ms   = bhhs + 192;           // 2 x 64
    float* hs   = ms + 128;             // 2 x 64
    float* gi   = hs + 128;             // 2 x 192
    float* gh   = gi + 384;             // 2 x 192
    int t = threadIdx.x;                // 192 threads
    for (int idx = t; idx < 192 * 64; idx += 192) {
        int j = idx / 64, i = idx % 64;
        WihT[i * 192 + j] = Wih[idx];
        WhhT[i * 192 + j] = Whh[idx];
    }
    bihs[t] = bih[t]; bhhs[t] = bhh[t];
    __syncthreads();
    for (int pair = blockIdx.x; pair < N_NODES / 2; pair += gridDim.x) {
        int n0 = pair * 2;
        if (t < 64) {
            ms[t]       = g_m[n0 * 64 + t];
            ms[64 + t]  = g_m[(n0 + 1) * 64 + t];
            hs[t]       = g_hidden[n0 * 64 + t];
            hs[64 + t]  = g_hidden[(n0 + 1) * 64 + t];
        }
        __syncthreads();
        float a0 = bihs[t], a1 = bihs[t], b0 = bhhs[t], b1 = bhhs[t];
        #pragma unroll 8
        for (int i = 0; i < 64; i++) {
            float w1 = WihT[i * 192 + t];
            float w2 = WhhT[i * 192 + t];
            a0 += ms[i] * w1;
            a1 += ms[64 + i] * w1;
            b0 += hs[i] * w2;
            b1 += hs[64 + i] * w2;
        }
        gi[t] = a0; gi[192 + t] = a1;
        gh[t] = b0; gh[192 + t] = b1;
        __syncthreads();
        if (t < 128) {
            int ns = t >> 6, tt = t & 63;
            int node = n0 + ns;
            const float* gin = gi + ns * 192;
            const float* ghn = gh + ns * 192;
            float r = 1.f / (1.f + expf(-(gin[tt] + ghn[tt])));
            float z = 1.f / (1.f + expf(-(gin[64 + tt] + ghn[64 + tt])));
            float n = tanhf(gin[128 + tt] + r * ghn[128 + tt]);
            float nh = (1.f - z) * n + z * hs[ns * 64 + tt];
            g_hidden[node * 64 + tt] = nh;
            g_h[node * 64 + tt] = nh;
            if (last) dout[node * 64 + tt] = nh;
        }
        __syncthreads();
    }
}

// ---------------- launcher ----------------------------------------------------
extern "C" void kernel_launch(void* const* d_in, const int* in_sizes, int n_in,
                              void* d_out, int out_size) {
    const float* x     = (const float*)d_in[0];
    const float* ea    = (const float*)d_in[1];
    const float* Wn1   = (const float*)d_in[2];
    const float* bn1   = (const float*)d_in[3];
    const float* Wn2   = (const float*)d_in[4];
    const float* bn2   = (const float*)d_in[5];
    const float* Wn3   = (const float*)d_in[6];
    const float* bn3   = (const float*)d_in[7];
    const float* We1   = (const float*)d_in[8];
    const float* be1   = (const float*)d_in[9];
    const float* We2   = (const float*)d_in[10];
    const float* be2   = (const float*)d_in[11];
    const float* We3   = (const float*)d_in[12];
    const float* be3   = (const float*)d_in[13];
    const float* roots = (const float*)d_in[14];
    const float* cbias = (const float*)d_in[15];
    const float* gWih  = (const float*)d_in[16];
    const float* gWhh  = (const float*)d_in[17];
    const float* gbih  = (const float*)d_in[18];
    const float* gbhh  = (const float*)d_in[19];
    const int*   ei    = (const int*)d_in[20];
    float* dout = (float*)d_out;

    cudaFuncSetAttribute(k_gru, cudaFuncAttributeMaxDynamicSharedMemorySize, GRU_SMEM);
    cudaFuncSetAttribute(k_gemm_mma, cudaFuncAttributeMaxDynamicSharedMemorySize, GEMM_SMEM);

    k_zero_misc<<<400, 256>>>();
    k_node_mlp<<<296, 256>>>(x, Wn1, bn1, Wn2, bn2, Wn3, bn3);
    k_edge_mlp<<<296, 256>>>(ea, We1, be1, We2, be2);
    k_hist<<<200, 256>>>(ei);
    k_scan<<<1, 1024>>>();
    k_fill<<<200, 256>>>(ei);
    k_sort<<<(N_NODES + 255) / 256, 256>>>();
    k_buildB_static<<<264, 256>>>(We3, be3);

    for (int l = 0; l < N_LAYERS; l++) {
        k_buildB_roots<<<16, 256>>>(roots, l);
        k_buildP<<<N_NODES / 2, 128>>>(ei);
        k_gemm_mma<<<M_PAD / 64, 256, GEMM_SMEM>>>(cbias, l);
        k_gru<<<296, 192, GRU_SMEM>>>(gWih, gWhh, gbih, gbhh, dout, l == N_LAYERS - 1);
    }
}

// round 14
// speedup vs baseline: 2.5037x; 1.1537x over previous
#include <cuda_runtime.h>
#include <cuda_bf16.h>
#include <cuda_fp16.h>
#include <cstdint>
#include <math.h>

#define N_NODES 25000
#define M_PAD   25088            // 392 * 64
#define N_EDGES 100000
#define H 64
#define K2 4224                  // 4096 (P edge part) + 64 (h for roots) + 64 (Q for be3)
#define N_LAYERS 3

// ---------------- scratch (static device globals) ---------------------------
__device__ float g_h[N_NODES * H];
__device__ float g_hidden[N_NODES * H];
__device__ float g_ew2[N_EDGES * H];
__device__ __align__(128) __half g_P16[(size_t)M_PAD * K2];          // ~212 MB fp16
__device__ __align__(128) __half g_B16[H * K2];                      // Bt[n][k] fp16
__device__ float g_m[N_NODES * H];
__device__ int   g_deg[N_NODES];
__device__ int   g_off[N_NODES + 1];
__device__ int   g_cur[N_NODES];
__device__ int   g_csr[N_EDGES];

// ---------------- helpers ------------------------------------------------
__device__ __forceinline__ uint32_t smem_u32(const void* p) {
    uint32_t a;
    asm("{ .reg .u64 t; cvta.to.shared.u64 t, %1; cvt.u32.u64 %0, t; }" : "=r"(a) : "l"(p));
    return a;
}

__device__ __forceinline__ void mma16816h(float* c, const uint32_t* a, uint32_t b0, uint32_t b1) {
    asm volatile("mma.sync.aligned.m16n8k16.row.col.f32.f16.f16.f32 "
        "{%0,%1,%2,%3}, {%4,%5,%6,%7}, {%8,%9}, {%0,%1,%2,%3};"
        : "+f"(c[0]), "+f"(c[1]), "+f"(c[2]), "+f"(c[3])
        : "r"(a[0]), "r"(a[1]), "r"(a[2]), "r"(a[3]), "r"(b0), "r"(b1));
}

__device__ __forceinline__ void ldsm_x4(uint32_t* r, uint32_t addr) {
    asm volatile("ldmatrix.sync.aligned.m8n8.x4.shared.b16 {%0,%1,%2,%3}, [%4];"
        : "=r"(r[0]), "=r"(r[1]), "=r"(r[2]), "=r"(r[3]) : "r"(addr));
}

// ---------------- zero init --------------------------------------------------
__global__ void k_zero_misc() {
    int i = blockIdx.x * blockDim.x + threadIdx.x;
    int st = gridDim.x * blockDim.x;
    for (int idx = i; idx < N_NODES; idx += st) g_deg[idx] = 0;
    for (int idx = i; idx < N_NODES * H; idx += st) g_hidden[idx] = 0.f;
    const size_t padN = (size_t)(M_PAD - N_NODES) * K2;
    __half z = __float2half_rn(0.f);
    for (size_t idx = i; idx < padN; idx += st)
        g_P16[(size_t)N_NODES * K2 + idx] = z;
}

// ---------------- node MLP ---------------------------------------------------
__global__ void k_node_mlp(const float* __restrict__ x,
                           const float* __restrict__ W1, const float* __restrict__ b1,
                           const float* __restrict__ W2, const float* __restrict__ b2,
                           const float* __restrict__ W3, const float* __restrict__ b3) {
    __shared__ float W1T[32 * 64], W2T[64 * 64], W3T[64 * 64];
    __shared__ float b1s[64], b2s[64], b3s[64];
    __shared__ float xs[4][32], h1[4][64], h2[4][64];
    int tid = threadIdx.x;
    for (int idx = tid; idx < 32 * 64; idx += 256) { int o = idx / 32, j = idx % 32; W1T[j * 64 + o] = W1[idx]; }
    for (int idx = tid; idx < 64 * 64; idx += 256) { int o = idx / 64, j = idx % 64; W2T[j * 64 + o] = W2[idx]; W3T[j * 64 + o] = W3[idx]; }
    if (tid < 64) { b1s[tid] = b1[tid]; b2s[tid] = b2[tid]; b3s[tid] = b3[tid]; }
    __syncthreads();
    int nl = tid >> 6, o = tid & 63;
    for (int base = blockIdx.x * 4; base < N_NODES; base += gridDim.x * 4) {
        int node = base + nl;
        if (o < 32 && node < N_NODES) xs[nl][o] = x[node * 32 + o];
        __syncthreads();
        if (node < N_NODES) {
            float a = b1s[o];
            #pragma unroll
            for (int j = 0; j < 32; j++) a += xs[nl][j] * W1T[j * 64 + o];
            h1[nl][o] = fmaxf(a, 0.f);
        }
        __syncthreads();
        if (node < N_NODES) {
            float a = b2s[o];
            #pragma unroll
            for (int j = 0; j < 64; j++) a += h1[nl][j] * W2T[j * 64 + o];
            h2[nl][o] = fmaxf(a, 0.f);
        }
        __syncthreads();
        if (node < N_NODES) {
            float a = b3s[o];
            #pragma unroll
            for (int j = 0; j < 64; j++) a += h2[nl][j] * W3T[j * 64 + o];
            g_h[node * 64 + o] = a;
        }
        __syncthreads();
    }
}

// ---------------- edge MLP (layers 1,2) --------------------------------------
__global__ void k_edge_mlp(const float* __restrict__ ea,
                           const float* __restrict__ W1, const float* __restrict__ b1,
                           const float* __restrict__ W2, const float* __restrict__ b2) {
    __shared__ float W1T[16 * 64], W2T[64 * 64];
    __shared__ float b1s[64], b2s[64];
    __shared__ float es[4][16], h1[4][64];
    int tid = threadIdx.x;
    for (int idx = tid; idx < 16 * 64; idx += 256) { int o = idx >> 4, j = idx & 15; W1T[j * 64 + o] = W1[idx]; }
    for (int idx = tid; idx < 64 * 64; idx += 256) { int o = idx >> 6, j = idx & 63; W2T[j * 64 + o] = W2[idx]; }
    if (tid < 64) { b1s[tid] = b1[tid]; b2s[tid] = b2[tid]; }
    __syncthreads();
    int nl = tid >> 6, o = tid & 63;
    for (int base = blockIdx.x * 4; base < N_EDGES; base += gridDim.x * 4) {
        int e = base + nl;
        if (o < 16 && e < N_EDGES) es[nl][o] = ea[e * 16 + o];
        __syncthreads();
        if (e < N_EDGES) {
            float a = b1s[o];
            #pragma unroll
            for (int j = 0; j < 16; j++) a += es[nl][j] * W1T[j * 64 + o];
            h1[nl][o] = fmaxf(a, 0.f);
        }
        __syncthreads();
        if (e < N_EDGES) {
            float a = b2s[o];
            #pragma unroll
            for (int j = 0; j < 64; j++) a += h1[nl][j] * W2T[j * 64 + o];
            g_ew2[e * 64 + o] = fmaxf(a, 0.f);
        }
        __syncthreads();
    }
}

// ---------------- CSR build --------------------------------------------------
__global__ void k_hist(const int* __restrict__ ei) {
    int i = blockIdx.x * blockDim.x + threadIdx.x, st = gridDim.x * blockDim.x;
    for (int e = i; e < N_EDGES; e += st) atomicAdd(&g_deg[ei[N_EDGES + e]], 1);
}

__global__ void k_scan() {
    __shared__ int part[1024];
    int t = threadIdx.x;
    const int CH = (N_NODES + 1023) / 1024;
    int b0 = t * CH, b1 = min(b0 + CH, N_NODES);
    int s = 0;
    for (int i = b0; i < b1; i++) s += g_deg[i];
    part[t] = s;
    __syncthreads();
    for (int d = 1; d < 1024; d <<= 1) {
        int v = (t >= d) ? part[t - d] : 0;
        __syncthreads();
        part[t] += v;
        __syncthreads();
    }
    int run = (t == 0) ? 0 : part[t - 1];
    for (int i = b0; i < b1; i++) { g_off[i] = run; g_cur[i] = run; run += g_deg[i]; }
    if (t == 1023) g_off[N_NODES] = part[1023];
}

__global__ void k_fill(const int* __restrict__ ei) {
    int i = blockIdx.x * blockDim.x + threadIdx.x, st = gridDim.x * blockDim.x;
    for (int e = i; e < N_EDGES; e += st) {
        int d = ei[N_EDGES + e];
        int p = atomicAdd(&g_cur[d], 1);
        g_csr[p] = e;
    }
}

__global__ void k_sort() {
    int d = blockIdx.x * blockDim.x + threadIdx.x;
    if (d >= N_NODES) return;
    int a = g_off[d], b = g_off[d + 1];
    for (int i = a + 1; i < b; i++) {
        int v = g_csr[i];
        int j = i - 1;
        while (j >= a && g_csr[j] > v) { g_csr[j + 1] = g_csr[j]; j--; }
        g_csr[j + 1] = v;
    }
}

// ---------------- build Bt[n][k] fp16: layer-invariant part (once) ------------
__global__ void k_buildB_static(const float* __restrict__ We3, const float* __restrict__ be3) {
    int i0 = blockIdx.x * blockDim.x + threadIdx.x, st = gridDim.x * blockDim.x;
    for (int idx = i0; idx < H * K2; idx += st) {
        int n = idx / K2, kg = idx % K2;
        if (kg >= 4096 && kg < 4160) continue;         // roots rows: per layer
        float v;
        if (kg < 4096) { int i = kg >> 6, k = kg & 63; v = We3[((i << 6) + n) * 64 + k]; }
        else           { v = be3[((kg - 4160) << 6) + n]; }
        g_B16[idx] = __float2half_rn(v);
    }
}

// per-layer: only the 64 roots rows (kg in [4096,4160))
__global__ void k_buildB_roots(const float* __restrict__ roots, int l) {
    int idx = blockIdx.x * blockDim.x + threadIdx.x;     // 64*64
    if (idx >= 64 * 64) return;
    int n = idx >> 6, r = idx & 63;
    g_B16[n * K2 + 4096 + r] = __float2half_rn(roots[(l * 64 + r) * 64 + n]);
}

// ---------------- build P rows (fp32 accum, fp16 stores) ----------------------
__global__ void __launch_bounds__(128) k_buildP(const int* __restrict__ ei) {
    int tid = threadIdx.x, warp = tid >> 5, lane = tid & 31;
    int ns_w = warp >> 1, kh = warp & 1;
    int d = blockIdx.x * 2 + ns_w;
    int kcol = kh * 32 + lane;

    float acc[64];
    #pragma unroll
    for (int i = 0; i < 64; i++) acc[i] = 0.f;

    int off0 = g_off[d];
    int deg = g_off[d + 1] - off0;
    for (int j = 0; j < deg; j++) {
        int e = g_csr[off0 + j];               // sorted -> deterministic order
        int s = ei[e];
        float ew = g_ew2[e * 64 + kcol];
        const float4* hr = (const float4*)(g_h + s * 64);
        #pragma unroll
        for (int i4 = 0; i4 < 16; i4++) {
            float4 hv = hr[i4];
            acc[i4 * 4 + 0] += hv.x * ew;
            acc[i4 * 4 + 1] += hv.y * ew;
            acc[i4 * 4 + 2] += hv.z * ew;
            acc[i4 * 4 + 3] += hv.w * ew;
        }
    }
    size_t rb = (size_t)d * K2;
    #pragma unroll
    for (int i = 0; i < 64; i++)
        g_P16[rb + i * 64 + kcol] = __float2half_rn(acc[i]);

    {
        int ns = tid >> 6, i = tid & 63;
        int dn = blockIdx.x * 2 + ns;
        size_t rb2 = (size_t)dn * K2;
        g_P16[rb2 + 4096 + i] = __float2half_rn(g_h[dn * 64 + i]);
        int o0 = g_off[dn], dg = g_off[dn + 1] - o0;
        float q = 0.f;
        for (int j = 0; j < dg; j++) q += g_h[ei[g_csr[o0 + j]] * 64 + i];
        g_P16[rb2 + 4160 + i] = __float2half_rn(q);
    }
}

// ---------------- GEMM (M64, single fp16 pass, 4-stage cp.async) --------------
// smem: A stages x4 (64x40 fp16 = 5120 B) at 0 + s*5120;
//       B stages x4 (64x40 fp16 = 5120 B) at 20480 + s*5120.  Total 40960.
#define NKB2 132                 // K2 / 32
#define A_STAGE 5120
#define B_OFF   20480
#define B_STAGE 5120
#define GEMM_SMEM 40960

__device__ __forceinline__ void copy_stage(char* smb, int slot, int m0, int kb, int tid) {
    int row = tid >> 2, c4 = tid & 3;           // 64 rows x 4 chunks(16B)
    // A chunk
    {
        const __half* src = g_P16 + (size_t)(m0 + row) * K2 + kb * 32 + c4 * 8;
        uint32_t dst = smem_u32(smb + slot * A_STAGE + row * 80 + c4 * 16);
        asm volatile("cp.async.cg.shared.global [%0], [%1], 16;" :: "r"(dst), "l"(src));
    }
    // B chunk
    {
        const __half* src = g_B16 + (size_t)row * K2 + kb * 32 + c4 * 8;
        uint32_t dst = smem_u32(smb + B_OFF + slot * B_STAGE + row * 80 + c4 * 16);
        asm volatile("cp.async.cg.shared.global [%0], [%1], 16;" :: "r"(dst), "l"(src));
    }
    asm volatile("cp.async.commit_group;" ::: "memory");
}

__global__ void __launch_bounds__(256, 3) k_gemm_mma(const float* __restrict__ cbias, int l) {
    extern __shared__ __align__(16) char smb[];
    const int tid = threadIdx.x, w = tid >> 5, lane = tid & 31;
    const int m0 = blockIdx.x * 64;
    const int lq = lane >> 2;          // 0..7
    const int lr = lane & 3;           // 0..3
    const int wm = w >> 1;             // 0..3 (m16 group)
    const int wn = w & 1;              // 0..1 (n32 half)

    // ldmatrix lane-address components (rows of 40 fp16 = 80B)
    const int l7 = lane & 7;
    const int lbit = (lane >> 3) & 1;
    const int csel = (lane >> 4) ? 16 : 0;
    const uint32_t aoff = (uint32_t)((wm * 16 + l7 + lbit * 8) * 80 + csel);
    uint32_t brow_off[2];
    #pragma unroll
    for (int g = 0; g < 2; g++)
        brow_off[g] = (uint32_t)((wn * 32 + g * 16 + l7 + lbit * 8) * 80 + csel);

    float acc[4][4];
    #pragma unroll
    for (int na = 0; na < 4; na++)
        #pragma unroll
        for (int v = 0; v < 4; v++) acc[na][v] = 0.f;

    // prologue: prefetch 3 stages
    copy_stage(smb, 0, m0, 0, tid);
    copy_stage(smb, 1, m0, 1, tid);
    copy_stage(smb, 2, m0, 2, tid);

    uint32_t sb = smem_u32(smb);
    for (int blk = 0; blk < NKB2; blk++) {
        int rem = NKB2 - 1 - blk;
        if (rem >= 2)      asm volatile("cp.async.wait_group 2;" ::: "memory");
        else if (rem == 1) asm volatile("cp.async.wait_group 1;" ::: "memory");
        else               asm volatile("cp.async.wait_group 0;" ::: "memory");
        __syncthreads();

        uint32_t abase = sb + (blk & 3) * A_STAGE;
        uint32_t bbase = sb + B_OFF + (blk & 3) * B_STAGE;
        #pragma unroll
        for (int s = 0; s < 2; s++) {
            uint32_t k0b = (uint32_t)(s * 32);
            uint32_t af[4];
            ldsm_x4(af, abase + aoff + k0b);
            #pragma unroll
            for (int g = 0; g < 2; g++) {
                uint32_t bh[4];
                ldsm_x4(bh, bbase + brow_off[g] + k0b);
                mma16816h(acc[2 * g],     af, bh[0], bh[2]);
                mma16816h(acc[2 * g + 1], af, bh[1], bh[3]);
            }
        }
        if (blk + 3 < NKB2) copy_stage(smb, (blk + 3) & 3, m0, blk + 3, tid);
    }

    // epilogue: rows m0 + wm*16 + lq (+8), cols wn*32 + na*8 + lr*2 (+1)
    int r0 = m0 + wm * 16 + lq;
    #pragma unroll
    for (int na = 0; na < 4; na++) {
        int c0 = wn * 32 + na * 8 + lr * 2;
        float bx = cbias[l * 64 + c0], by = cbias[l * 64 + c0 + 1];
        if (r0 < N_NODES) {
            g_m[r0 * 64 + c0]     = acc[na][0] + bx;
            g_m[r0 * 64 + c0 + 1] = acc[na][1] + by;
        }
        if (r0 + 8 < N_NODES) {
            g_m[(r0 + 8) * 64 + c0]     = acc[na][2] + bx;
            g_m[(r0 + 8) * 64 + c0 + 1] = acc[na][3] + by;
        }
    }
}

// ---------------- GRU step (2 nodes per iteration) ----------------------------
#define GRU_SMEM ((12288 * 2 + 192 * 2 + 64 * 4 + 192 * 4) * 4)
__global__ void k_gru(const float* __restrict__ Wih, const float* __restrict__ Whh,
                      const float* __restrict__ bih, const float* __restrict__ bhh,
                      float* __restrict__ dout, int last) {
    extern __shared__ float smf[];
    float* WihT = smf;                  // [i*192 + t]
    float* WhhT = smf + 12288;
    float* bihs = smf + 24576;
    float* bhhs = bihs + 192;
    float* ms   = bhhs + 192;           // 2 x 64
    float* hs   = ms + 128;             // 2 x 64
    float* gi   = hs + 128;             // 2 x 192
    float* gh   = gi + 384;             // 2 x 192
    int t = threadIdx.x;                // 192 threads
    for (int idx = t; idx < 192 * 64; idx += 192) {
        int j = idx / 64, i = idx % 64;
        WihT[i * 192 + j] = Wih[idx];
        WhhT[i * 192 + j] = Whh[idx];
    }
    bihs[t] = bih[t]; bhhs[t] = bhh[t];
    __syncthreads();
    for (int pair = blockIdx.x; pair < N_NODES / 2; pair += gridDim.x) {
        int n0 = pair * 2;
        if (t < 64) {
            ms[t]       = g_m[n0 * 64 + t];
            ms[64 + t]  = g_m[(n0 + 1) * 64 + t];
            hs[t]       = g_hidden[n0 * 64 + t];
            hs[64 + t]  = g_hidden[(n0 + 1) * 64 + t];
        }
        __syncthreads();
        float a0 = bihs[t], a1 = bihs[t], b0 = bhhs[t], b1 = bhhs[t];
        #pragma unroll 8
        for (int i = 0; i < 64; i++) {
            float w1 = WihT[i * 192 + t];
            float w2 = WhhT[i * 192 + t];
            a0 += ms[i] * w1;
            a1 += ms[64 + i] * w1;
            b0 += hs[i] * w2;
            b1 += hs[64 + i] * w2;
        }
        gi[t] = a0; gi[192 + t] = a1;
        gh[t] = b0; gh[192 + t] = b1;
        __syncthreads();
        if (t < 128) {
            int ns = t >> 6, tt = t & 63;
            int node = n0 + ns;
            const float* gin = gi + ns * 192;
            const float* ghn = gh + ns * 192;
            float r = 1.f / (1.f + expf(-(gin[tt] + ghn[tt])));
            float z = 1.f / (1.f + expf(-(gin[64 + tt] + ghn[64 + tt])));
            float n = tanhf(gin[128 + tt] + r * ghn[128 + tt]);
            float nh = (1.f - z) * n + z * hs[ns * 64 + tt];
            g_hidden[node * 64 + tt] = nh;
            g_h[node * 64 + tt] = nh;
            if (last) dout[node * 64 + tt] = nh;
        }
        __syncthreads();
    }
}

// ---------------- launcher ----------------------------------------------------
extern "C" void kernel_launch(void* const* d_in, const int* in_sizes, int n_in,
                              void* d_out, int out_size) {
    const float* x     = (const float*)d_in[0];
    const float* ea    = (const float*)d_in[1];
    const float* Wn1   = (const float*)d_in[2];
    const float* bn1   = (const float*)d_in[3];
    const float* Wn2   = (const float*)d_in[4];
    const float* bn2   = (const float*)d_in[5];
    const float* Wn3   = (const float*)d_in[6];
    const float* bn3   = (const float*)d_in[7];
    const float* We1   = (const float*)d_in[8];
    const float* be1   = (const float*)d_in[9];
    const float* We2   = (const float*)d_in[10];
    const float* be2   = (const float*)d_in[11];
    const float* We3   = (const float*)d_in[12];
    const float* be3   = (const float*)d_in[13];
    const float* roots = (const float*)d_in[14];
    const float* cbias = (const float*)d_in[15];
    const float* gWih  = (const float*)d_in[16];
    const float* gWhh  = (const float*)d_in[17];
    const float* gbih  = (const float*)d_in[18];
    const float* gbhh  = (const float*)d_in[19];
    const int*   ei    = (const int*)d_in[20];
    float* dout = (float*)d_out;

    cudaFuncSetAttribute(k_gru, cudaFuncAttributeMaxDynamicSharedMemorySize, GRU_SMEM);
    cudaFuncSetAttribute(k_gemm_mma, cudaFuncAttributeMaxDynamicSharedMemorySize, GEMM_SMEM);

    k_zero_misc<<<400, 256>>>();
    k_node_mlp<<<296, 256>>>(x, Wn1, bn1, Wn2, bn2, Wn3, bn3);
    k_edge_mlp<<<296, 256>>>(ea, We1, be1, We2, be2);
    k_hist<<<200, 256>>>(ei);
    k_scan<<<1, 1024>>>();
    k_fill<<<200, 256>>>(ei);
    k_sort<<<(N_NODES + 255) / 256, 256>>>();
    k_buildB_static<<<264, 256>>>(We3, be3);

    for (int l = 0; l < N_LAYERS; l++) {
        k_buildB_roots<<<16, 256>>>(roots, l);
        k_buildP<<<N_NODES / 2, 128>>>(ei);
        k_gemm_mma<<<M_PAD / 64, 256, GEMM_SMEM>>>(cbias, l);
        k_gru<<<296, 192, GRU_SMEM>>>(gWih, gWhh, gbih, gbhh, dout, l == N_LAYERS - 1);
    }
}

// round 15
// speedup vs baseline: 2.6788x; 1.0700x over previous
#include <cuda_runtime.h>
#include <cuda_bf16.h>
#include <cuda_fp16.h>
#include <cstdint>
#include <math.h>

#define N_NODES 25000
#define M_PAD   25088            // 392 * 64
#define N_EDGES 100000
#define H 64
#define K2 4224                  // 4096 (P edge part) + 64 (h for roots) + 64 (Q for be3)
#define N_LAYERS 3

// ---------------- scratch (static device globals) ---------------------------
__device__ float g_h[N_NODES * H];
__device__ float g_hidden[N_NODES * H];
__device__ float g_ew2[N_EDGES * H];
__device__ __align__(128) __half g_P16[(size_t)M_PAD * K2];          // ~212 MB fp16
__device__ __align__(128) __half g_B16[H * K2];                      // Bt[n][k] fp16
__device__ float g_m[N_NODES * H];
__device__ int   g_deg[N_NODES];
__device__ int   g_off[N_NODES + 1];
__device__ int   g_cur[N_NODES];
__device__ int   g_csr[N_EDGES];

// ---------------- helpers ------------------------------------------------
__device__ __forceinline__ uint32_t smem_u32(const void* p) {
    uint32_t a;
    asm("{ .reg .u64 t; cvta.to.shared.u64 t, %1; cvt.u32.u64 %0, t; }" : "=r"(a) : "l"(p));
    return a;
}

__device__ __forceinline__ void mma16816h(float* c, const uint32_t* a, uint32_t b0, uint32_t b1) {
    asm volatile("mma.sync.aligned.m16n8k16.row.col.f32.f16.f16.f32 "
        "{%0,%1,%2,%3}, {%4,%5,%6,%7}, {%8,%9}, {%0,%1,%2,%3};"
        : "+f"(c[0]), "+f"(c[1]), "+f"(c[2]), "+f"(c[3])
        : "r"(a[0]), "r"(a[1]), "r"(a[2]), "r"(a[3]), "r"(b0), "r"(b1));
}

__device__ __forceinline__ void ldsm_x4(uint32_t* r, uint32_t addr) {
    asm volatile("ldmatrix.sync.aligned.m8n8.x4.shared.b16 {%0,%1,%2,%3}, [%4];"
        : "=r"(r[0]), "=r"(r[1]), "=r"(r[2]), "=r"(r[3]) : "r"(addr));
}

// ---------------- zero init --------------------------------------------------
__global__ void k_zero_misc() {
    int i = blockIdx.x * blockDim.x + threadIdx.x;
    int st = gridDim.x * blockDim.x;
    for (int idx = i; idx < N_NODES; idx += st) g_deg[idx] = 0;
    for (int idx = i; idx < N_NODES * H; idx += st) g_hidden[idx] = 0.f;
    const size_t padN = (size_t)(M_PAD - N_NODES) * K2;
    __half z = __float2half_rn(0.f);
    for (size_t idx = i; idx < padN; idx += st)
        g_P16[(size_t)N_NODES * K2 + idx] = z;
}

// ---------------- node MLP (register-blocked 4x4, tile=64 nodes) --------------
// smem floats: W1T 32*64 | W2T 64*64 | W3T 64*64 | b1 64 | b2 64 | b3 64 |
//              xT 32*68 | h1T 64*68 | h2T 64*68
#define NMLP_SMEM ((2048 + 4096 + 4096 + 192 + 32 * 68 + 64 * 68 + 64 * 68) * 4)
__global__ void __launch_bounds__(256) k_node_mlp(const float* __restrict__ x,
                           const float* __restrict__ W1, const float* __restrict__ b1,
                           const float* __restrict__ W2, const float* __restrict__ b2,
                           const float* __restrict__ W3, const float* __restrict__ b3) {
    extern __shared__ float sm[];
    float* W1T = sm;                 // [j][o] j<32
    float* W2T = W1T + 2048;
    float* W3T = W2T + 4096;
    float* b1s = W3T + 4096;
    float* b2s = b1s + 64;
    float* b3s = b2s + 64;
    float* xT  = b3s + 64;           // [j][n] stride 68, j<32
    float* h1T = xT + 32 * 68;       // [j][n] stride 68
    float* h2T = h1T + 64 * 68;
    int tid = threadIdx.x;
    for (int i = tid; i < 2048; i += 256) { int o = i >> 5, j = i & 31; W1T[j * 64 + o] = W1[i]; }
    for (int i = tid; i < 4096; i += 256) { int o = i >> 6, j = i & 63; W2T[j * 64 + o] = W2[i]; W3T[j * 64 + o] = W3[i]; }
    if (tid < 64) { b1s[tid] = b1[tid]; b2s[tid] = b2[tid]; b3s[tid] = b3[tid]; }
    int n0 = blockIdx.x * 64;
    // stage x transposed: 64 nodes x 32 = 2048 floats, 512 float4 loads
    #pragma unroll
    for (int q = 0; q < 2; q++) {
        int idx = q * 256 + tid;                 // 0..511
        int n = idx >> 3, j = (idx & 7) * 4;
        float4 v = make_float4(0.f, 0.f, 0.f, 0.f);
        if (n0 + n < N_NODES) v = *(const float4*)(x + (size_t)(n0 + n) * 32 + j);
        xT[(j + 0) * 68 + n] = v.x;
        xT[(j + 1) * 68 + n] = v.y;
        xT[(j + 2) * 68 + n] = v.z;
        xT[(j + 3) * 68 + n] = v.w;
    }
    __syncthreads();
    int ng = (tid & 15) * 4;          // node offset 0..60
    int og = (tid >> 4) * 4;          // output col 0..60
    float acc[4][4];
    // layer 1 (K=32)
    #pragma unroll
    for (int ni = 0; ni < 4; ni++)
        #pragma unroll
        for (int oi = 0; oi < 4; oi++) acc[ni][oi] = b1s[og + oi];
    for (int j = 0; j < 32; j++) {
        float4 wv = *(const float4*)&W1T[j * 64 + og];
        float4 ev = *(const float4*)&xT[j * 68 + ng];
        float e[4] = {ev.x, ev.y, ev.z, ev.w};
        float wl[4] = {wv.x, wv.y, wv.z, wv.w};
        #pragma unroll
        for (int ni = 0; ni < 4; ni++)
            #pragma unroll
            for (int oi = 0; oi < 4; oi++) acc[ni][oi] += e[ni] * wl[oi];
    }
    #pragma unroll
    for (int oi = 0; oi < 4; oi++) {
        float4 v = make_float4(fmaxf(acc[0][oi], 0.f), fmaxf(acc[1][oi], 0.f),
                               fmaxf(acc[2][oi], 0.f), fmaxf(acc[3][oi], 0.f));
        *(float4*)&h1T[(og + oi) * 68 + ng] = v;
    }
    __syncthreads();
    // layer 2 (K=64)
    #pragma unroll
    for (int ni = 0; ni < 4; ni++)
        #pragma unroll
        for (int oi = 0; oi < 4; oi++) acc[ni][oi] = b2s[og + oi];
    for (int j = 0; j < 64; j++) {
        float4 wv = *(const float4*)&W2T[j * 64 + og];
        float4 ev = *(const float4*)&h1T[j * 68 + ng];
        float e[4] = {ev.x, ev.y, ev.z, ev.w};
        float wl[4] = {wv.x, wv.y, wv.z, wv.w};
        #pragma unroll
        for (int ni = 0; ni < 4; ni++)
            #pragma unroll
            for (int oi = 0; oi < 4; oi++) acc[ni][oi] += e[ni] * wl[oi];
    }
    #pragma unroll
    for (int oi = 0; oi < 4; oi++) {
        float4 v = make_float4(fmaxf(acc[0][oi], 0.f), fmaxf(acc[1][oi], 0.f),
                               fmaxf(acc[2][oi], 0.f), fmaxf(acc[3][oi], 0.f));
        *(float4*)&h2T[(og + oi) * 68 + ng] = v;
    }
    __syncthreads();
    // layer 3 (K=64, no relu) -> g_h
    #pragma unroll
    for (int ni = 0; ni < 4; ni++)
        #pragma unroll
        for (int oi = 0; oi < 4; oi++) acc[ni][oi] = b3s[og + oi];
    for (int j = 0; j < 64; j++) {
        float4 wv = *(const float4*)&W3T[j * 64 + og];
        float4 ev = *(const float4*)&h2T[j * 68 + ng];
        float e[4] = {ev.x, ev.y, ev.z, ev.w};
        float wl[4] = {wv.x, wv.y, wv.z, wv.w};
        #pragma unroll
        for (int ni = 0; ni < 4; ni++)
            #pragma unroll
            for (int oi = 0; oi < 4; oi++) acc[ni][oi] += e[ni] * wl[oi];
    }
    #pragma unroll
    for (int ni = 0; ni < 4; ni++) {
        int node = n0 + ng + ni;
        if (node < N_NODES)
            *(float4*)&g_h[(size_t)node * 64 + og] =
                make_float4(acc[ni][0], acc[ni][1], acc[ni][2], acc[ni][3]);
    }
}

// ---------------- edge MLP (register-blocked 4x4, tile=64 edges) --------------
// smem floats: W1T 16*64 | W2T 64*64 | b1 64 | b2 64 | eaT 16*68 | h1T 64*68
#define EMLP_SMEM ((1024 + 4096 + 128 + 16 * 68 + 64 * 68) * 4)
__global__ void __launch_bounds__(256) k_edge_mlp(const float* __restrict__ ea,
                           const float* __restrict__ W1, const float* __restrict__ b1,
                           const float* __restrict__ W2, const float* __restrict__ b2) {
    extern __shared__ float sm[];
    float* W1T = sm;                 // [j][o] j<16
    float* W2T = W1T + 1024;
    float* b1s = W2T + 4096;
    float* b2s = b1s + 64;
    float* eaT = b2s + 64;           // [j][e] stride 68, j<16
    float* h1T = eaT + 16 * 68;      // [j][e] stride 68
    int tid = threadIdx.x;
    for (int i = tid; i < 1024; i += 256) { int o = i >> 4, j = i & 15; W1T[j * 64 + o] = W1[i]; }
    for (int i = tid; i < 4096; i += 256) { int o = i >> 6, j = i & 63; W2T[j * 64 + o] = W2[i]; }
    if (tid < 64) { b1s[tid] = b1[tid]; b2s[tid] = b2[tid]; }
    int e0 = blockIdx.x * 64;
    // stage ea transposed: 64 edges x 16 = 1024 floats, 256 float4 loads
    {
        int e = tid >> 2, j = (tid & 3) * 4;
        float4 v = make_float4(0.f, 0.f, 0.f, 0.f);
        if (e0 + e < N_EDGES) v = *(const float4*)(ea + (size_t)(e0 + e) * 16 + j);
        eaT[(j + 0) * 68 + e] = v.x;
        eaT[(j + 1) * 68 + e] = v.y;
        eaT[(j + 2) * 68 + e] = v.z;
        eaT[(j + 3) * 68 + e] = v.w;
    }
    __syncthreads();
    int eg = (tid & 15) * 4;
    int og = (tid >> 4) * 4;
    float acc[4][4];
    // layer 1 (K=16)
    #pragma unroll
    for (int ei = 0; ei < 4; ei++)
        #pragma unroll
        for (int oi = 0; oi < 4; oi++) acc[ei][oi] = b1s[og + oi];
    #pragma unroll
    for (int j = 0; j < 16; j++) {
        float4 wv = *(const float4*)&W1T[j * 64 + og];
        float4 ev = *(const float4*)&eaT[j * 68 + eg];
        float e[4] = {ev.x, ev.y, ev.z, ev.w};
        float wl[4] = {wv.x, wv.y, wv.z, wv.w};
        #pragma unroll
        for (int ei = 0; ei < 4; ei++)
            #pragma unroll
            for (int oi = 0; oi < 4; oi++) acc[ei][oi] += e[ei] * wl[oi];
    }
    #pragma unroll
    for (int oi = 0; oi < 4; oi++) {
        float4 v = make_float4(fmaxf(acc[0][oi], 0.f), fmaxf(acc[1][oi], 0.f),
                               fmaxf(acc[2][oi], 0.f), fmaxf(acc[3][oi], 0.f));
        *(float4*)&h1T[(og + oi) * 68 + eg] = v;
    }
    __syncthreads();
    // layer 2 (K=64) -> relu -> g_ew2
    #pragma unroll
    for (int ei = 0; ei < 4; ei++)
        #pragma unroll
        for (int oi = 0; oi < 4; oi++) acc[ei][oi] = b2s[og + oi];
    for (int j = 0; j < 64; j++) {
        float4 wv = *(const float4*)&W2T[j * 64 + og];
        float4 ev = *(const float4*)&h1T[j * 68 + eg];
        float e[4] = {ev.x, ev.y, ev.z, ev.w};
        float wl[4] = {wv.x, wv.y, wv.z, wv.w};
        #pragma unroll
        for (int ei = 0; ei < 4; ei++)
            #pragma unroll
            for (int oi = 0; oi < 4; oi++) acc[ei][oi] += e[ei] * wl[oi];
    }
    #pragma unroll
    for (int ei = 0; ei < 4; ei++) {
        int e = e0 + eg + ei;
        if (e < N_EDGES)
            *(float4*)&g_ew2[(size_t)e * 64 + og] =
                make_float4(fmaxf(acc[ei][0], 0.f), fmaxf(acc[ei][1], 0.f),
                            fmaxf(acc[ei][2], 0.f), fmaxf(acc[ei][3], 0.f));
    }
}

// ---------------- CSR build --------------------------------------------------
__global__ void k_hist(const int* __restrict__ ei) {
    int i = blockIdx.x * blockDim.x + threadIdx.x, st = gridDim.x * blockDim.x;
    for (int e = i; e < N_EDGES; e += st) atomicAdd(&g_deg[ei[N_EDGES + e]], 1);
}

__global__ void k_scan() {
    __shared__ int part[1024];
    int t = threadIdx.x;
    const int CH = (N_NODES + 1023) / 1024;
    int b0 = t * CH, b1 = min(b0 + CH, N_NODES);
    int s = 0;
    for (int i = b0; i < b1; i++) s += g_deg[i];
    part[t] = s;
    __syncthreads();
    for (int d = 1; d < 1024; d <<= 1) {
        int v = (t >= d) ? part[t - d] : 0;
        __syncthreads();
        part[t] += v;
        __syncthreads();
    }
    int run = (t == 0) ? 0 : part[t - 1];
    for (int i = b0; i < b1; i++) { g_off[i] = run; g_cur[i] = run; run += g_deg[i]; }
    if (t == 1023) g_off[N_NODES] = part[1023];
}

__global__ void k_fill(const int* __restrict__ ei) {
    int i = blockIdx.x * blockDim.x + threadIdx.x, st = gridDim.x * blockDim.x;
    for (int e = i; e < N_EDGES; e += st) {
        int d = ei[N_EDGES + e];
        int p = atomicAdd(&g_cur[d], 1);
        g_csr[p] = e;
    }
}

__global__ void k_sort() {
    int d = blockIdx.x * blockDim.x + threadIdx.x;
    if (d >= N_NODES) return;
    int a = g_off[d], b = g_off[d + 1];
    for (int i = a + 1; i < b; i++) {
        int v = g_csr[i];
        int j = i - 1;
        while (j >= a && g_csr[j] > v) { g_csr[j + 1] = g_csr[j]; j--; }
        g_csr[j + 1] = v;
    }
}

// ---------------- build Bt[n][k] fp16: layer-invariant part (once) ------------
__global__ void k_buildB_static(const float* __restrict__ We3, const float* __restrict__ be3) {
    int i0 = blockIdx.x * blockDim.x + threadIdx.x, st = gridDim.x * blockDim.x;
    for (int idx = i0; idx < H * K2; idx += st) {
        int n = idx / K2, kg = idx % K2;
        if (kg >= 4096 && kg < 4160) continue;         // roots rows: per layer
        float v;
        if (kg < 4096) { int i = kg >> 6, k = kg & 63; v = We3[((i << 6) + n) * 64 + k]; }
        else           { v = be3[((kg - 4160) << 6) + n]; }
        g_B16[idx] = __float2half_rn(v);
    }
}

// per-layer: only the 64 roots rows (kg in [4096,4160))
__global__ void k_buildB_roots(const float* __restrict__ roots, int l) {
    int idx = blockIdx.x * blockDim.x + threadIdx.x;     // 64*64
    if (idx >= 64 * 64) return;
    int n = idx >> 6, r = idx & 63;
    g_B16[n * K2 + 4096 + r] = __float2half_rn(roots[(l * 64 + r) * 64 + n]);
}

// ---------------- build P rows (fp32 accum, fp16 stores) ----------------------
__global__ void __launch_bounds__(128) k_buildP(const int* __restrict__ ei) {
    int tid = threadIdx.x, warp = tid >> 5, lane = tid & 31;
    int ns_w = warp >> 1, kh = warp & 1;
    int d = blockIdx.x * 2 + ns_w;
    int kcol = kh * 32 + lane;

    float acc[64];
    #pragma unroll
    for (int i = 0; i < 64; i++) acc[i] = 0.f;

    int off0 = g_off[d];
    int deg = g_off[d + 1] - off0;
    for (int j = 0; j < deg; j++) {
        int e = g_csr[off0 + j];               // sorted -> deterministic order
        int s = ei[e];
        float ew = g_ew2[e * 64 + kcol];
        const float4* hr = (const float4*)(g_h + s * 64);
        #pragma unroll
        for (int i4 = 0; i4 < 16; i4++) {
            float4 hv = hr[i4];
            acc[i4 * 4 + 0] += hv.x * ew;
            acc[i4 * 4 + 1] += hv.y * ew;
            acc[i4 * 4 + 2] += hv.z * ew;
            acc[i4 * 4 + 3] += hv.w * ew;
        }
    }
    size_t rb = (size_t)d * K2;
    #pragma unroll
    for (int i = 0; i < 64; i++)
        g_P16[rb + i * 64 + kcol] = __float2half_rn(acc[i]);

    {
        int ns = tid >> 6, i = tid & 63;
        int dn = blockIdx.x * 2 + ns;
        size_t rb2 = (size_t)dn * K2;
        g_P16[rb2 + 4096 + i] = __float2half_rn(g_h[dn * 64 + i]);
        int o0 = g_off[dn], dg = g_off[dn + 1] - o0;
        float q = 0.f;
        for (int j = 0; j < dg; j++) q += g_h[ei[g_csr[o0 + j]] * 64 + i];
        g_P16[rb2 + 4160 + i] = __float2half_rn(q);
    }
}

// ---------------- GEMM (M64, single fp16 pass, 4-stage cp.async) --------------
#define NKB2 132                 // K2 / 32
#define A_STAGE 5120
#define B_OFF   20480
#define B_STAGE 5120
#define GEMM_SMEM 40960

__device__ __forceinline__ void copy_stage(char* smb, int slot, int m0, int kb, int tid) {
    int row = tid >> 2, c4 = tid & 3;           // 64 rows x 4 chunks(16B)
    {
        const __half* src = g_P16 + (size_t)(m0 + row) * K2 + kb * 32 + c4 * 8;
        uint32_t dst = smem_u32(smb + slot * A_STAGE + row * 80 + c4 * 16);
        asm volatile("cp.async.cg.shared.global [%0], [%1], 16;" :: "r"(dst), "l"(src));
    }
    {
        const __half* src = g_B16 + (size_t)row * K2 + kb * 32 + c4 * 8;
        uint32_t dst = smem_u32(smb + B_OFF + slot * B_STAGE + row * 80 + c4 * 16);
        asm volatile("cp.async.cg.shared.global [%0], [%1], 16;" :: "r"(dst), "l"(src));
    }
    asm volatile("cp.async.commit_group;" ::: "memory");
}

__global__ void __launch_bounds__(256, 3) k_gemm_mma(const float* __restrict__ cbias, int l) {
    extern __shared__ __align__(16) char smb[];
    const int tid = threadIdx.x, w = tid >> 5, lane = tid & 31;
    const int m0 = blockIdx.x * 64;
    const int lq = lane >> 2;
    const int lr = lane & 3;
    const int wm = w >> 1;
    const int wn = w & 1;

    const int l7 = lane & 7;
    const int lbit = (lane >> 3) & 1;
    const int csel = (lane >> 4) ? 16 : 0;
    const uint32_t aoff = (uint32_t)((wm * 16 + l7 + lbit * 8) * 80 + csel);
    uint32_t brow_off[2];
    #pragma unroll
    for (int g = 0; g < 2; g++)
        brow_off[g] = (uint32_t)((wn * 32 + g * 16 + l7 + lbit * 8) * 80 + csel);

    float acc[4][4];
    #pragma unroll
    for (int na = 0; na < 4; na++)
        #pragma unroll
        for (int v = 0; v < 4; v++) acc[na][v] = 0.f;

    copy_stage(smb, 0, m0, 0, tid);
    copy_stage(smb, 1, m0, 1, tid);
    copy_stage(smb, 2, m0, 2, tid);

    uint32_t sb = smem_u32(smb);
    for (int blk = 0; blk < NKB2; blk++) {
        int rem = NKB2 - 1 - blk;
        if (rem >= 2)      asm volatile("cp.async.wait_group 2;" ::: "memory");
        else if (rem == 1) asm volatile("cp.async.wait_group 1;" ::: "memory");
        else               asm volatile("cp.async.wait_group 0;" ::: "memory");
        __syncthreads();

        uint32_t abase = sb + (blk & 3) * A_STAGE;
        uint32_t bbase = sb + B_OFF + (blk & 3) * B_STAGE;
        #pragma unroll
        for (int s = 0; s < 2; s++) {
            uint32_t k0b = (uint32_t)(s * 32);
            uint32_t af[4];
            ldsm_x4(af, abase + aoff + k0b);
            #pragma unroll
            for (int g = 0; g < 2; g++) {
                uint32_t bh[4];
                ldsm_x4(bh, bbase + brow_off[g] + k0b);
                mma16816h(acc[2 * g],     af, bh[0], bh[2]);
                mma16816h(acc[2 * g + 1], af, bh[1], bh[3]);
            }
        }
        if (blk + 3 < NKB2) copy_stage(smb, (blk + 3) & 3, m0, blk + 3, tid);
    }

    int r0 = m0 + wm * 16 + lq;
    #pragma unroll
    for (int na = 0; na < 4; na++) {
        int c0 = wn * 32 + na * 8 + lr * 2;
        float bx = cbias[l * 64 + c0], by = cbias[l * 64 + c0 + 1];
        if (r0 < N_NODES) {
            g_m[r0 * 64 + c0]     = acc[na][0] + bx;
            g_m[r0 * 64 + c0 + 1] = acc[na][1] + by;
        }
        if (r0 + 8 < N_NODES) {
            g_m[(r0 + 8) * 64 + c0]     = acc[na][2] + bx;
            g_m[(r0 + 8) * 64 + c0 + 1] = acc[na][3] + by;
        }
    }
}

// ---------------- GRU step (2 nodes per iteration) ----------------------------
#define GRU_SMEM ((12288 * 2 + 192 * 2 + 64 * 4 + 192 * 4) * 4)
__global__ void k_gru(const float* __restrict__ Wih, const float* __restrict__ Whh,
                      const float* __restrict__ bih, const float* __restrict__ bhh,
                      float* __restrict__ dout, int last) {
    extern __shared__ float smf[];
    float* WihT = smf;
    float* WhhT = smf + 12288;
    float* bihs = smf + 24576;
    float* bhhs = bihs + 192;
    float* ms   = bhhs + 192;
    float* hs   = ms + 128;
    float* gi   = hs + 128;
    float* gh   = gi + 384;
    int t = threadIdx.x;
    for (int idx = t; idx < 192 * 64; idx += 192) {
        int j = idx / 64, i = idx % 64;
        WihT[i * 192 + j] = Wih[idx];
        WhhT[i * 192 + j] = Whh[idx];
    }
    bihs[t] = bih[t]; bhhs[t] = bhh[t];
    __syncthreads();
    for (int pair = blockIdx.x; pair < N_NODES / 2; pair += gridDim.x) {
        int n0 = pair * 2;
        if (t < 64) {
            ms[t]       = g_m[n0 * 64 + t];
            ms[64 + t]  = g_m[(n0 + 1) * 64 + t];
            hs[t]       = g_hidden[n0 * 64 + t];
            hs[64 + t]  = g_hidden[(n0 + 1) * 64 + t];
        }
        __syncthreads();
        float a0 = bihs[t], a1 = bihs[t], b0 = bhhs[t], b1 = bhhs[t];
        #pragma unroll 8
        for (int i = 0; i < 64; i++) {
            float w1 = WihT[i * 192 + t];
            float w2 = WhhT[i * 192 + t];
            a0 += ms[i] * w1;
            a1 += ms[64 + i] * w1;
            b0 += hs[i] * w2;
            b1 += hs[64 + i] * w2;
        }
        gi[t] = a0; gi[192 + t] = a1;
        gh[t] = b0; gh[192 + t] = b1;
        __syncthreads();
        if (t < 128) {
            int ns = t >> 6, tt = t & 63;
            int node = n0 + ns;
            const float* gin = gi + ns * 192;
            const float* ghn = gh + ns * 192;
            float r = 1.f / (1.f + expf(-(gin[tt] + ghn[tt])));
            float z = 1.f / (1.f + expf(-(gin[64 + tt] + ghn[64 + tt])));
            float n = tanhf(gin[128 + tt] + r * ghn[128 + tt]);
            float nh = (1.f - z) * n + z * hs[ns * 64 + tt];
            g_hidden[node * 64 + tt] = nh;
            g_h[node * 64 + tt] = nh;
            if (last) dout[node * 64 + tt] = nh;
        }
        __syncthreads();
    }
}

// ---------------- launcher ----------------------------------------------------
extern "C" void kernel_launch(void* const* d_in, const int* in_sizes, int n_in,
                              void* d_out, int out_size) {
    const float* x     = (const float*)d_in[0];
    const float* ea    = (const float*)d_in[1];
    const float* Wn1   = (const float*)d_in[2];
    const float* bn1   = (const float*)d_in[3];
    const float* Wn2   = (const float*)d_in[4];
    const float* bn2   = (const float*)d_in[5];
    const float* Wn3   = (const float*)d_in[6];
    const float* bn3   = (const float*)d_in[7];
    const float* We1   = (const float*)d_in[8];
    const float* be1   = (const float*)d_in[9];
    const float* We2   = (const float*)d_in[10];
    const float* be2   = (const float*)d_in[11];
    const float* We3   = (const float*)d_in[12];
    const float* be3   = (const float*)d_in[13];
    const float* roots = (const float*)d_in[14];
    const float* cbias = (const float*)d_in[15];
    const float* gWih  = (const float*)d_in[16];
    const float* gWhh  = (const float*)d_in[17];
    const float* gbih  = (const float*)d_in[18];
    const float* gbhh  = (const float*)d_in[19];
    const int*   ei    = (const int*)d_in[20];
    float* dout = (float*)d_out;

    cudaFuncSetAttribute(k_gru, cudaFuncAttributeMaxDynamicSharedMemorySize, GRU_SMEM);
    cudaFuncSetAttribute(k_gemm_mma, cudaFuncAttributeMaxDynamicSharedMemorySize, GEMM_SMEM);
    cudaFuncSetAttribute(k_node_mlp, cudaFuncAttributeMaxDynamicSharedMemorySize, NMLP_SMEM);
    cudaFuncSetAttribute(k_edge_mlp, cudaFuncAttributeMaxDynamicSharedMemorySize, EMLP_SMEM);

    k_zero_misc<<<400, 256>>>();
    k_node_mlp<<<(N_NODES + 63) / 64, 256, NMLP_SMEM>>>(x, Wn1, bn1, Wn2, bn2, Wn3, bn3);
    k_edge_mlp<<<(N_EDGES + 63) / 64, 256, EMLP_SMEM>>>(ea, We1, be1, We2, be2);
    k_hist<<<200, 256>>>(ei);
    k_scan<<<1, 1024>>>();
    k_fill<<<200, 256>>>(ei);
    k_sort<<<(N_NODES + 255) / 256, 256>>>();
    k_buildB_static<<<264, 256>>>(We3, be3);

    for (int l = 0; l < N_LAYERS; l++) {
        k_buildB_roots<<<16, 256>>>(roots, l);
        k_buildP<<<N_NODES / 2, 128>>>(ei);
        k_gemm_mma<<<M_PAD / 64, 256, GEMM_SMEM>>>(cbias, l);
        k_gru<<<296, 192, GRU_SMEM>>>(gWih, gWhh, gbih, gbhh, dout, l == N_LAYERS - 1);
    }
}

// round 16
// speedup vs baseline: 2.9849x; 1.1143x over previous
#include <cuda_runtime.h>
#include <cuda_bf16.h>
#include <cuda_fp16.h>
#include <cstdint>
#include <math.h>

#define N_NODES 25000
#define M_PAD   25088            // 392 * 64
#define N_EDGES 100000
#define H 64
#define K2 4224                  // 4096 (P edge part) + 64 (h for roots) + 64 (Q for be3)
#define N_LAYERS 3

// ---------------- scratch (static device globals) ---------------------------
__device__ float g_h[N_NODES * H];
__device__ float g_hidden[N_NODES * H];
__device__ float g_ew2[N_EDGES * H];
__device__ __align__(128) __half g_P16[(size_t)M_PAD * K2];          // ~212 MB fp16
__device__ __align__(128) __half g_B16[H * K2];                      // Bt[n][k] fp16
__device__ float g_m[N_NODES * H];
__device__ float g_gi[(size_t)N_NODES * 192];                        // GRU input gates
__device__ int   g_deg[N_NODES];
__device__ int   g_off[N_NODES + 1];
__device__ int   g_cur[N_NODES];
__device__ int   g_csr[N_EDGES];

// ---------------- helpers ------------------------------------------------
__device__ __forceinline__ uint32_t smem_u32(const void* p) {
    uint32_t a;
    asm("{ .reg .u64 t; cvta.to.shared.u64 t, %1; cvt.u32.u64 %0, t; }" : "=r"(a) : "l"(p));
    return a;
}

__device__ __forceinline__ void mma16816h(float* c, const uint32_t* a, uint32_t b0, uint32_t b1) {
    asm volatile("mma.sync.aligned.m16n8k16.row.col.f32.f16.f16.f32 "
        "{%0,%1,%2,%3}, {%4,%5,%6,%7}, {%8,%9}, {%0,%1,%2,%3};"
        : "+f"(c[0]), "+f"(c[1]), "+f"(c[2]), "+f"(c[3])
        : "r"(a[0]), "r"(a[1]), "r"(a[2]), "r"(a[3]), "r"(b0), "r"(b1));
}

__device__ __forceinline__ void ldsm_x4(uint32_t* r, uint32_t addr) {
    asm volatile("ldmatrix.sync.aligned.m8n8.x4.shared.b16 {%0,%1,%2,%3}, [%4];"
        : "=r"(r[0]), "=r"(r[1]), "=r"(r[2]), "=r"(r[3]) : "r"(addr));
}

// ---------------- zero init --------------------------------------------------
__global__ void k_zero_misc() {
    int i = blockIdx.x * blockDim.x + threadIdx.x;
    int st = gridDim.x * blockDim.x;
    for (int idx = i; idx < N_NODES; idx += st) g_deg[idx] = 0;
    for (int idx = i; idx < N_NODES * H; idx += st) g_hidden[idx] = 0.f;
    const size_t padN = (size_t)(M_PAD - N_NODES) * K2;
    __half z = __float2half_rn(0.f);
    for (size_t idx = i; idx < padN; idx += st)
        g_P16[(size_t)N_NODES * K2 + idx] = z;
}

// ---------------- node MLP (register-blocked 4x4, tile=64 nodes) --------------
#define NMLP_SMEM ((2048 + 4096 + 4096 + 192 + 32 * 68 + 64 * 68 + 64 * 68) * 4)
__global__ void __launch_bounds__(256) k_node_mlp(const float* __restrict__ x,
                           const float* __restrict__ W1, const float* __restrict__ b1,
                           const float* __restrict__ W2, const float* __restrict__ b2,
                           const float* __restrict__ W3, const float* __restrict__ b3) {
    extern __shared__ float sm[];
    float* W1T = sm;
    float* W2T = W1T + 2048;
    float* W3T = W2T + 4096;
    float* b1s = W3T + 4096;
    float* b2s = b1s + 64;
    float* b3s = b2s + 64;
    float* xT  = b3s + 64;
    float* h1T = xT + 32 * 68;
    float* h2T = h1T + 64 * 68;
    int tid = threadIdx.x;
    for (int i = tid; i < 2048; i += 256) { int o = i >> 5, j = i & 31; W1T[j * 64 + o] = W1[i]; }
    for (int i = tid; i < 4096; i += 256) { int o = i >> 6, j = i & 63; W2T[j * 64 + o] = W2[i]; W3T[j * 64 + o] = W3[i]; }
    if (tid < 64) { b1s[tid] = b1[tid]; b2s[tid] = b2[tid]; b3s[tid] = b3[tid]; }
    int n0 = blockIdx.x * 64;
    #pragma unroll
    for (int q = 0; q < 2; q++) {
        int idx = q * 256 + tid;
        int n = idx >> 3, j = (idx & 7) * 4;
        float4 v = make_float4(0.f, 0.f, 0.f, 0.f);
        if (n0 + n < N_NODES) v = *(const float4*)(x + (size_t)(n0 + n) * 32 + j);
        xT[(j + 0) * 68 + n] = v.x;
        xT[(j + 1) * 68 + n] = v.y;
        xT[(j + 2) * 68 + n] = v.z;
        xT[(j + 3) * 68 + n] = v.w;
    }
    __syncthreads();
    int ng = (tid & 15) * 4;
    int og = (tid >> 4) * 4;
    float acc[4][4];
    #pragma unroll
    for (int ni = 0; ni < 4; ni++)
        #pragma unroll
        for (int oi = 0; oi < 4; oi++) acc[ni][oi] = b1s[og + oi];
    for (int j = 0; j < 32; j++) {
        float4 wv = *(const float4*)&W1T[j * 64 + og];
        float4 ev = *(const float4*)&xT[j * 68 + ng];
        float e[4] = {ev.x, ev.y, ev.z, ev.w};
        float wl[4] = {wv.x, wv.y, wv.z, wv.w};
        #pragma unroll
        for (int ni = 0; ni < 4; ni++)
            #pragma unroll
            for (int oi = 0; oi < 4; oi++) acc[ni][oi] += e[ni] * wl[oi];
    }
    #pragma unroll
    for (int oi = 0; oi < 4; oi++) {
        float4 v = make_float4(fmaxf(acc[0][oi], 0.f), fmaxf(acc[1][oi], 0.f),
                               fmaxf(acc[2][oi], 0.f), fmaxf(acc[3][oi], 0.f));
        *(float4*)&h1T[(og + oi) * 68 + ng] = v;
    }
    __syncthreads();
    #pragma unroll
    for (int ni = 0; ni < 4; ni++)
        #pragma unroll
        for (int oi = 0; oi < 4; oi++) acc[ni][oi] = b2s[og + oi];
    for (int j = 0; j < 64; j++) {
        float4 wv = *(const float4*)&W2T[j * 64 + og];
        float4 ev = *(const float4*)&h1T[j * 68 + ng];
        float e[4] = {ev.x, ev.y, ev.z, ev.w};
        float wl[4] = {wv.x, wv.y, wv.z, wv.w};
        #pragma unroll
        for (int ni = 0; ni < 4; ni++)
            #pragma unroll
            for (int oi = 0; oi < 4; oi++) acc[ni][oi] += e[ni] * wl[oi];
    }
    #pragma unroll
    for (int oi = 0; oi < 4; oi++) {
        float4 v = make_float4(fmaxf(acc[0][oi], 0.f), fmaxf(acc[1][oi], 0.f),
                               fmaxf(acc[2][oi], 0.f), fmaxf(acc[3][oi], 0.f));
        *(float4*)&h2T[(og + oi) * 68 + ng] = v;
    }
    __syncthreads();
    #pragma unroll
    for (int ni = 0; ni < 4; ni++)
        #pragma unroll
        for (int oi = 0; oi < 4; oi++) acc[ni][oi] = b3s[og + oi];
    for (int j = 0; j < 64; j++) {
        float4 wv = *(const float4*)&W3T[j * 64 + og];
        float4 ev = *(const float4*)&h2T[j * 68 + ng];
        float e[4] = {ev.x, ev.y, ev.z, ev.w};
        float wl[4] = {wv.x, wv.y, wv.z, wv.w};
        #pragma unroll
        for (int ni = 0; ni < 4; ni++)
            #pragma unroll
            for (int oi = 0; oi < 4; oi++) acc[ni][oi] += e[ni] * wl[oi];
    }
    #pragma unroll
    for (int ni = 0; ni < 4; ni++) {
        int node = n0 + ng + ni;
        if (node < N_NODES)
            *(float4*)&g_h[(size_t)node * 64 + og] =
                make_float4(acc[ni][0], acc[ni][1], acc[ni][2], acc[ni][3]);
    }
}

// ---------------- edge MLP (register-blocked 4x4, tile=64 edges) --------------
#define EMLP_SMEM ((1024 + 4096 + 128 + 16 * 68 + 64 * 68) * 4)
__global__ void __launch_bounds__(256) k_edge_mlp(const float* __restrict__ ea,
                           const float* __restrict__ W1, const float* __restrict__ b1,
                           const float* __restrict__ W2, const float* __restrict__ b2) {
    extern __shared__ float sm[];
    float* W1T = sm;
    float* W2T = W1T + 1024;
    float* b1s = W2T + 4096;
    float* b2s = b1s + 64;
    float* eaT = b2s + 64;
    float* h1T = eaT + 16 * 68;
    int tid = threadIdx.x;
    for (int i = tid; i < 1024; i += 256) { int o = i >> 4, j = i & 15; W1T[j * 64 + o] = W1[i]; }
    for (int i = tid; i < 4096; i += 256) { int o = i >> 6, j = i & 63; W2T[j * 64 + o] = W2[i]; }
    if (tid < 64) { b1s[tid] = b1[tid]; b2s[tid] = b2[tid]; }
    int e0 = blockIdx.x * 64;
    {
        int e = tid >> 2, j = (tid & 3) * 4;
        float4 v = make_float4(0.f, 0.f, 0.f, 0.f);
        if (e0 + e < N_EDGES) v = *(const float4*)(ea + (size_t)(e0 + e) * 16 + j);
        eaT[(j + 0) * 68 + e] = v.x;
        eaT[(j + 1) * 68 + e] = v.y;
        eaT[(j + 2) * 68 + e] = v.z;
        eaT[(j + 3) * 68 + e] = v.w;
    }
    __syncthreads();
    int eg = (tid & 15) * 4;
    int og = (tid >> 4) * 4;
    float acc[4][4];
    #pragma unroll
    for (int ei = 0; ei < 4; ei++)
        #pragma unroll
        for (int oi = 0; oi < 4; oi++) acc[ei][oi] = b1s[og + oi];
    #pragma unroll
    for (int j = 0; j < 16; j++) {
        float4 wv = *(const float4*)&W1T[j * 64 + og];
        float4 ev = *(const float4*)&eaT[j * 68 + eg];
        float e[4] = {ev.x, ev.y, ev.z, ev.w};
        float wl[4] = {wv.x, wv.y, wv.z, wv.w};
        #pragma unroll
        for (int ei = 0; ei < 4; ei++)
            #pragma unroll
            for (int oi = 0; oi < 4; oi++) acc[ei][oi] += e[ei] * wl[oi];
    }
    #pragma unroll
    for (int oi = 0; oi < 4; oi++) {
        float4 v = make_float4(fmaxf(acc[0][oi], 0.f), fmaxf(acc[1][oi], 0.f),
                               fmaxf(acc[2][oi], 0.f), fmaxf(acc[3][oi], 0.f));
        *(float4*)&h1T[(og + oi) * 68 + eg] = v;
    }
    __syncthreads();
    #pragma unroll
    for (int ei = 0; ei < 4; ei++)
        #pragma unroll
        for (int oi = 0; oi < 4; oi++) acc[ei][oi] = b2s[og + oi];
    for (int j = 0; j < 64; j++) {
        float4 wv = *(const float4*)&W2T[j * 64 + og];
        float4 ev = *(const float4*)&h1T[j * 68 + eg];
        float e[4] = {ev.x, ev.y, ev.z, ev.w};
        float wl[4] = {wv.x, wv.y, wv.z, wv.w};
        #pragma unroll
        for (int ei = 0; ei < 4; ei++)
            #pragma unroll
            for (int oi = 0; oi < 4; oi++) acc[ei][oi] += e[ei] * wl[oi];
    }
    #pragma unroll
    for (int ei = 0; ei < 4; ei++) {
        int e = e0 + eg + ei;
        if (e < N_EDGES)
            *(float4*)&g_ew2[(size_t)e * 64 + og] =
                make_float4(fmaxf(acc[ei][0], 0.f), fmaxf(acc[ei][1], 0.f),
                            fmaxf(acc[ei][2], 0.f), fmaxf(acc[ei][3], 0.f));
    }
}

// ---------------- CSR build --------------------------------------------------
__global__ void k_hist(const int* __restrict__ ei) {
    int i = blockIdx.x * blockDim.x + threadIdx.x, st = gridDim.x * blockDim.x;
    for (int e = i; e < N_EDGES; e += st) atomicAdd(&g_deg[ei[N_EDGES + e]], 1);
}

__global__ void k_scan() {
    __shared__ int part[1024];
    int t = threadIdx.x;
    const int CH = (N_NODES + 1023) / 1024;
    int b0 = t * CH, b1 = min(b0 + CH, N_NODES);
    int s = 0;
    for (int i = b0; i < b1; i++) s += g_deg[i];
    part[t] = s;
    __syncthreads();
    for (int d = 1; d < 1024; d <<= 1) {
        int v = (t >= d) ? part[t - d] : 0;
        __syncthreads();
        part[t] += v;
        __syncthreads();
    }
    int run = (t == 0) ? 0 : part[t - 1];
    for (int i = b0; i < b1; i++) { g_off[i] = run; g_cur[i] = run; run += g_deg[i]; }
    if (t == 1023) g_off[N_NODES] = part[1023];
}

__global__ void k_fill(const int* __restrict__ ei) {
    int i = blockIdx.x * blockDim.x + threadIdx.x, st = gridDim.x * blockDim.x;
    for (int e = i; e < N_EDGES; e += st) {
        int d = ei[N_EDGES + e];
        int p = atomicAdd(&g_cur[d], 1);
        g_csr[p] = e;
    }
}

__global__ void k_sort() {
    int d = blockIdx.x * blockDim.x + threadIdx.x;
    if (d >= N_NODES) return;
    int a = g_off[d], b = g_off[d + 1];
    for (int i = a + 1; i < b; i++) {
        int v = g_csr[i];
        int j = i - 1;
        while (j >= a && g_csr[j] > v) { g_csr[j + 1] = g_csr[j]; j--; }
        g_csr[j + 1] = v;
    }
}

// ---------------- build Bt[n][k] fp16: layer-invariant part (once) ------------
__global__ void k_buildB_static(const float* __restrict__ We3, const float* __restrict__ be3) {
    int i0 = blockIdx.x * blockDim.x + threadIdx.x, st = gridDim.x * blockDim.x;
    for (int idx = i0; idx < H * K2; idx += st) {
        int n = idx / K2, kg = idx % K2;
        if (kg >= 4096 && kg < 4160) continue;
        float v;
        if (kg < 4096) { int i = kg >> 6, k = kg & 63; v = We3[((i << 6) + n) * 64 + k]; }
        else           { v = be3[((kg - 4160) << 6) + n]; }
        g_B16[idx] = __float2half_rn(v);
    }
}

__global__ void k_buildB_roots(const float* __restrict__ roots, int l) {
    int idx = blockIdx.x * blockDim.x + threadIdx.x;
    if (idx >= 64 * 64) return;
    int n = idx >> 6, r = idx & 63;
    g_B16[n * K2 + 4096 + r] = __float2half_rn(roots[(l * 64 + r) * 64 + n]);
}

// ---------------- build P rows (fp32 accum, fp16 stores) ----------------------
__global__ void __launch_bounds__(128) k_buildP(const int* __restrict__ ei) {
    int tid = threadIdx.x, warp = tid >> 5, lane = tid & 31;
    int ns_w = warp >> 1, kh = warp & 1;
    int d = blockIdx.x * 2 + ns_w;
    int kcol = kh * 32 + lane;

    float acc[64];
    #pragma unroll
    for (int i = 0; i < 64; i++) acc[i] = 0.f;

    int off0 = g_off[d];
    int deg = g_off[d + 1] - off0;
    for (int j = 0; j < deg; j++) {
        int e = g_csr[off0 + j];
        int s = ei[e];
        float ew = g_ew2[e * 64 + kcol];
        const float4* hr = (const float4*)(g_h + s * 64);
        #pragma unroll
        for (int i4 = 0; i4 < 16; i4++) {
            float4 hv = hr[i4];
            acc[i4 * 4 + 0] += hv.x * ew;
            acc[i4 * 4 + 1] += hv.y * ew;
            acc[i4 * 4 + 2] += hv.z * ew;
            acc[i4 * 4 + 3] += hv.w * ew;
        }
    }
    size_t rb = (size_t)d * K2;
    #pragma unroll
    for (int i = 0; i < 64; i++)
        g_P16[rb + i * 64 + kcol] = __float2half_rn(acc[i]);

    {
        int ns = tid >> 6, i = tid & 63;
        int dn = blockIdx.x * 2 + ns;
        size_t rb2 = (size_t)dn * K2;
        g_P16[rb2 + 4096 + i] = __float2half_rn(g_h[dn * 64 + i]);
        int o0 = g_off[dn], dg = g_off[dn + 1] - o0;
        float q = 0.f;
        for (int j = 0; j < dg; j++) q += g_h[ei[g_csr[o0 + j]] * 64 + i];
        g_P16[rb2 + 4160 + i] = __float2half_rn(q);
    }
}

// ---------------- GEMM (M64, single fp16 pass, 4-stage cp.async) --------------
#define NKB2 132                 // K2 / 32
#define A_STAGE 5120
#define B_OFF   20480
#define B_STAGE 5120
#define GEMM_SMEM 40960

__device__ __forceinline__ void copy_stage(char* smb, int slot, int m0, int kb, int tid) {
    int row = tid >> 2, c4 = tid & 3;
    {
        const __half* src = g_P16 + (size_t)(m0 + row) * K2 + kb * 32 + c4 * 8;
        uint32_t dst = smem_u32(smb + slot * A_STAGE + row * 80 + c4 * 16);
        asm volatile("cp.async.cg.shared.global [%0], [%1], 16;" :: "r"(dst), "l"(src));
    }
    {
        const __half* src = g_B16 + (size_t)row * K2 + kb * 32 + c4 * 8;
        uint32_t dst = smem_u32(smb + B_OFF + slot * B_STAGE + row * 80 + c4 * 16);
        asm volatile("cp.async.cg.shared.global [%0], [%1], 16;" :: "r"(dst), "l"(src));
    }
    asm volatile("cp.async.commit_group;" ::: "memory");
}

__global__ void __launch_bounds__(256, 3) k_gemm_mma(const float* __restrict__ cbias, int l) {
    extern __shared__ __align__(16) char smb[];
    const int tid = threadIdx.x, w = tid >> 5, lane = tid & 31;
    const int m0 = blockIdx.x * 64;
    const int lq = lane >> 2;
    const int lr = lane & 3;
    const int wm = w >> 1;
    const int wn = w & 1;

    const int l7 = lane & 7;
    const int lbit = (lane >> 3) & 1;
    const int csel = (lane >> 4) ? 16 : 0;
    const uint32_t aoff = (uint32_t)((wm * 16 + l7 + lbit * 8) * 80 + csel);
    uint32_t brow_off[2];
    #pragma unroll
    for (int g = 0; g < 2; g++)
        brow_off[g] = (uint32_t)((wn * 32 + g * 16 + l7 + lbit * 8) * 80 + csel);

    float acc[4][4];
    #pragma unroll
    for (int na = 0; na < 4; na++)
        #pragma unroll
        for (int v = 0; v < 4; v++) acc[na][v] = 0.f;

    copy_stage(smb, 0, m0, 0, tid);
    copy_stage(smb, 1, m0, 1, tid);
    copy_stage(smb, 2, m0, 2, tid);

    uint32_t sb = smem_u32(smb);
    for (int blk = 0; blk < NKB2; blk++) {
        int rem = NKB2 - 1 - blk;
        if (rem >= 2)      asm volatile("cp.async.wait_group 2;" ::: "memory");
        else if (rem == 1) asm volatile("cp.async.wait_group 1;" ::: "memory");
        else               asm volatile("cp.async.wait_group 0;" ::: "memory");
        __syncthreads();

        uint32_t abase = sb + (blk & 3) * A_STAGE;
        uint32_t bbase = sb + B_OFF + (blk & 3) * B_STAGE;
        #pragma unroll
        for (int s = 0; s < 2; s++) {
            uint32_t k0b = (uint32_t)(s * 32);
            uint32_t af[4];
            ldsm_x4(af, abase + aoff + k0b);
            #pragma unroll
            for (int g = 0; g < 2; g++) {
                uint32_t bh[4];
                ldsm_x4(bh, bbase + brow_off[g] + k0b);
                mma16816h(acc[2 * g],     af, bh[0], bh[2]);
                mma16816h(acc[2 * g + 1], af, bh[1], bh[3]);
            }
        }
        if (blk + 3 < NKB2) copy_stage(smb, (blk + 3) & 3, m0, blk + 3, tid);
    }

    int r0 = m0 + wm * 16 + lq;
    #pragma unroll
    for (int na = 0; na < 4; na++) {
        int c0 = wn * 32 + na * 8 + lr * 2;
        float bx = cbias[l * 64 + c0], by = cbias[l * 64 + c0 + 1];
        if (r0 < N_NODES) {
            g_m[r0 * 64 + c0]     = acc[na][0] + bx;
            g_m[r0 * 64 + c0 + 1] = acc[na][1] + by;
        }
        if (r0 + 8 < N_NODES) {
            g_m[(r0 + 8) * 64 + c0]     = acc[na][2] + bx;
            g_m[(r0 + 8) * 64 + c0 + 1] = acc[na][3] + by;
        }
    }
}

// ---------------- GRU part 1: gi = m @ Wih^T + bih ----------------------------
// tile = 64 nodes, 256 threads; thread = 4 nodes x 12 cols.
// smem: WihT [64][192] (48KB) | bih [192] | mT [64][68] (17KB)
#define GIK_SMEM ((12288 + 192 + 64 * 68) * 4)
__global__ void __launch_bounds__(256) k_gru_gi(const float* __restrict__ Wih,
                                                const float* __restrict__ bih) {
    extern __shared__ float sm[];
    float* WT   = sm;                // [i*192 + j]
    float* bihs = WT + 12288;
    float* mT   = bihs + 192;        // [i][n] stride 68
    int tid = threadIdx.x;
    for (int idx = tid; idx < 12288; idx += 256) {
        int j = idx >> 6, i = idx & 63;
        WT[i * 192 + j] = Wih[idx];
    }
    if (tid < 192) bihs[tid] = bih[tid];
    int n0 = blockIdx.x * 64;
    #pragma unroll
    for (int q = 0; q < 4; q++) {
        int idx = q * 256 + tid;                 // 1024 = 64 nodes x 16 float4
        int n = idx >> 4, c4 = (idx & 15) * 4;
        float4 v = make_float4(0.f, 0.f, 0.f, 0.f);
        if (n0 + n < N_NODES) v = *(const float4*)(g_m + (size_t)(n0 + n) * 64 + c4);
        mT[(c4 + 0) * 68 + n] = v.x;
        mT[(c4 + 1) * 68 + n] = v.y;
        mT[(c4 + 2) * 68 + n] = v.z;
        mT[(c4 + 3) * 68 + n] = v.w;
    }
    __syncthreads();
    int ng = (tid & 15) * 4;
    int og = (tid >> 4) * 12;
    float acc[4][12];
    #pragma unroll
    for (int ni = 0; ni < 4; ni++)
        #pragma unroll
        for (int oi = 0; oi < 12; oi++) acc[ni][oi] = bihs[og + oi];
    for (int i = 0; i < 64; i++) {
        float4 mv = *(const float4*)&mT[i * 68 + ng];
        float m4[4] = {mv.x, mv.y, mv.z, mv.w};
        float wl[12];
        #pragma unroll
        for (int q = 0; q < 3; q++) {
            float4 wv = *(const float4*)&WT[i * 192 + og + q * 4];
            wl[q * 4 + 0] = wv.x; wl[q * 4 + 1] = wv.y;
            wl[q * 4 + 2] = wv.z; wl[q * 4 + 3] = wv.w;
        }
        #pragma unroll
        for (int ni = 0; ni < 4; ni++)
            #pragma unroll
            for (int oi = 0; oi < 12; oi++) acc[ni][oi] += m4[ni] * wl[oi];
    }
    #pragma unroll
    for (int ni = 0; ni < 4; ni++) {
        int node = n0 + ng + ni;
        if (node < N_NODES) {
            #pragma unroll
            for (int q = 0; q < 3; q++)
                *(float4*)&g_gi[(size_t)node * 192 + og + q * 4] =
                    make_float4(acc[ni][q * 4 + 0], acc[ni][q * 4 + 1],
                                acc[ni][q * 4 + 2], acc[ni][q * 4 + 3]);
        }
    }
}

// ---------------- GRU part 2: gh + combine ------------------------------------
// tile = 64 nodes, 256 threads; thread = 4 nodes x 4 gate-cols (all 3 thirds).
// smem: WhhT [64][192] (48KB) | bhh [192] | hT [64][68] (17KB)
#define GCB_SMEM ((12288 + 192 + 64 * 68) * 4)
__global__ void __launch_bounds__(256) k_gru_comb(const float* __restrict__ Whh,
                                                  const float* __restrict__ bhh,
                                                  float* __restrict__ dout, int last) {
    extern __shared__ float sm[];
    float* WT   = sm;                // [i*192 + j]
    float* bhhs = WT + 12288;
    float* hT   = bhhs + 192;        // [i][n] stride 68 (hidden transposed)
    int tid = threadIdx.x;
    for (int idx = tid; idx < 12288; idx += 256) {
        int j = idx >> 6, i = idx & 63;
        WT[i * 192 + j] = Whh[idx];
    }
    if (tid < 192) bhhs[tid] = bhh[tid];
    int n0 = blockIdx.x * 64;
    #pragma unroll
    for (int q = 0; q < 4; q++) {
        int idx = q * 256 + tid;
        int n = idx >> 4, c4 = (idx & 15) * 4;
        float4 v = make_float4(0.f, 0.f, 0.f, 0.f);
        if (n0 + n < N_NODES) v = *(const float4*)(g_hidden + (size_t)(n0 + n) * 64 + c4);
        hT[(c4 + 0) * 68 + n] = v.x;
        hT[(c4 + 1) * 68 + n] = v.y;
        hT[(c4 + 2) * 68 + n] = v.z;
        hT[(c4 + 3) * 68 + n] = v.w;
    }
    __syncthreads();
    int ng = (tid & 15) * 4;
    int cg = (tid >> 4) * 4;          // gate col 0..60
    float ar[4][4], az[4][4], an[4][4];
    #pragma unroll
    for (int ni = 0; ni < 4; ni++)
        #pragma unroll
        for (int oi = 0; oi < 4; oi++) {
            ar[ni][oi] = bhhs[cg + oi];
            az[ni][oi] = bhhs[64 + cg + oi];
            an[ni][oi] = bhhs[128 + cg + oi];
        }
    for (int i = 0; i < 64; i++) {
        float4 hv = *(const float4*)&hT[i * 68 + ng];
        float h4[4] = {hv.x, hv.y, hv.z, hv.w};
        float4 wr = *(const float4*)&WT[i * 192 + cg];
        float4 wz = *(const float4*)&WT[i * 192 + 64 + cg];
        float4 wn = *(const float4*)&WT[i * 192 + 128 + cg];
        float wrl[4] = {wr.x, wr.y, wr.z, wr.w};
        float wzl[4] = {wz.x, wz.y, wz.z, wz.w};
        float wnl[4] = {wn.x, wn.y, wn.z, wn.w};
        #pragma unroll
        for (int ni = 0; ni < 4; ni++)
            #pragma unroll
            for (int oi = 0; oi < 4; oi++) {
                ar[ni][oi] += h4[ni] * wrl[oi];
                az[ni][oi] += h4[ni] * wzl[oi];
                an[ni][oi] += h4[ni] * wnl[oi];
            }
    }
    #pragma unroll
    for (int ni = 0; ni < 4; ni++) {
        int node = n0 + ng + ni;
        if (node >= N_NODES) continue;
        float4 gir = *(const float4*)&g_gi[(size_t)node * 192 + cg];
        float4 giz = *(const float4*)&g_gi[(size_t)node * 192 + 64 + cg];
        float4 gin = *(const float4*)&g_gi[(size_t)node * 192 + 128 + cg];
        float gr[4] = {gir.x, gir.y, gir.z, gir.w};
        float gz[4] = {giz.x, giz.y, giz.z, giz.w};
        float gn[4] = {gin.x, gin.y, gin.z, gin.w};
        float out[4];
        #pragma unroll
        for (int oi = 0; oi < 4; oi++) {
            float hid = hT[(cg + oi) * 68 + ng + ni];
            float r = 1.f / (1.f + expf(-(gr[oi] + ar[ni][oi])));
            float z = 1.f / (1.f + expf(-(gz[oi] + az[ni][oi])));
            float n = tanhf(gn[oi] + r * an[ni][oi]);
            out[oi] = (1.f - z) * n + z * hid;
        }
        float4 o4 = make_float4(out[0], out[1], out[2], out[3]);
        *(float4*)&g_hidden[(size_t)node * 64 + cg] = o4;
        *(float4*)&g_h[(size_t)node * 64 + cg] = o4;
        if (last) *(float4*)&dout[(size_t)node * 64 + cg] = o4;
    }
}

// ---------------- launcher ----------------------------------------------------
extern "C" void kernel_launch(void* const* d_in, const int* in_sizes, int n_in,
                              void* d_out, int out_size) {
    const float* x     = (const float*)d_in[0];
    const float* ea    = (const float*)d_in[1];
    const float* Wn1   = (const float*)d_in[2];
    const float* bn1   = (const float*)d_in[3];
    const float* Wn2   = (const float*)d_in[4];
    const float* bn2   = (const float*)d_in[5];
    const float* Wn3   = (const float*)d_in[6];
    const float* bn3   = (const float*)d_in[7];
    const float* We1   = (const float*)d_in[8];
    const float* be1   = (const float*)d_in[9];
    const float* We2   = (const float*)d_in[10];
    const float* be2   = (const float*)d_in[11];
    const float* We3   = (const float*)d_in[12];
    const float* be3   = (const float*)d_in[13];
    const float* roots = (const float*)d_in[14];
    const float* cbias = (const float*)d_in[15];
    const float* gWih  = (const float*)d_in[16];
    const float* gWhh  = (const float*)d_in[17];
    const float* gbih  = (const float*)d_in[18];
    const float* gbhh  = (const float*)d_in[19];
    const int*   ei    = (const int*)d_in[20];
    float* dout = (float*)d_out;

    cudaFuncSetAttribute(k_gemm_mma, cudaFuncAttributeMaxDynamicSharedMemorySize, GEMM_SMEM);
    cudaFuncSetAttribute(k_node_mlp, cudaFuncAttributeMaxDynamicSharedMemorySize, NMLP_SMEM);
    cudaFuncSetAttribute(k_edge_mlp, cudaFuncAttributeMaxDynamicSharedMemorySize, EMLP_SMEM);
    cudaFuncSetAttribute(k_gru_gi,   cudaFuncAttributeMaxDynamicSharedMemorySize, GIK_SMEM);
    cudaFuncSetAttribute(k_gru_comb, cudaFuncAttributeMaxDynamicSharedMemorySize, GCB_SMEM);

    k_zero_misc<<<400, 256>>>();
    k_node_mlp<<<(N_NODES + 63) / 64, 256, NMLP_SMEM>>>(x, Wn1, bn1, Wn2, bn2, Wn3, bn3);
    k_edge_mlp<<<(N_EDGES + 63) / 64, 256, EMLP_SMEM>>>(ea, We1, be1, We2, be2);
    k_hist<<<200, 256>>>(ei);
    k_scan<<<1, 1024>>>();
    k_fill<<<200, 256>>>(ei);
    k_sort<<<(N_NODES + 255) / 256, 256>>>();
    k_buildB_static<<<264, 256>>>(We3, be3);

    for (int l = 0; l < N_LAYERS; l++) {
        k_buildB_roots<<<16, 256>>>(roots, l);
        k_buildP<<<N_NODES / 2, 128>>>(ei);
        k_gemm_mma<<<M_PAD / 64, 256, GEMM_SMEM>>>(cbias, l);
        k_gru_gi<<<(N_NODES + 63) / 64, 256, GIK_SMEM>>>(gWih, gbih);
        k_gru_comb<<<(N_NODES + 63) / 64, 256, GCB_SMEM>>>(gWhh, gbhh, dout, l == N_LAYERS - 1);
    }
}